// round 3
// baseline (speedup 1.0000x reference)
#include <cuda_runtime.h>
#include <math.h>
#include <stdint.h>

#define N_NODES 20000
#define N_EDGES 320000
#define HC      256     // HEADS*HIDDEN
#define HEADS   4
#define HIDDEN  64
#define TD      64

// ---------------- scratch (device globals; no runtime allocation) ----------------
__device__ float g_te   [(size_t)N_EDGES * TD];     //  82 MB
__device__ float g_tenc1[(size_t)N_EDGES * HC];     // 328 MB
__device__ float g_tenc2[(size_t)N_EDGES * HC];     // 328 MB
__device__ float g_q [(size_t)N_NODES * HC];
__device__ float g_k [(size_t)N_NODES * HC];
__device__ float g_v [(size_t)N_NODES * HC];
__device__ float g_x1[(size_t)N_NODES * HC];
__device__ float g_x2[(size_t)N_NODES * HC];
__device__ float g_alpha[(size_t)N_EDGES * HEADS];
__device__ float g_amax [(size_t)N_NODES * HEADS];
__device__ float g_denom[(size_t)N_NODES * HEADS];
__device__ int   g_src[N_EDGES];
__device__ int   g_dst[N_EDGES];
__device__ int   g_is64;

// ---------------- edge_index dtype detection + conversion ----------------
// If the buffer is true int64 (values < N_NODES), every odd 32-bit word is 0.
// If it's int32, odd words are random node ids — 256 consecutive zeros is
// practically impossible. Deterministic pure function of the input.
__global__ void detect_idx_kernel(const unsigned int* __restrict__ w) {
    if (threadIdx.x == 0 && blockIdx.x == 0) {
        int ok = 1;
        for (int i = 0; i < 256; i++) {
            unsigned lo = w[2 * i], hi = w[2 * i + 1];
            if (hi != 0u || lo >= (unsigned)N_NODES) { ok = 0; break; }
        }
        g_is64 = ok;
    }
}

__global__ void convert_idx_kernel(const int* __restrict__ w) {
    int i = blockIdx.x * blockDim.x + threadIdx.x;
    if (i >= 2 * N_EDGES) return;
    int v = g_is64 ? w[2 * i] : w[i];    // little-endian low word
    if (i < N_EDGES) g_src[i] = v;
    else             g_dst[i - N_EDGES] = v;
}

// ---------------- time encoding: te[e, 2i]=sin(t*div_i), te[e,2i+1]=cos ----------------
__global__ void time_encode_kernel(const float* __restrict__ raw, const float* __restrict__ noise) {
    int e = blockIdx.x * 8 + (threadIdx.x >> 5);
    int lane = threadIdx.x & 31;
    if (e >= N_EDGES) return;
    float t = raw[e] + noise[e];
    const float cst = -0.14391156831212787f;        // -ln(10000)/64
    float div = expf((float)(2 * lane) * cst);
    float arg = t * div;
    // accurate range reduction (arg can be ~1e5; fast-math sinf would be wrong)
    double kd = rint((double)arg * 0.15915494309189535);   // 1/(2*pi)
    double r  = fma(-kd, 6.283185307179586, (double)arg);
    float rf = (float)r;
    float s = sinf(rf);
    float c = cosf(rf);
    g_te[(size_t)e * TD + 2 * lane]     = s;
    g_te[(size_t)e * TD + 2 * lane + 1] = c;
}

// ---------------- generic fp32 GEMM+bias: C[M,256] = A[M,K] @ W[K,256] + b ----------------
__global__ void sgemm_bias_kernel(const float* __restrict__ A, const float* __restrict__ W,
                                  const float* __restrict__ bias, float* __restrict__ C,
                                  int M, int K) {
    const int N = HC; // 256
    __shared__ float sA[16][64];
    __shared__ float sW[16][64];

    int tid = threadIdx.x;          // 256 threads
    int tx = tid & 15, ty = tid >> 4;
    int bm = blockIdx.y * 64, bn = blockIdx.x * 64;

    int lr = tid >> 2;              // 0..63  A-load row
    int lc = (tid & 3) << 2;        // 0,4,8,12 A-load col
    int wr = tid >> 4;              // 0..15  W-load row
    int wcol = (tid & 15) << 2;     // 0..60  W-load col

    float acc[4][4];
#pragma unroll
    for (int i = 0; i < 4; i++)
#pragma unroll
        for (int j = 0; j < 4; j++) acc[i][j] = 0.f;

    for (int k0 = 0; k0 < K; k0 += 16) {
        float4 av = make_float4(0.f, 0.f, 0.f, 0.f);
        if (bm + lr < M)
            av = *(const float4*)(A + (size_t)(bm + lr) * K + k0 + lc);
        sA[lc + 0][lr] = av.x;
        sA[lc + 1][lr] = av.y;
        sA[lc + 2][lr] = av.z;
        sA[lc + 3][lr] = av.w;
        float4 wv = *(const float4*)(W + (size_t)(k0 + wr) * N + bn + wcol);
        *(float4*)&sW[wr][wcol] = wv;
        __syncthreads();
#pragma unroll
        for (int kk = 0; kk < 16; kk++) {
            float4 a = *(const float4*)&sA[kk][ty * 4];
            float4 w = *(const float4*)&sW[kk][tx * 4];
            float ar[4] = {a.x, a.y, a.z, a.w};
            float wr4[4] = {w.x, w.y, w.z, w.w};
#pragma unroll
            for (int i = 0; i < 4; i++)
#pragma unroll
                for (int j = 0; j < 4; j++)
                    acc[i][j] = fmaf(ar[i], wr4[j], acc[i][j]);
        }
        __syncthreads();
    }

    float4 bv = *(const float4*)(bias + bn + tx * 4);
    float bb[4] = {bv.x, bv.y, bv.z, bv.w};
#pragma unroll
    for (int i = 0; i < 4; i++) {
        int m = bm + ty * 4 + i;
        if (m < M) {
            float4 o;
            o.x = acc[i][0] + bb[0];
            o.y = acc[i][1] + bb[1];
            o.z = acc[i][2] + bb[2];
            o.w = acc[i][3] + bb[3];
            *(float4*)(C + (size_t)m * N + bn + tx * 4) = o;
        }
    }
}

// ---------------- per-layer init: zero x-out, reset softmax stats ----------------
__global__ void init_kernel(float* __restrict__ xout) {
    int i = blockIdx.x * blockDim.x + threadIdx.x;
    if (i < N_NODES * HC) xout[i] = 0.f;
    if (i < N_NODES * HEADS) {
        g_amax[i] = -3.402823466e38f;
        g_denom[i] = 0.f;
    }
}

// ---------------- helpers ----------------
__device__ __forceinline__ void atomicMaxFloat(float* addr, float v) {
    if (v >= 0.f) atomicMax((int*)addr, __float_as_int(v));
    else          atomicMin((unsigned int*)addr, __float_as_uint(v));
}

// ---------------- pass A: alpha_raw = <q[dst], k[src]+tenc>/8 per head; amax ----------------
__global__ void edge_alpha_kernel(const float* __restrict__ q, const float* __restrict__ k,
                                  const float* __restrict__ tenc) {
    int e = blockIdx.x * 8 + (threadIdx.x >> 5);
    int lane = threadIdx.x & 31;
    if (e >= N_EDGES) return;
    int s = g_src[e], d = g_dst[e];
    int c0 = lane * 8;
    const float4* qp = (const float4*)(q + (size_t)d * HC + c0);
    const float4* kp = (const float4*)(k + (size_t)s * HC + c0);
    const float4* tp = (const float4*)(tenc + (size_t)e * HC + c0);
    float4 q0 = qp[0], q1 = qp[1];
    float4 k0 = kp[0], k1 = kp[1];
    float4 t0 = tp[0], t1 = tp[1];
    float p = q0.x * (k0.x + t0.x) + q0.y * (k0.y + t0.y)
            + q0.z * (k0.z + t0.z) + q0.w * (k0.w + t0.w)
            + q1.x * (k1.x + t1.x) + q1.y * (k1.y + t1.y)
            + q1.z * (k1.z + t1.z) + q1.w * (k1.w + t1.w);
    // reduce within 8-lane head groups
    p += __shfl_down_sync(0xffffffffu, p, 4, 8);
    p += __shfl_down_sync(0xffffffffu, p, 2, 8);
    p += __shfl_down_sync(0xffffffffu, p, 1, 8);
    if ((lane & 7) == 0) {
        int h = lane >> 3;
        float alpha = p * 0.125f;   // / sqrt(64)
        g_alpha[(size_t)e * HEADS + h] = alpha;
        atomicMaxFloat(&g_amax[(size_t)d * HEADS + h], alpha);
    }
}

// ---------------- pass B: ea = exp(alpha - amax[dst]); denom += ea ----------------
__global__ void edge_exp_kernel() {
    int i = blockIdx.x * blockDim.x + threadIdx.x;
    if (i >= N_EDGES * HEADS) return;
    int e = i >> 2, h = i & 3;
    int d = g_dst[e];
    float ea = expf(g_alpha[i] - g_amax[(size_t)d * HEADS + h]);
    g_alpha[i] = ea;
    atomicAdd(&g_denom[(size_t)d * HEADS + h], ea);
}

// ---------------- pass C: out[dst] += v[src] * (ea/denom[dst]) ----------------
__global__ void edge_agg_kernel(const float* __restrict__ v, float* __restrict__ xout) {
    int e = blockIdx.x * 8 + (threadIdx.x >> 5);
    int lane = threadIdx.x & 31;
    if (e >= N_EDGES) return;
    int s = g_src[e], d = g_dst[e];
    int h = lane >> 3;
    float a = g_alpha[(size_t)e * HEADS + h] / (g_denom[(size_t)d * HEADS + h] + 1e-16f);
    int c0 = lane * 8;
    float4 v0 = *(const float4*)(v + (size_t)s * HC + c0);
    float4 v1 = *(const float4*)(v + (size_t)s * HC + c0 + 4);
    float* o = xout + (size_t)d * HC + c0;
    atomicAdd(o + 0, v0.x * a);
    atomicAdd(o + 1, v0.y * a);
    atomicAdd(o + 2, v0.z * a);
    atomicAdd(o + 3, v0.w * a);
    atomicAdd(o + 4, v1.x * a);
    atomicAdd(o + 5, v1.y * a);
    atomicAdd(o + 6, v1.z * a);
    atomicAdd(o + 7, v1.w * a);
}

__global__ void relu_kernel(float* __restrict__ x, int n) {
    int i = blockIdx.x * blockDim.x + threadIdx.x;
    if (i < n) x[i] = fmaxf(x[i], 0.f);
}

// ---------------- final: out[e] = <x[src]+x[dst], wc> + bc ----------------
__global__ void edge_out_kernel(const float* __restrict__ x, const float* __restrict__ wc,
                                const float* __restrict__ bc, float* __restrict__ out) {
    int e = blockIdx.x * 8 + (threadIdx.x >> 5);
    int lane = threadIdx.x & 31;
    if (e >= N_EDGES) return;
    int s = g_src[e], d = g_dst[e];
    int c0 = lane * 8;
    const float4* xs = (const float4*)(x + (size_t)s * HC + c0);
    const float4* xd = (const float4*)(x + (size_t)d * HC + c0);
    const float4* wp = (const float4*)(wc + c0);
    float4 s0 = xs[0], s1 = xs[1];
    float4 d0 = xd[0], d1 = xd[1];
    float4 w0 = wp[0], w1 = wp[1];
    float p = (s0.x + d0.x) * w0.x + (s0.y + d0.y) * w0.y
            + (s0.z + d0.z) * w0.z + (s0.w + d0.w) * w0.w
            + (s1.x + d1.x) * w1.x + (s1.y + d1.y) * w1.y
            + (s1.z + d1.z) * w1.z + (s1.w + d1.w) * w1.w;
#pragma unroll
    for (int off = 16; off >= 1; off >>= 1)
        p += __shfl_down_sync(0xffffffffu, p, off);
    if (lane == 0) out[e] = p + bc[0];
}

// ---------------- launch ----------------
extern "C" void kernel_launch(void* const* d_in, const int* in_sizes, int n_in,
                              void* d_out, int out_size) {
    const void* ei        = d_in[0];
    const float* raw_time = (const float*)d_in[1];
    const float* noise    = (const float*)d_in[2];
    const float* node_emb = (const float*)d_in[3];
    const float* wq1 = (const float*)d_in[4],  *bq1 = (const float*)d_in[5];
    const float* wk1 = (const float*)d_in[6],  *bk1 = (const float*)d_in[7];
    const float* wv1 = (const float*)d_in[8],  *bv1 = (const float*)d_in[9];
    const float* wt1 = (const float*)d_in[10], *bt1 = (const float*)d_in[11];
    const float* wq2 = (const float*)d_in[12], *bq2 = (const float*)d_in[13];
    const float* wk2 = (const float*)d_in[14], *bk2 = (const float*)d_in[15];
    const float* wv2 = (const float*)d_in[16], *bv2 = (const float*)d_in[17];
    const float* wt2 = (const float*)d_in[18], *bt2 = (const float*)d_in[19];
    const float* wc  = (const float*)d_in[20], *bc  = (const float*)d_in[21];
    float* out = (float*)d_out;

    float *te, *tenc1, *tenc2, *q, *k, *v, *x1, *x2;
    cudaGetSymbolAddress((void**)&te,    g_te);
    cudaGetSymbolAddress((void**)&tenc1, g_tenc1);
    cudaGetSymbolAddress((void**)&tenc2, g_tenc2);
    cudaGetSymbolAddress((void**)&q,     g_q);
    cudaGetSymbolAddress((void**)&k,     g_k);
    cudaGetSymbolAddress((void**)&v,     g_v);
    cudaGetSymbolAddress((void**)&x1,    g_x1);
    cudaGetSymbolAddress((void**)&x2,    g_x2);

    dim3 gN(HC / 64, (N_NODES + 63) / 64);   // (4, 313)
    dim3 gE(HC / 64, N_EDGES / 64);          // (4, 5000)
    const int EB = N_EDGES / 8;              // 40000 blocks, warp/edge

    // index dtype detection + int32 conversion
    detect_idx_kernel<<<1, 32>>>((const unsigned int*)ei);
    convert_idx_kernel<<<(2 * N_EDGES + 255) / 256, 256>>>((const int*)ei);

    // time encoding + time projections (shared by both layers)
    time_encode_kernel<<<EB, 256>>>(raw_time, noise);
    sgemm_bias_kernel<<<gE, 256>>>(te, wt1, bt1, tenc1, N_EDGES, TD);
    sgemm_bias_kernel<<<gE, 256>>>(te, wt2, bt2, tenc2, N_EDGES, TD);

    // ---- layer 1 ----
    sgemm_bias_kernel<<<gN, 256>>>(node_emb, wq1, bq1, q, N_NODES, 128);
    sgemm_bias_kernel<<<gN, 256>>>(node_emb, wk1, bk1, k, N_NODES, 128);
    sgemm_bias_kernel<<<gN, 256>>>(node_emb, wv1, bv1, v, N_NODES, 128);
    init_kernel<<<(N_NODES * HC + 255) / 256, 256>>>(x1);
    edge_alpha_kernel<<<EB, 256>>>(q, k, tenc1);
    edge_exp_kernel<<<(N_EDGES * HEADS + 255) / 256, 256>>>();
    edge_agg_kernel<<<EB, 256>>>(v, x1);
    relu_kernel<<<(N_NODES * HC + 255) / 256, 256>>>(x1, N_NODES * HC);

    // ---- layer 2 ----
    sgemm_bias_kernel<<<gN, 256>>>(x1, wq2, bq2, q, N_NODES, 256);
    sgemm_bias_kernel<<<gN, 256>>>(x1, wk2, bk2, k, N_NODES, 256);
    sgemm_bias_kernel<<<gN, 256>>>(x1, wv2, bv2, v, N_NODES, 256);
    init_kernel<<<(N_NODES * HC + 255) / 256, 256>>>(x2);
    edge_alpha_kernel<<<EB, 256>>>(q, k, tenc2);
    edge_exp_kernel<<<(N_EDGES * HEADS + 255) / 256, 256>>>();
    edge_agg_kernel<<<EB, 256>>>(v, x2);
    relu_kernel<<<(N_NODES * HC + 255) / 256, 256>>>(x2, N_NODES * HC);

    // ---- edge readout ----
    edge_out_kernel<<<EB, 256>>>(x2, wc, bc, out);
}

// round 6
// speedup vs baseline: 2.0196x; 2.0196x over previous
#include <cuda_runtime.h>
#include <math.h>
#include <stdint.h>

#define N_NODES 20000
#define N_EDGES 320000
#define HC      256     // HEADS*HIDDEN
#define HEADS   4
#define HIDDEN  64
#define TD      64

// ---------------- scratch (device globals; no runtime allocation) ----------------
__device__ float g_te [(size_t)N_EDGES * TD];       //  82 MB
__device__ float g_q  [(size_t)N_NODES * HC];
__device__ float g_k  [(size_t)N_NODES * HC];
__device__ float g_v  [(size_t)N_NODES * HC];
__device__ float g_qt [(size_t)N_NODES * HC];       // per-node time-proj of q
__device__ float g_qb [(size_t)N_NODES * HEADS];    // q · bt per head
__device__ float g_x1 [(size_t)N_NODES * HC];
__device__ float g_x2 [(size_t)N_NODES * HC];
__device__ float g_alpha[(size_t)N_EDGES * HEADS];
__device__ float g_amax [(size_t)N_NODES * HEADS];
__device__ float g_denom[(size_t)N_NODES * HEADS];
__device__ int   g_src[N_EDGES];
__device__ int   g_dst[N_EDGES];
__device__ int   g_is64;

// ---------------- edge_index dtype detection + conversion ----------------
__global__ void detect_idx_kernel(const unsigned int* __restrict__ w) {
    if (threadIdx.x == 0 && blockIdx.x == 0) {
        int ok = 1;
        for (int i = 0; i < 256; i++) {
            unsigned lo = w[2 * i], hi = w[2 * i + 1];
            if (hi != 0u || lo >= (unsigned)N_NODES) { ok = 0; break; }
        }
        g_is64 = ok;
    }
}

__global__ void convert_idx_kernel(const int* __restrict__ w) {
    int i = blockIdx.x * blockDim.x + threadIdx.x;
    if (i >= 2 * N_EDGES) return;
    int v = g_is64 ? w[2 * i] : w[i];    // little-endian low word
    if (i < N_EDGES) g_src[i] = v;
    else             g_dst[i - N_EDGES] = v;
}

// ---------------- time encoding ----------------
__global__ void time_encode_kernel(const float* __restrict__ raw, const float* __restrict__ noise) {
    int e = blockIdx.x * 8 + (threadIdx.x >> 5);
    int lane = threadIdx.x & 31;
    if (e >= N_EDGES) return;
    float t = raw[e] + noise[e];
    const float cst = -0.14391156831212787f;        // -ln(10000)/64
    float div = expf((float)(2 * lane) * cst);
    float arg = t * div;
    double kd = rint((double)arg * 0.15915494309189535);   // 1/(2*pi)
    double r  = fma(-kd, 6.283185307179586, (double)arg);
    float rf = (float)r;
    float s = sinf(rf);
    float c = cosf(rf);
    g_te[(size_t)e * TD + 2 * lane]     = s;
    g_te[(size_t)e * TD + 2 * lane + 1] = c;
}

// ---------------- generic fp32 GEMM+bias: C[M,256] = A[M,K] @ W[K,256] + b ----------------
// reluA != 0 applies relu to A elements on load (folds previous layer's relu).
__global__ void sgemm_bias_kernel(const float* __restrict__ A, const float* __restrict__ W,
                                  const float* __restrict__ bias, float* __restrict__ C,
                                  int M, int K, int reluA) {
    const int N = HC; // 256
    __shared__ float sA[16][64];
    __shared__ float sW[16][64];

    int tid = threadIdx.x;          // 256 threads
    int tx = tid & 15, ty = tid >> 4;
    int bm = blockIdx.y * 64, bn = blockIdx.x * 64;

    int lr = tid >> 2;              // 0..63  A-load row
    int lc = (tid & 3) << 2;        // 0,4,8,12 A-load col
    int wr = tid >> 4;              // 0..15  W-load row
    int wcol = (tid & 15) << 2;     // 0..60  W-load col

    float acc[4][4];
#pragma unroll
    for (int i = 0; i < 4; i++)
#pragma unroll
        for (int j = 0; j < 4; j++) acc[i][j] = 0.f;

    for (int k0 = 0; k0 < K; k0 += 16) {
        float4 av = make_float4(0.f, 0.f, 0.f, 0.f);
        if (bm + lr < M)
            av = *(const float4*)(A + (size_t)(bm + lr) * K + k0 + lc);
        if (reluA) {
            av.x = fmaxf(av.x, 0.f); av.y = fmaxf(av.y, 0.f);
            av.z = fmaxf(av.z, 0.f); av.w = fmaxf(av.w, 0.f);
        }
        sA[lc + 0][lr] = av.x;
        sA[lc + 1][lr] = av.y;
        sA[lc + 2][lr] = av.z;
        sA[lc + 3][lr] = av.w;
        float4 wv = *(const float4*)(W + (size_t)(k0 + wr) * N + bn + wcol);
        *(float4*)&sW[wr][wcol] = wv;
        __syncthreads();
#pragma unroll
        for (int kk = 0; kk < 16; kk++) {
            float4 a = *(const float4*)&sA[kk][ty * 4];
            float4 w = *(const float4*)&sW[kk][tx * 4];
            float ar[4] = {a.x, a.y, a.z, a.w};
            float wr4[4] = {w.x, w.y, w.z, w.w};
#pragma unroll
            for (int i = 0; i < 4; i++)
#pragma unroll
                for (int j = 0; j < 4; j++)
                    acc[i][j] = fmaf(ar[i], wr4[j], acc[i][j]);
        }
        __syncthreads();
    }

    float4 bv = *(const float4*)(bias + bn + tx * 4);
    float bb[4] = {bv.x, bv.y, bv.z, bv.w};
#pragma unroll
    for (int i = 0; i < 4; i++) {
        int m = bm + ty * 4 + i;
        if (m < M) {
            float4 o;
            o.x = acc[i][0] + bb[0];
            o.y = acc[i][1] + bb[1];
            o.z = acc[i][2] + bb[2];
            o.w = acc[i][3] + bb[3];
            *(float4*)(C + (size_t)m * N + bn + tx * 4) = o;
        }
    }
}

// ---------------- per-node time transform of q ----------------
// qt[d, h*64+j] = sum_c q[d,h*64+c] * wt[j, h*64+c]      (wt is [TD=64, HC])
// qb[d, h]      = sum_c q[d,h*64+c] * bt[h*64+c]
// NOTE: padded row stride 68 (multiple of 4) so float4 ld/st stay 16B-aligned.
__global__ void qt_kernel(const float* __restrict__ q, const float* __restrict__ wt,
                          const float* __restrict__ bt,
                          float* __restrict__ qt, float* __restrict__ qb) {
    __shared__ float sQ[64][68];   // q rows x channel
    __shared__ float sW[64][68];   // wt j x channel
    __shared__ float sB[64];
    int h = blockIdx.x;
    int bm = blockIdx.y * 64;
    int tid = threadIdx.x;         // 256

    int lr = tid >> 2;             // 0..63
    int lc = (tid & 3) * 16;       // 0,16,32,48
#pragma unroll
    for (int i = 0; i < 16; i += 4) {
        float4 v = make_float4(0.f, 0.f, 0.f, 0.f);
        if (bm + lr < N_NODES)
            v = *(const float4*)(q + (size_t)(bm + lr) * HC + h * 64 + lc + i);
        *(float4*)&sQ[lr][lc + i] = v;
        *(float4*)&sW[lr][lc + i] = *(const float4*)(wt + (size_t)lr * HC + h * 64 + lc + i);
    }
    if (tid < 64) sB[tid] = bt[h * 64 + tid];
    __syncthreads();

    int tx = tid & 15, ty = tid >> 4;    // out: rows ty*4.., j tx*4..
    float acc[4][4];
#pragma unroll
    for (int i = 0; i < 4; i++)
#pragma unroll
        for (int j = 0; j < 4; j++) acc[i][j] = 0.f;
#pragma unroll 8
    for (int c = 0; c < 64; c++) {
        float a0 = sQ[ty * 4 + 0][c], a1 = sQ[ty * 4 + 1][c];
        float a2 = sQ[ty * 4 + 2][c], a3 = sQ[ty * 4 + 3][c];
        float w0 = sW[tx * 4 + 0][c], w1 = sW[tx * 4 + 1][c];
        float w2 = sW[tx * 4 + 2][c], w3 = sW[tx * 4 + 3][c];
        acc[0][0] = fmaf(a0, w0, acc[0][0]); acc[0][1] = fmaf(a0, w1, acc[0][1]);
        acc[0][2] = fmaf(a0, w2, acc[0][2]); acc[0][3] = fmaf(a0, w3, acc[0][3]);
        acc[1][0] = fmaf(a1, w0, acc[1][0]); acc[1][1] = fmaf(a1, w1, acc[1][1]);
        acc[1][2] = fmaf(a1, w2, acc[1][2]); acc[1][3] = fmaf(a1, w3, acc[1][3]);
        acc[2][0] = fmaf(a2, w0, acc[2][0]); acc[2][1] = fmaf(a2, w1, acc[2][1]);
        acc[2][2] = fmaf(a2, w2, acc[2][2]); acc[2][3] = fmaf(a2, w3, acc[2][3]);
        acc[3][0] = fmaf(a3, w0, acc[3][0]); acc[3][1] = fmaf(a3, w1, acc[3][1]);
        acc[3][2] = fmaf(a3, w2, acc[3][2]); acc[3][3] = fmaf(a3, w3, acc[3][3]);
    }
#pragma unroll
    for (int i = 0; i < 4; i++) {
        int m = bm + ty * 4 + i;
        if (m < N_NODES) {
            float4 o = make_float4(acc[i][0], acc[i][1], acc[i][2], acc[i][3]);
            *(float4*)(qt + (size_t)m * HC + h * 64 + tx * 4) = o;
        }
    }

    // qb: 4 threads per row, 16 channels each
    {
        int row = tid >> 2, part = tid & 3;
        float ssum = 0.f;
#pragma unroll
        for (int c = part * 16; c < part * 16 + 16; c++)
            ssum += sQ[row][c] * sB[c];
        ssum += __shfl_down_sync(0xffffffffu, ssum, 2, 4);
        ssum += __shfl_down_sync(0xffffffffu, ssum, 1, 4);
        if (part == 0 && bm + row < N_NODES)
            qb[(size_t)(bm + row) * HEADS + h] = ssum;
    }
}

// ---------------- per-layer init ----------------
__global__ void init_kernel(float* __restrict__ xout) {
    int i = blockIdx.x * blockDim.x + threadIdx.x;
    if (i < N_NODES * HC) xout[i] = 0.f;
    if (i < N_NODES * HEADS) {
        g_amax[i] = -3.402823466e38f;
        g_denom[i] = 0.f;
    }
}

__device__ __forceinline__ void atomicMaxFloat(float* addr, float v) {
    if (v >= 0.f) atomicMax((int*)addr, __float_as_int(v));
    else          atomicMin((unsigned int*)addr, __float_as_uint(v));
}

// ---------------- pass A: alpha = (q·k + te·qt[d] + qb[d]) / 8; amax ----------------
__global__ void edge_alpha_kernel(const float* __restrict__ q, const float* __restrict__ k,
                                  const float* __restrict__ qt, const float* __restrict__ qb) {
    int e = blockIdx.x * 8 + (threadIdx.x >> 5);
    int lane = threadIdx.x & 31;
    if (e >= N_EDGES) return;
    int s = g_src[e], d = g_dst[e];
    int c0 = lane * 8;             // == h*64 + (lane&7)*8
    int j0 = (lane & 7) * 8;
    const float4* qp = (const float4*)(q  + (size_t)d * HC + c0);
    const float4* kp = (const float4*)(k  + (size_t)s * HC + c0);
    const float4* wp = (const float4*)(qt + (size_t)d * HC + c0);
    const float4* tp = (const float4*)(g_te + (size_t)e * TD + j0);
    float4 q0 = qp[0], q1 = qp[1];
    float4 k0 = kp[0], k1 = kp[1];
    float4 w0 = wp[0], w1 = wp[1];
    float4 t0 = tp[0], t1 = tp[1];
    float p = q0.x * k0.x + q0.y * k0.y + q0.z * k0.z + q0.w * k0.w
            + q1.x * k1.x + q1.y * k1.y + q1.z * k1.z + q1.w * k1.w
            + w0.x * t0.x + w0.y * t0.y + w0.z * t0.z + w0.w * t0.w
            + w1.x * t1.x + w1.y * t1.y + w1.z * t1.z + w1.w * t1.w;
    p += __shfl_down_sync(0xffffffffu, p, 4, 8);
    p += __shfl_down_sync(0xffffffffu, p, 2, 8);
    p += __shfl_down_sync(0xffffffffu, p, 1, 8);
    if ((lane & 7) == 0) {
        int h = lane >> 3;
        float alpha = (p + qb[(size_t)d * HEADS + h]) * 0.125f;   // / sqrt(64)
        g_alpha[(size_t)e * HEADS + h] = alpha;
        atomicMaxFloat(&g_amax[(size_t)d * HEADS + h], alpha);
    }
}

// ---------------- pass B: ea = exp(alpha - amax[dst]); denom += ea ----------------
__global__ void edge_exp_kernel() {
    int i = blockIdx.x * blockDim.x + threadIdx.x;
    if (i >= N_EDGES * HEADS) return;
    int e = i >> 2, h = i & 3;
    int d = g_dst[e];
    float ea = expf(g_alpha[i] - g_amax[(size_t)d * HEADS + h]);
    g_alpha[i] = ea;
    atomicAdd(&g_denom[(size_t)d * HEADS + h], ea);
}

// ---------------- pass C: out[dst] += v[src] * (ea/denom[dst]) ----------------
__global__ void edge_agg_kernel(const float* __restrict__ v, float* __restrict__ xout) {
    int e = blockIdx.x * 8 + (threadIdx.x >> 5);
    int lane = threadIdx.x & 31;
    if (e >= N_EDGES) return;
    int s = g_src[e], d = g_dst[e];
    int h = lane >> 3;
    float a = g_alpha[(size_t)e * HEADS + h] / (g_denom[(size_t)d * HEADS + h] + 1e-16f);
    int c0 = lane * 8;
    float4 v0 = *(const float4*)(v + (size_t)s * HC + c0);
    float4 v1 = *(const float4*)(v + (size_t)s * HC + c0 + 4);
    float* o = xout + (size_t)d * HC + c0;
#if __CUDA_ARCH__ >= 900
    atomicAdd((float4*)o,       make_float4(v0.x * a, v0.y * a, v0.z * a, v0.w * a));
    atomicAdd((float4*)(o + 4), make_float4(v1.x * a, v1.y * a, v1.z * a, v1.w * a));
#else
    atomicAdd(o + 0, v0.x * a); atomicAdd(o + 1, v0.y * a);
    atomicAdd(o + 2, v0.z * a); atomicAdd(o + 3, v0.w * a);
    atomicAdd(o + 4, v1.x * a); atomicAdd(o + 5, v1.y * a);
    atomicAdd(o + 6, v1.z * a); atomicAdd(o + 7, v1.w * a);
#endif
}

// ---------------- final: out[e] = <relu(x[src])+relu(x[dst]), wc> + bc ----------------
__global__ void edge_out_kernel(const float* __restrict__ x, const float* __restrict__ wc,
                                const float* __restrict__ bc, float* __restrict__ out) {
    int e = blockIdx.x * 8 + (threadIdx.x >> 5);
    int lane = threadIdx.x & 31;
    if (e >= N_EDGES) return;
    int s = g_src[e], d = g_dst[e];
    int c0 = lane * 8;
    const float4* xs = (const float4*)(x + (size_t)s * HC + c0);
    const float4* xd = (const float4*)(x + (size_t)d * HC + c0);
    const float4* wp = (const float4*)(wc + c0);
    float4 s0 = xs[0], s1 = xs[1];
    float4 d0 = xd[0], d1 = xd[1];
    float4 w0 = wp[0], w1 = wp[1];
    float p = (fmaxf(s0.x, 0.f) + fmaxf(d0.x, 0.f)) * w0.x
            + (fmaxf(s0.y, 0.f) + fmaxf(d0.y, 0.f)) * w0.y
            + (fmaxf(s0.z, 0.f) + fmaxf(d0.z, 0.f)) * w0.z
            + (fmaxf(s0.w, 0.f) + fmaxf(d0.w, 0.f)) * w0.w
            + (fmaxf(s1.x, 0.f) + fmaxf(d1.x, 0.f)) * w1.x
            + (fmaxf(s1.y, 0.f) + fmaxf(d1.y, 0.f)) * w1.y
            + (fmaxf(s1.z, 0.f) + fmaxf(d1.z, 0.f)) * w1.z
            + (fmaxf(s1.w, 0.f) + fmaxf(d1.w, 0.f)) * w1.w;
#pragma unroll
    for (int off = 16; off >= 1; off >>= 1)
        p += __shfl_down_sync(0xffffffffu, p, off);
    if (lane == 0) out[e] = p + bc[0];
}

// ---------------- launch ----------------
extern "C" void kernel_launch(void* const* d_in, const int* in_sizes, int n_in,
                              void* d_out, int out_size) {
    const void* ei        = d_in[0];
    const float* raw_time = (const float*)d_in[1];
    const float* noise    = (const float*)d_in[2];
    const float* node_emb = (const float*)d_in[3];
    const float* wq1 = (const float*)d_in[4],  *bq1 = (const float*)d_in[5];
    const float* wk1 = (const float*)d_in[6],  *bk1 = (const float*)d_in[7];
    const float* wv1 = (const float*)d_in[8],  *bv1 = (const float*)d_in[9];
    const float* wt1 = (const float*)d_in[10], *bt1 = (const float*)d_in[11];
    const float* wq2 = (const float*)d_in[12], *bq2 = (const float*)d_in[13];
    const float* wk2 = (const float*)d_in[14], *bk2 = (const float*)d_in[15];
    const float* wv2 = (const float*)d_in[16], *bv2 = (const float*)d_in[17];
    const float* wt2 = (const float*)d_in[18], *bt2 = (const float*)d_in[19];
    const float* wc  = (const float*)d_in[20], *bc  = (const float*)d_in[21];
    float* out = (float*)d_out;

    float *q, *k, *v, *qt, *qb, *x1, *x2;
    cudaGetSymbolAddress((void**)&q,  g_q);
    cudaGetSymbolAddress((void**)&k,  g_k);
    cudaGetSymbolAddress((void**)&v,  g_v);
    cudaGetSymbolAddress((void**)&qt, g_qt);
    cudaGetSymbolAddress((void**)&qb, g_qb);
    cudaGetSymbolAddress((void**)&x1, g_x1);
    cudaGetSymbolAddress((void**)&x2, g_x2);

    dim3 gN(HC / 64, (N_NODES + 63) / 64);   // (4, 313)
    dim3 gQT(HEADS, (N_NODES + 63) / 64);    // (4, 313)
    const int EB = N_EDGES / 8;              // 40000 blocks, warp/edge

    // index dtype detection + int32 conversion
    detect_idx_kernel<<<1, 32>>>((const unsigned int*)ei);
    convert_idx_kernel<<<(2 * N_EDGES + 255) / 256, 256>>>((const int*)ei);

    // time encoding (shared by both layers)
    time_encode_kernel<<<EB, 256>>>(raw_time, noise);

    // ---- layer 1 ----
    sgemm_bias_kernel<<<gN, 256>>>(node_emb, wq1, bq1, q, N_NODES, 128, 0);
    sgemm_bias_kernel<<<gN, 256>>>(node_emb, wk1, bk1, k, N_NODES, 128, 0);
    sgemm_bias_kernel<<<gN, 256>>>(node_emb, wv1, bv1, v, N_NODES, 128, 0);
    qt_kernel<<<gQT, 256>>>(q, wt1, bt1, qt, qb);
    init_kernel<<<(N_NODES * HC + 255) / 256, 256>>>(x1);
    edge_alpha_kernel<<<EB, 256>>>(q, k, qt, qb);
    edge_exp_kernel<<<(N_EDGES * HEADS + 255) / 256, 256>>>();
    edge_agg_kernel<<<EB, 256>>>(v, x1);

    // ---- layer 2 (relu of x1 folded into GEMM A-loads) ----
    sgemm_bias_kernel<<<gN, 256>>>(x1, wq2, bq2, q, N_NODES, 256, 1);
    sgemm_bias_kernel<<<gN, 256>>>(x1, wk2, bk2, k, N_NODES, 256, 1);
    sgemm_bias_kernel<<<gN, 256>>>(x1, wv2, bv2, v, N_NODES, 256, 1);
    qt_kernel<<<gQT, 256>>>(q, wt2, bt2, qt, qb);
    init_kernel<<<(N_NODES * HC + 255) / 256, 256>>>(x2);
    edge_alpha_kernel<<<EB, 256>>>(q, k, qt, qb);
    edge_exp_kernel<<<(N_EDGES * HEADS + 255) / 256, 256>>>();
    edge_agg_kernel<<<EB, 256>>>(v, x2);

    // ---- edge readout (relu of x2 folded in) ----
    edge_out_kernel<<<EB, 256>>>(x2, wc, bc, out);
}

// round 7
// speedup vs baseline: 2.4983x; 1.2371x over previous
#include <cuda_runtime.h>
#include <math.h>
#include <stdint.h>

#define N_NODES 20000
#define N_EDGES 320000
#define HC      256     // HEADS*HIDDEN
#define HEADS   4
#define HIDDEN  64
#define TD      64

// ---------------- scratch (device globals; no runtime allocation) ----------------
__device__ float g_te [(size_t)N_EDGES * TD];       //  82 MB
__device__ float g_q  [(size_t)N_NODES * HC];
__device__ float g_k  [(size_t)N_NODES * HC];
__device__ float g_v  [(size_t)N_NODES * HC];
__device__ float g_qt [(size_t)N_NODES * HC];       // per-node time-proj of q
__device__ float g_qb [(size_t)N_NODES * HEADS];    // q · bt per head
__device__ float g_x1 [(size_t)N_NODES * HC];
__device__ float g_x2 [(size_t)N_NODES * HC];
__device__ float g_y  [N_NODES];                    // per-node readout dot
__device__ float g_alpha[(size_t)N_EDGES * HEADS];
__device__ float g_amax [(size_t)N_NODES * HEADS];
__device__ float g_denom[(size_t)N_NODES * HEADS];
__device__ int   g_src[N_EDGES];
__device__ int   g_dst[N_EDGES];
__device__ int   g_is64;

// ---------------- edge_index dtype detection + conversion ----------------
__global__ void detect_idx_kernel(const unsigned int* __restrict__ w) {
    if (threadIdx.x == 0 && blockIdx.x == 0) {
        int ok = 1;
        for (int i = 0; i < 256; i++) {
            unsigned lo = w[2 * i], hi = w[2 * i + 1];
            if (hi != 0u || lo >= (unsigned)N_NODES) { ok = 0; break; }
        }
        g_is64 = ok;
    }
}

__global__ void convert_idx_kernel(const int* __restrict__ w) {
    int i = blockIdx.x * blockDim.x + threadIdx.x;
    if (i >= 2 * N_EDGES) return;
    int v = g_is64 ? w[2 * i] : w[i];    // little-endian low word
    if (i < N_EDGES) g_src[i] = v;
    else             g_dst[i - N_EDGES] = v;
}

// ---------------- time encoding (fp32 Cody-Waite range reduction) ----------------
__global__ void time_encode_kernel(const float* __restrict__ raw, const float* __restrict__ noise) {
    int e = blockIdx.x * 8 + (threadIdx.x >> 5);
    int lane = threadIdx.x & 31;
    if (e >= N_EDGES) return;
    float t = raw[e] + noise[e];
    const float cst = -0.14391156831212787f;        // -ln(10000)/64
    float div = expf((float)(2 * lane) * cst);
    float arg = t * div;
    // Cody-Waite: 2*pi = 6.28125 (8-bit mantissa; k*PI_HI exact for k<2^16) + 1.9353072e-3
    float kf = rintf(arg * 0.15915494309189535f);
    float r  = fmaf(-kf, 6.28125f, arg);
    r = fmaf(-kf, 1.9353071795864792e-3f, r);
    float s = __sinf(r);
    float c = __cosf(r);
    g_te[(size_t)e * TD + 2 * lane]     = s;
    g_te[(size_t)e * TD + 2 * lane + 1] = c;
}

// ---------------- fused QKV GEMM: C{q,k,v}[M,256] = A[M,K] @ W{q,k,v} + b ----------------
// 128x64 tile, 256 threads, 8x4 outputs/thread. blockIdx.z selects q/k/v.
__global__ void sgemm3_kernel(const float* __restrict__ A,
                              const float* __restrict__ W0, const float* __restrict__ W1,
                              const float* __restrict__ W2,
                              const float* __restrict__ b0, const float* __restrict__ b1,
                              const float* __restrict__ b2,
                              float* __restrict__ C0, float* __restrict__ C1,
                              float* __restrict__ C2,
                              int M, int K, int reluA) {
    const int N = HC;
    const float* W    = blockIdx.z == 0 ? W0 : (blockIdx.z == 1 ? W1 : W2);
    const float* bias = blockIdx.z == 0 ? b0 : (blockIdx.z == 1 ? b1 : b2);
    float*       C    = blockIdx.z == 0 ? C0 : (blockIdx.z == 1 ? C1 : C2);

    __shared__ float sA[16][128];
    __shared__ float sW[16][64];

    int tid = threadIdx.x;              // 256
    int tx = tid & 15, ty = tid >> 4;
    int bm = blockIdx.y * 128, bn = blockIdx.x * 64;

    int ar = tid >> 1;                  // 0..127
    int ac = (tid & 1) * 8;             // 0 or 8
    int wr = tid >> 4;                  // 0..15
    int wcol = (tid & 15) * 4;          // 0..60

    float acc[8][4];
#pragma unroll
    for (int i = 0; i < 8; i++)
#pragma unroll
        for (int j = 0; j < 4; j++) acc[i][j] = 0.f;

    for (int k0 = 0; k0 < K; k0 += 16) {
        float4 a0 = make_float4(0.f, 0.f, 0.f, 0.f);
        float4 a1 = make_float4(0.f, 0.f, 0.f, 0.f);
        if (bm + ar < M) {
            a0 = *(const float4*)(A + (size_t)(bm + ar) * K + k0 + ac);
            a1 = *(const float4*)(A + (size_t)(bm + ar) * K + k0 + ac + 4);
        }
        if (reluA) {
            a0.x = fmaxf(a0.x, 0.f); a0.y = fmaxf(a0.y, 0.f);
            a0.z = fmaxf(a0.z, 0.f); a0.w = fmaxf(a0.w, 0.f);
            a1.x = fmaxf(a1.x, 0.f); a1.y = fmaxf(a1.y, 0.f);
            a1.z = fmaxf(a1.z, 0.f); a1.w = fmaxf(a1.w, 0.f);
        }
        sA[ac + 0][ar] = a0.x; sA[ac + 1][ar] = a0.y;
        sA[ac + 2][ar] = a0.z; sA[ac + 3][ar] = a0.w;
        sA[ac + 4][ar] = a1.x; sA[ac + 5][ar] = a1.y;
        sA[ac + 6][ar] = a1.z; sA[ac + 7][ar] = a1.w;
        *(float4*)&sW[wr][wcol] = *(const float4*)(W + (size_t)(k0 + wr) * N + bn + wcol);
        __syncthreads();
#pragma unroll
        for (int kk = 0; kk < 16; kk++) {
            float4 w = *(const float4*)&sW[kk][tx * 4];
            float a[8];
#pragma unroll
            for (int i = 0; i < 8; i++) a[i] = sA[kk][ty * 8 + i];
#pragma unroll
            for (int i = 0; i < 8; i++) {
                acc[i][0] = fmaf(a[i], w.x, acc[i][0]);
                acc[i][1] = fmaf(a[i], w.y, acc[i][1]);
                acc[i][2] = fmaf(a[i], w.z, acc[i][2]);
                acc[i][3] = fmaf(a[i], w.w, acc[i][3]);
            }
        }
        __syncthreads();
    }

    float4 bv = *(const float4*)(bias + bn + tx * 4);
#pragma unroll
    for (int i = 0; i < 8; i++) {
        int m = bm + ty * 8 + i;
        if (m < M) {
            float4 o;
            o.x = acc[i][0] + bv.x;
            o.y = acc[i][1] + bv.y;
            o.z = acc[i][2] + bv.z;
            o.w = acc[i][3] + bv.w;
            *(float4*)(C + (size_t)m * N + bn + tx * 4) = o;
        }
    }
}

// ---------------- per-node time transform of q ----------------
// qt[d, h*64+j] = sum_c q[d,h*64+c] * wt[j, h*64+c]      (wt is [TD=64, HC])
// qb[d, h]      = sum_c q[d,h*64+c] * bt[h*64+c]
__global__ void qt_kernel(const float* __restrict__ q, const float* __restrict__ wt,
                          const float* __restrict__ bt,
                          float* __restrict__ qt, float* __restrict__ qb) {
    __shared__ float sQ[64][68];   // stride 68: 16B-aligned float4 + bank rotation
    __shared__ float sW[64][68];
    __shared__ float sB[64];
    int h = blockIdx.x;
    int bm = blockIdx.y * 64;
    int tid = threadIdx.x;         // 256

    int lr = tid >> 2;             // 0..63
    int lc = (tid & 3) * 16;       // 0,16,32,48
#pragma unroll
    for (int i = 0; i < 16; i += 4) {
        float4 v = make_float4(0.f, 0.f, 0.f, 0.f);
        if (bm + lr < N_NODES)
            v = *(const float4*)(q + (size_t)(bm + lr) * HC + h * 64 + lc + i);
        *(float4*)&sQ[lr][lc + i] = v;
        *(float4*)&sW[lr][lc + i] = *(const float4*)(wt + (size_t)lr * HC + h * 64 + lc + i);
    }
    if (tid < 64) sB[tid] = bt[h * 64 + tid];
    __syncthreads();

    int tx = tid & 15, ty = tid >> 4;
    float acc[4][4];
#pragma unroll
    for (int i = 0; i < 4; i++)
#pragma unroll
        for (int j = 0; j < 4; j++) acc[i][j] = 0.f;
#pragma unroll 8
    for (int c = 0; c < 64; c++) {
        float a0 = sQ[ty * 4 + 0][c], a1 = sQ[ty * 4 + 1][c];
        float a2 = sQ[ty * 4 + 2][c], a3 = sQ[ty * 4 + 3][c];
        float w0 = sW[tx * 4 + 0][c], w1 = sW[tx * 4 + 1][c];
        float w2 = sW[tx * 4 + 2][c], w3 = sW[tx * 4 + 3][c];
        acc[0][0] = fmaf(a0, w0, acc[0][0]); acc[0][1] = fmaf(a0, w1, acc[0][1]);
        acc[0][2] = fmaf(a0, w2, acc[0][2]); acc[0][3] = fmaf(a0, w3, acc[0][3]);
        acc[1][0] = fmaf(a1, w0, acc[1][0]); acc[1][1] = fmaf(a1, w1, acc[1][1]);
        acc[1][2] = fmaf(a1, w2, acc[1][2]); acc[1][3] = fmaf(a1, w3, acc[1][3]);
        acc[2][0] = fmaf(a2, w0, acc[2][0]); acc[2][1] = fmaf(a2, w1, acc[2][1]);
        acc[2][2] = fmaf(a2, w2, acc[2][2]); acc[2][3] = fmaf(a2, w3, acc[2][3]);
        acc[3][0] = fmaf(a3, w0, acc[3][0]); acc[3][1] = fmaf(a3, w1, acc[3][1]);
        acc[3][2] = fmaf(a3, w2, acc[3][2]); acc[3][3] = fmaf(a3, w3, acc[3][3]);
    }
#pragma unroll
    for (int i = 0; i < 4; i++) {
        int m = bm + ty * 4 + i;
        if (m < N_NODES) {
            float4 o = make_float4(acc[i][0], acc[i][1], acc[i][2], acc[i][3]);
            *(float4*)(qt + (size_t)m * HC + h * 64 + tx * 4) = o;
        }
    }

    {
        int row = tid >> 2, part = tid & 3;
        float ssum = 0.f;
#pragma unroll
        for (int c = part * 16; c < part * 16 + 16; c++)
            ssum += sQ[row][c] * sB[c];
        ssum += __shfl_down_sync(0xffffffffu, ssum, 2, 4);
        ssum += __shfl_down_sync(0xffffffffu, ssum, 1, 4);
        if (part == 0 && bm + row < N_NODES)
            qb[(size_t)(bm + row) * HEADS + h] = ssum;
    }
}

// ---------------- per-layer init ----------------
__global__ void init_kernel(float* __restrict__ xout) {
    int i = blockIdx.x * blockDim.x + threadIdx.x;
    if (i < N_NODES * HC) xout[i] = 0.f;
    if (i < N_NODES * HEADS) {
        g_amax[i] = -3.402823466e38f;
        g_denom[i] = 0.f;
    }
}

__device__ __forceinline__ void atomicMaxFloat(float* addr, float v) {
    if (v >= 0.f) atomicMax((int*)addr, __float_as_int(v));
    else          atomicMin((unsigned int*)addr, __float_as_uint(v));
}

// ---------------- pass A: alpha = (q·k + te·qt[d] + qb[d]) / 8; amax ----------------
__global__ void edge_alpha_kernel(const float* __restrict__ q, const float* __restrict__ k,
                                  const float* __restrict__ qt, const float* __restrict__ qb) {
    int e = blockIdx.x * 8 + (threadIdx.x >> 5);
    int lane = threadIdx.x & 31;
    if (e >= N_EDGES) return;
    int s = g_src[e], d = g_dst[e];
    int c0 = lane * 8;             // == h*64 + (lane&7)*8
    int j0 = (lane & 7) * 8;
    const float4* qp = (const float4*)(q  + (size_t)d * HC + c0);
    const float4* kp = (const float4*)(k  + (size_t)s * HC + c0);
    const float4* wp = (const float4*)(qt + (size_t)d * HC + c0);
    const float4* tp = (const float4*)(g_te + (size_t)e * TD + j0);
    float4 q0 = qp[0], q1 = qp[1];
    float4 k0 = kp[0], k1 = kp[1];
    float4 w0 = wp[0], w1 = wp[1];
    float4 t0 = tp[0], t1 = tp[1];
    float p = q0.x * k0.x + q0.y * k0.y + q0.z * k0.z + q0.w * k0.w
            + q1.x * k1.x + q1.y * k1.y + q1.z * k1.z + q1.w * k1.w
            + w0.x * t0.x + w0.y * t0.y + w0.z * t0.z + w0.w * t0.w
            + w1.x * t1.x + w1.y * t1.y + w1.z * t1.z + w1.w * t1.w;
    p += __shfl_down_sync(0xffffffffu, p, 4, 8);
    p += __shfl_down_sync(0xffffffffu, p, 2, 8);
    p += __shfl_down_sync(0xffffffffu, p, 1, 8);
    if ((lane & 7) == 0) {
        int h = lane >> 3;
        float alpha = (p + qb[(size_t)d * HEADS + h]) * 0.125f;   // / sqrt(64)
        g_alpha[(size_t)e * HEADS + h] = alpha;
        atomicMaxFloat(&g_amax[(size_t)d * HEADS + h], alpha);
    }
}

// ---------------- pass B: ea = exp(alpha - amax[dst]); denom += ea ----------------
__global__ void edge_exp_kernel() {
    int i = blockIdx.x * blockDim.x + threadIdx.x;
    if (i >= N_EDGES * HEADS) return;
    int e = i >> 2, h = i & 3;
    int d = g_dst[e];
    float ea = expf(g_alpha[i] - g_amax[(size_t)d * HEADS + h]);
    g_alpha[i] = ea;
    atomicAdd(&g_denom[(size_t)d * HEADS + h], ea);
}

// ---------------- pass C: out[dst] += v[src] * (ea/denom[dst]) ----------------
__global__ void edge_agg_kernel(const float* __restrict__ v, float* __restrict__ xout) {
    int e = blockIdx.x * 8 + (threadIdx.x >> 5);
    int lane = threadIdx.x & 31;
    if (e >= N_EDGES) return;
    int s = g_src[e], d = g_dst[e];
    int h = lane >> 3;
    float a = g_alpha[(size_t)e * HEADS + h] / (g_denom[(size_t)d * HEADS + h] + 1e-16f);
    int c0 = lane * 8;
    float4 v0 = *(const float4*)(v + (size_t)s * HC + c0);
    float4 v1 = *(const float4*)(v + (size_t)s * HC + c0 + 4);
    float* o = xout + (size_t)d * HC + c0;
    atomicAdd((float4*)o,       make_float4(v0.x * a, v0.y * a, v0.z * a, v0.w * a));
    atomicAdd((float4*)(o + 4), make_float4(v1.x * a, v1.y * a, v1.z * a, v1.w * a));
}

// ---------------- per-node readout: y[n] = <relu(x[n]), wc> ----------------
__global__ void node_y_kernel(const float* __restrict__ x, const float* __restrict__ wc) {
    int n = blockIdx.x * 8 + (threadIdx.x >> 5);
    int lane = threadIdx.x & 31;
    if (n >= N_NODES) return;
    int c0 = lane * 8;
    const float4* xp = (const float4*)(x + (size_t)n * HC + c0);
    const float4* wp = (const float4*)(wc + c0);
    float4 x0 = xp[0], x1 = xp[1];
    float4 w0 = wp[0], w1 = wp[1];
    float p = fmaxf(x0.x, 0.f) * w0.x + fmaxf(x0.y, 0.f) * w0.y
            + fmaxf(x0.z, 0.f) * w0.z + fmaxf(x0.w, 0.f) * w0.w
            + fmaxf(x1.x, 0.f) * w1.x + fmaxf(x1.y, 0.f) * w1.y
            + fmaxf(x1.z, 0.f) * w1.z + fmaxf(x1.w, 0.f) * w1.w;
#pragma unroll
    for (int off = 16; off >= 1; off >>= 1)
        p += __shfl_down_sync(0xffffffffu, p, off);
    if (lane == 0) g_y[n] = p;
}

// ---------------- final: out[e] = y[src] + y[dst] + bc ----------------
__global__ void edge_final_kernel(const float* __restrict__ bc, float* __restrict__ out) {
    int e = blockIdx.x * blockDim.x + threadIdx.x;
    if (e >= N_EDGES) return;
    out[e] = g_y[g_src[e]] + g_y[g_dst[e]] + bc[0];
}

// ---------------- launch ----------------
extern "C" void kernel_launch(void* const* d_in, const int* in_sizes, int n_in,
                              void* d_out, int out_size) {
    const void* ei        = d_in[0];
    const float* raw_time = (const float*)d_in[1];
    const float* noise    = (const float*)d_in[2];
    const float* node_emb = (const float*)d_in[3];
    const float* wq1 = (const float*)d_in[4],  *bq1 = (const float*)d_in[5];
    const float* wk1 = (const float*)d_in[6],  *bk1 = (const float*)d_in[7];
    const float* wv1 = (const float*)d_in[8],  *bv1 = (const float*)d_in[9];
    const float* wt1 = (const float*)d_in[10], *bt1 = (const float*)d_in[11];
    const float* wq2 = (const float*)d_in[12], *bq2 = (const float*)d_in[13];
    const float* wk2 = (const float*)d_in[14], *bk2 = (const float*)d_in[15];
    const float* wv2 = (const float*)d_in[16], *bv2 = (const float*)d_in[17];
    const float* wt2 = (const float*)d_in[18], *bt2 = (const float*)d_in[19];
    const float* wc  = (const float*)d_in[20], *bc  = (const float*)d_in[21];
    float* out = (float*)d_out;

    float *q, *k, *v, *qt, *qb, *x1, *x2;
    cudaGetSymbolAddress((void**)&q,  g_q);
    cudaGetSymbolAddress((void**)&k,  g_k);
    cudaGetSymbolAddress((void**)&v,  g_v);
    cudaGetSymbolAddress((void**)&qt, g_qt);
    cudaGetSymbolAddress((void**)&qb, g_qb);
    cudaGetSymbolAddress((void**)&x1, g_x1);
    cudaGetSymbolAddress((void**)&x2, g_x2);

    dim3 g3(HC / 64, (N_NODES + 127) / 128, 3);   // (4, 157, 3)
    dim3 gQT(HEADS, (N_NODES + 63) / 64);         // (4, 313)
    const int EB = N_EDGES / 8;                   // 40000 blocks, warp/edge

    // index dtype detection + int32 conversion
    detect_idx_kernel<<<1, 32>>>((const unsigned int*)ei);
    convert_idx_kernel<<<(2 * N_EDGES + 255) / 256, 256>>>((const int*)ei);

    // time encoding (shared by both layers)
    time_encode_kernel<<<EB, 256>>>(raw_time, noise);

    // ---- layer 1 ----
    sgemm3_kernel<<<g3, 256>>>(node_emb, wq1, wk1, wv1, bq1, bk1, bv1, q, k, v, N_NODES, 128, 0);
    qt_kernel<<<gQT, 256>>>(q, wt1, bt1, qt, qb);
    init_kernel<<<(N_NODES * HC + 255) / 256, 256>>>(x1);
    edge_alpha_kernel<<<EB, 256>>>(q, k, qt, qb);
    edge_exp_kernel<<<(N_EDGES * HEADS + 255) / 256, 256>>>();
    edge_agg_kernel<<<EB, 256>>>(v, x1);

    // ---- layer 2 (relu of x1 folded into GEMM A-loads) ----
    sgemm3_kernel<<<g3, 256>>>(x1, wq2, wk2, wv2, bq2, bk2, bv2, q, k, v, N_NODES, 256, 1);
    qt_kernel<<<gQT, 256>>>(q, wt2, bt2, qt, qb);
    init_kernel<<<(N_NODES * HC + 255) / 256, 256>>>(x2);
    edge_alpha_kernel<<<EB, 256>>>(q, k, qt, qb);
    edge_exp_kernel<<<(N_EDGES * HEADS + 255) / 256, 256>>>();
    edge_agg_kernel<<<EB, 256>>>(v, x2);

    // ---- edge readout: per-node GEMV + trivial edge pass ----
    node_y_kernel<<<(N_NODES + 7) / 8, 256>>>(x2, wc);
    edge_final_kernel<<<(N_EDGES + 255) / 256, 256>>>(bc, out);
}

// round 11
// speedup vs baseline: 3.0439x; 1.2184x over previous
#include <cuda_runtime.h>
#include <math.h>
#include <float.h>
#include <stdint.h>

#define N_NODES 20000
#define N_EDGES 320000
#define HC      256     // HEADS*HIDDEN
#define HEADS   4
#define HIDDEN  64
#define TD      64

// ---------------- scratch (device globals; no runtime allocation) ----------------
__device__ float g_te [(size_t)N_EDGES * TD];       //  82 MB
__device__ float g_q  [(size_t)N_NODES * HC];
__device__ float g_k  [(size_t)N_NODES * HC];
__device__ float g_v  [(size_t)N_NODES * HC];
__device__ float g_qt [(size_t)N_NODES * HC];       // per-node time-proj of q
__device__ float g_qb [(size_t)N_NODES * HEADS];    // q · bt per head
__device__ float g_x1 [(size_t)N_NODES * HC];
__device__ float g_y  [N_NODES];                    // per-node readout dot
__device__ float g_alpha[(size_t)N_EDGES * HEADS];  // CSR-position order
__device__ int   g_src[N_EDGES];
__device__ int   g_dst[N_EDGES];
__device__ int   g_off[N_NODES + 1];                // CSR offsets (by dst)
__device__ int   g_cur[N_NODES];                    // scatter cursors
__device__ int   g_eid[N_EDGES];                    // edge ids grouped by dst
__device__ int   g_is64;

// ---------------- edge_index dtype detection + conversion ----------------
__global__ void detect_idx_kernel(const unsigned int* __restrict__ w) {
    if (threadIdx.x == 0 && blockIdx.x == 0) {
        int ok = 1;
        for (int i = 0; i < 256; i++) {
            unsigned lo = w[2 * i], hi = w[2 * i + 1];
            if (hi != 0u || lo >= (unsigned)N_NODES) { ok = 0; break; }
        }
        g_is64 = ok;
    }
}

__global__ void convert_idx_kernel(const int* __restrict__ w) {
    int i = blockIdx.x * blockDim.x + threadIdx.x;
    if (i >= 2 * N_EDGES) return;
    int v = g_is64 ? w[2 * i] : w[i];    // little-endian low word
    if (i < N_EDGES) g_src[i] = v;
    else             g_dst[i - N_EDGES] = v;
}

// ---------------- CSR build: histogram -> scan -> scatter ----------------
__global__ void hist_zero_kernel() {
    int i = blockIdx.x * blockDim.x + threadIdx.x;
    if (i < N_NODES) g_cur[i] = 0;
}

__global__ void hist_kernel() {
    int e = blockIdx.x * blockDim.x + threadIdx.x;
    if (e < N_EDGES) atomicAdd(&g_cur[g_dst[e]], 1);
}

// single block, 1024 threads; each thread scans a 20-element chunk
__global__ void scan_kernel() {
    __shared__ int part[1024];
    const int CH = (N_NODES + 1023) / 1024;   // 20
    int t = threadIdx.x;
    int b0 = t * CH;
    int b1 = min(b0 + CH, N_NODES);
    int s = 0;
    for (int i = b0; i < b1; i++) s += g_cur[i];
    part[t] = s;
    __syncthreads();
    // Hillis-Steele inclusive scan over 1024 partials
    for (int off = 1; off < 1024; off <<= 1) {
        int vv = (t >= off) ? part[t - off] : 0;
        __syncthreads();
        part[t] += vv;
        __syncthreads();
    }
    int run = part[t] - s;   // exclusive base of this chunk
    for (int i = b0; i < b1; i++) {
        int d = g_cur[i];
        g_off[i] = run;
        run += d;
    }
    if (t == 1023) g_off[N_NODES] = run;
    __syncthreads();
    // reset cursors to offsets for the scatter pass
    for (int i = b0; i < b1; i++) g_cur[i] = g_off[i];
}

__global__ void scatter_kernel() {
    int e = blockIdx.x * blockDim.x + threadIdx.x;
    if (e >= N_EDGES) return;
    int pos = atomicAdd(&g_cur[g_dst[e]], 1);
    g_eid[pos] = e;
}

// ---------------- time encoding (fp32 Cody-Waite range reduction) ----------------
__global__ void time_encode_kernel(const float* __restrict__ raw, const float* __restrict__ noise) {
    int e = blockIdx.x * 8 + (threadIdx.x >> 5);
    int lane = threadIdx.x & 31;
    if (e >= N_EDGES) return;
    float t = raw[e] + noise[e];
    const float cst = -0.14391156831212787f;        // -ln(10000)/64
    float div = expf((float)(2 * lane) * cst);
    float arg = t * div;
    float kf = rintf(arg * 0.15915494309189535f);
    float r  = fmaf(-kf, 6.28125f, arg);
    r = fmaf(-kf, 1.9353071795864792e-3f, r);
    float s = __sinf(r);
    float c = __cosf(r);
    g_te[(size_t)e * TD + 2 * lane]     = s;
    g_te[(size_t)e * TD + 2 * lane + 1] = c;
}

// ---------------- fused QKV GEMM: C{q,k,v}[M,256] = A[M,K] @ W{q,k,v} + b ----------------
__global__ void sgemm3_kernel(const float* __restrict__ A,
                              const float* __restrict__ W0, const float* __restrict__ W1,
                              const float* __restrict__ W2,
                              const float* __restrict__ b0, const float* __restrict__ b1,
                              const float* __restrict__ b2,
                              float* __restrict__ C0, float* __restrict__ C1,
                              float* __restrict__ C2,
                              int M, int K) {
    const int N = HC;
    const float* W    = blockIdx.z == 0 ? W0 : (blockIdx.z == 1 ? W1 : W2);
    const float* bias = blockIdx.z == 0 ? b0 : (blockIdx.z == 1 ? b1 : b2);
    float*       C    = blockIdx.z == 0 ? C0 : (blockIdx.z == 1 ? C1 : C2);

    __shared__ float sA[16][128];
    __shared__ float sW[16][64];

    int tid = threadIdx.x;              // 256
    int tx = tid & 15, ty = tid >> 4;
    int bm = blockIdx.y * 128, bn = blockIdx.x * 64;

    int ar = tid >> 1;                  // 0..127
    int ac = (tid & 1) * 8;             // 0 or 8
    int wr = tid >> 4;                  // 0..15
    int wcol = (tid & 15) * 4;          // 0..60

    float acc[8][4];
#pragma unroll
    for (int i = 0; i < 8; i++)
#pragma unroll
        for (int j = 0; j < 4; j++) acc[i][j] = 0.f;

    for (int k0 = 0; k0 < K; k0 += 16) {
        float4 a0 = make_float4(0.f, 0.f, 0.f, 0.f);
        float4 a1 = make_float4(0.f, 0.f, 0.f, 0.f);
        if (bm + ar < M) {
            a0 = *(const float4*)(A + (size_t)(bm + ar) * K + k0 + ac);
            a1 = *(const float4*)(A + (size_t)(bm + ar) * K + k0 + ac + 4);
        }
        sA[ac + 0][ar] = a0.x; sA[ac + 1][ar] = a0.y;
        sA[ac + 2][ar] = a0.z; sA[ac + 3][ar] = a0.w;
        sA[ac + 4][ar] = a1.x; sA[ac + 5][ar] = a1.y;
        sA[ac + 6][ar] = a1.z; sA[ac + 7][ar] = a1.w;
        *(float4*)&sW[wr][wcol] = *(const float4*)(W + (size_t)(k0 + wr) * N + bn + wcol);
        __syncthreads();
#pragma unroll
        for (int kk = 0; kk < 16; kk++) {
            float4 w = *(const float4*)&sW[kk][tx * 4];
            float a[8];
#pragma unroll
            for (int i = 0; i < 8; i++) a[i] = sA[kk][ty * 8 + i];
#pragma unroll
            for (int i = 0; i < 8; i++) {
                acc[i][0] = fmaf(a[i], w.x, acc[i][0]);
                acc[i][1] = fmaf(a[i], w.y, acc[i][1]);
                acc[i][2] = fmaf(a[i], w.z, acc[i][2]);
                acc[i][3] = fmaf(a[i], w.w, acc[i][3]);
            }
        }
        __syncthreads();
    }

    float4 bv = *(const float4*)(bias + bn + tx * 4);
#pragma unroll
    for (int i = 0; i < 8; i++) {
        int m = bm + ty * 8 + i;
        if (m < M) {
            float4 o;
            o.x = acc[i][0] + bv.x;
            o.y = acc[i][1] + bv.y;
            o.z = acc[i][2] + bv.z;
            o.w = acc[i][3] + bv.w;
            *(float4*)(C + (size_t)m * N + bn + tx * 4) = o;
        }
    }
}

// ---------------- per-node time transform of q ----------------
__global__ void qt_kernel(const float* __restrict__ q, const float* __restrict__ wt,
                          const float* __restrict__ bt,
                          float* __restrict__ qt, float* __restrict__ qb) {
    __shared__ float sQ[64][68];
    __shared__ float sW[64][68];
    __shared__ float sB[64];
    int h = blockIdx.x;
    int bm = blockIdx.y * 64;
    int tid = threadIdx.x;         // 256

    int lr = tid >> 2;
    int lc = (tid & 3) * 16;
#pragma unroll
    for (int i = 0; i < 16; i += 4) {
        float4 v = make_float4(0.f, 0.f, 0.f, 0.f);
        if (bm + lr < N_NODES)
            v = *(const float4*)(q + (size_t)(bm + lr) * HC + h * 64 + lc + i);
        *(float4*)&sQ[lr][lc + i] = v;
        *(float4*)&sW[lr][lc + i] = *(const float4*)(wt + (size_t)lr * HC + h * 64 + lc + i);
    }
    if (tid < 64) sB[tid] = bt[h * 64 + tid];
    __syncthreads();

    int tx = tid & 15, ty = tid >> 4;
    float acc[4][4];
#pragma unroll
    for (int i = 0; i < 4; i++)
#pragma unroll
        for (int j = 0; j < 4; j++) acc[i][j] = 0.f;
#pragma unroll 8
    for (int c = 0; c < 64; c++) {
        float a0 = sQ[ty * 4 + 0][c], a1 = sQ[ty * 4 + 1][c];
        float a2 = sQ[ty * 4 + 2][c], a3 = sQ[ty * 4 + 3][c];
        float w0 = sW[tx * 4 + 0][c], w1 = sW[tx * 4 + 1][c];
        float w2 = sW[tx * 4 + 2][c], w3 = sW[tx * 4 + 3][c];
        acc[0][0] = fmaf(a0, w0, acc[0][0]); acc[0][1] = fmaf(a0, w1, acc[0][1]);
        acc[0][2] = fmaf(a0, w2, acc[0][2]); acc[0][3] = fmaf(a0, w3, acc[0][3]);
        acc[1][0] = fmaf(a1, w0, acc[1][0]); acc[1][1] = fmaf(a1, w1, acc[1][1]);
        acc[1][2] = fmaf(a1, w2, acc[1][2]); acc[1][3] = fmaf(a1, w3, acc[1][3]);
        acc[2][0] = fmaf(a2, w0, acc[2][0]); acc[2][1] = fmaf(a2, w1, acc[2][1]);
        acc[2][2] = fmaf(a2, w2, acc[2][2]); acc[2][3] = fmaf(a2, w3, acc[2][3]);
        acc[3][0] = fmaf(a3, w0, acc[3][0]); acc[3][1] = fmaf(a3, w1, acc[3][1]);
        acc[3][2] = fmaf(a3, w2, acc[3][2]); acc[3][3] = fmaf(a3, w3, acc[3][3]);
    }
#pragma unroll
    for (int i = 0; i < 4; i++) {
        int m = bm + ty * 4 + i;
        if (m < N_NODES) {
            float4 o = make_float4(acc[i][0], acc[i][1], acc[i][2], acc[i][3]);
            *(float4*)(qt + (size_t)m * HC + h * 64 + tx * 4) = o;
        }
    }

    {
        int row = tid >> 2, part = tid & 3;
        float ssum = 0.f;
#pragma unroll
        for (int c = part * 16; c < part * 16 + 16; c++)
            ssum += sQ[row][c] * sB[c];
        ssum += __shfl_down_sync(0xffffffffu, ssum, 2, 4);
        ssum += __shfl_down_sync(0xffffffffu, ssum, 1, 4);
        if (part == 0 && bm + row < N_NODES)
            qb[(size_t)(bm + row) * HEADS + h] = ssum;
    }
}

// ---------------- fused per-node attention (warp per dst node) ----------------
// pass1: alpha_raw per in-edge (store), per-head max in regs
// pass2: denom = sum exp(alpha - amax)            (warp reduction)
// pass3: acc += v[src] * exp(alpha-amax)/denom    (register accumulator)
// epilogue: mode 0 -> xout[n] = relu(acc);  mode 1 -> y[n] = <relu(acc), wc>
__global__ void node_attn_kernel(const float* __restrict__ q, const float* __restrict__ k,
                                 const float* __restrict__ qt, const float* __restrict__ qb,
                                 const float* __restrict__ v,
                                 float* __restrict__ xout, const float* __restrict__ wc,
                                 float* __restrict__ y, int mode) {
    int n = blockIdx.x * 8 + (threadIdx.x >> 5);
    int lane = threadIdx.x & 31;
    if (n >= N_NODES) return;
    int off0 = g_off[n], off1 = g_off[n + 1];

    int c0 = lane * 8;              // channel block (h = lane>>3)
    int j0 = (lane & 7) * 8;        // te block
    int h8 = lane >> 3;

    float4 q0, q1, w0, w1;
    {
        const float4* qp = (const float4*)(q  + (size_t)n * HC + c0);
        const float4* wp = (const float4*)(qt + (size_t)n * HC + c0);
        q0 = qp[0]; q1 = qp[1];
        w0 = wp[0]; w1 = wp[1];
    }
    float qbh = 0.f;
    if ((lane & 7) == 0) qbh = qb[(size_t)n * HEADS + h8];

    // ---- pass 1: raw alphas + per-head max ----
    float maxv = -FLT_MAX;          // valid on lanes 0,8,16,24
    for (int i = off0; i < off1; i++) {
        int e = g_eid[i];
        int s = g_src[e];
        const float4* kp = (const float4*)(k + (size_t)s * HC + c0);
        const float4* tp = (const float4*)(g_te + (size_t)e * TD + j0);
        float4 k0 = kp[0], k1 = kp[1];
        float4 t0 = tp[0], t1 = tp[1];
        float p = q0.x * k0.x + q0.y * k0.y + q0.z * k0.z + q0.w * k0.w
                + q1.x * k1.x + q1.y * k1.y + q1.z * k1.z + q1.w * k1.w
                + w0.x * t0.x + w0.y * t0.y + w0.z * t0.z + w0.w * t0.w
                + w1.x * t1.x + w1.y * t1.y + w1.z * t1.z + w1.w * t1.w;
        p += __shfl_down_sync(0xffffffffu, p, 4, 8);
        p += __shfl_down_sync(0xffffffffu, p, 2, 8);
        p += __shfl_down_sync(0xffffffffu, p, 1, 8);
        if ((lane & 7) == 0) {
            float alpha = (p + qbh) * 0.125f;
            g_alpha[(size_t)i * HEADS + h8] = alpha;
            maxv = fmaxf(maxv, alpha);
        }
    }
    __threadfence_block();
    __syncwarp();

    // per-head max, broadcast: lane (lane&3)*8 holds max of head (lane&3)
    float amax_mod = __shfl_sync(0xffffffffu, maxv, (lane & 3) * 8);   // head = lane&3
    float amax_h8  = __shfl_sync(0xffffffffu, maxv, h8 * 8);           // head = lane>>3

    // ---- pass 2: denominators (8 edges x 4 heads per iteration) ----
    float dsum = 0.f;
    for (int i = off0 + (lane >> 2); i < off1; i += 8) {
        float a = g_alpha[(size_t)i * HEADS + (lane & 3)];
        dsum += __expf(a - amax_mod);
    }
    dsum += __shfl_xor_sync(0xffffffffu, dsum, 4);
    dsum += __shfl_xor_sync(0xffffffffu, dsum, 8);
    dsum += __shfl_xor_sync(0xffffffffu, dsum, 16);
    // lane now holds denom for head (lane&3)
    float inv = 1.f / (dsum + 1e-16f);
    float inv_h8 = __shfl_sync(0xffffffffu, inv, h8);   // lane h8 has head h8

    // ---- pass 3: weighted aggregation ----
    float4 acc0 = make_float4(0.f, 0.f, 0.f, 0.f);
    float4 acc1 = make_float4(0.f, 0.f, 0.f, 0.f);
    for (int i = off0; i < off1; i++) {
        int e = g_eid[i];
        int s = g_src[e];
        float a = g_alpha[(size_t)i * HEADS + h8];
        float wgt = __expf(a - amax_h8) * inv_h8;
        const float4* vp = (const float4*)(v + (size_t)s * HC + c0);
        float4 v0 = vp[0], v1 = vp[1];
        acc0.x = fmaf(v0.x, wgt, acc0.x); acc0.y = fmaf(v0.y, wgt, acc0.y);
        acc0.z = fmaf(v0.z, wgt, acc0.z); acc0.w = fmaf(v0.w, wgt, acc0.w);
        acc1.x = fmaf(v1.x, wgt, acc1.x); acc1.y = fmaf(v1.y, wgt, acc1.y);
        acc1.z = fmaf(v1.z, wgt, acc1.z); acc1.w = fmaf(v1.w, wgt, acc1.w);
    }

    // relu
    acc0.x = fmaxf(acc0.x, 0.f); acc0.y = fmaxf(acc0.y, 0.f);
    acc0.z = fmaxf(acc0.z, 0.f); acc0.w = fmaxf(acc0.w, 0.f);
    acc1.x = fmaxf(acc1.x, 0.f); acc1.y = fmaxf(acc1.y, 0.f);
    acc1.z = fmaxf(acc1.z, 0.f); acc1.w = fmaxf(acc1.w, 0.f);

    if (mode == 0) {
        float4* op = (float4*)(xout + (size_t)n * HC + c0);
        op[0] = acc0;
        op[1] = acc1;
    } else {
        const float4* wp = (const float4*)(wc + c0);
        float4 wc0 = wp[0], wc1 = wp[1];
        float p = acc0.x * wc0.x + acc0.y * wc0.y + acc0.z * wc0.z + acc0.w * wc0.w
                + acc1.x * wc1.x + acc1.y * wc1.y + acc1.z * wc1.z + acc1.w * wc1.w;
#pragma unroll
        for (int off = 16; off >= 1; off >>= 1)
            p += __shfl_down_sync(0xffffffffu, p, off);
        if (lane == 0) y[n] = p;
    }
}

// ---------------- final: out[e] = y[src] + y[dst] + bc ----------------
__global__ void edge_final_kernel(const float* __restrict__ bc, float* __restrict__ out) {
    int e = blockIdx.x * blockDim.x + threadIdx.x;
    if (e >= N_EDGES) return;
    out[e] = g_y[g_src[e]] + g_y[g_dst[e]] + bc[0];
}

// ---------------- launch ----------------
extern "C" void kernel_launch(void* const* d_in, const int* in_sizes, int n_in,
                              void* d_out, int out_size) {
    const void* ei        = d_in[0];
    const float* raw_time = (const float*)d_in[1];
    const float* noise    = (const float*)d_in[2];
    const float* node_emb = (const float*)d_in[3];
    const float* wq1 = (const float*)d_in[4],  *bq1 = (const float*)d_in[5];
    const float* wk1 = (const float*)d_in[6],  *bk1 = (const float*)d_in[7];
    const float* wv1 = (const float*)d_in[8],  *bv1 = (const float*)d_in[9];
    const float* wt1 = (const float*)d_in[10], *bt1 = (const float*)d_in[11];
    const float* wq2 = (const float*)d_in[12], *bq2 = (const float*)d_in[13];
    const float* wk2 = (const float*)d_in[14], *bk2 = (const float*)d_in[15];
    const float* wv2 = (const float*)d_in[16], *bv2 = (const float*)d_in[17];
    const float* wt2 = (const float*)d_in[18], *bt2 = (const float*)d_in[19];
    const float* wc  = (const float*)d_in[20], *bc  = (const float*)d_in[21];
    float* out = (float*)d_out;

    float *q, *k, *v, *qt, *qb, *x1, *y;
    cudaGetSymbolAddress((void**)&q,  g_q);
    cudaGetSymbolAddress((void**)&k,  g_k);
    cudaGetSymbolAddress((void**)&v,  g_v);
    cudaGetSymbolAddress((void**)&qt, g_qt);
    cudaGetSymbolAddress((void**)&qb, g_qb);
    cudaGetSymbolAddress((void**)&x1, g_x1);
    cudaGetSymbolAddress((void**)&y,  g_y);

    dim3 g3(HC / 64, (N_NODES + 127) / 128, 3);   // (4, 157, 3)
    dim3 gQT(HEADS, (N_NODES + 63) / 64);         // (4, 313)
    const int EB = N_EDGES / 8;                   // 40000 blocks, warp/edge
    const int NB = (N_NODES + 7) / 8;             // warp/node

    // index dtype detection + int32 conversion
    detect_idx_kernel<<<1, 32>>>((const unsigned int*)ei);
    convert_idx_kernel<<<(2 * N_EDGES + 255) / 256, 256>>>((const int*)ei);

    // CSR build (by dst)
    hist_zero_kernel<<<(N_NODES + 255) / 256, 256>>>();
    hist_kernel<<<(N_EDGES + 255) / 256, 256>>>();
    scan_kernel<<<1, 1024>>>();
    scatter_kernel<<<(N_EDGES + 255) / 256, 256>>>();

    // time encoding (shared by both layers)
    time_encode_kernel<<<EB, 256>>>(raw_time, noise);

    // ---- layer 1 ----
    sgemm3_kernel<<<g3, 256>>>(node_emb, wq1, wk1, wv1, bq1, bk1, bv1, q, k, v, N_NODES, 128);
    qt_kernel<<<gQT, 256>>>(q, wt1, bt1, qt, qb);
    node_attn_kernel<<<NB, 256>>>(q, k, qt, qb, v, x1, wc, y, 0);

    // ---- layer 2 (x1 already relu'd; epilogue emits y directly) ----
    sgemm3_kernel<<<g3, 256>>>(x1, wq2, wk2, wv2, bq2, bk2, bv2, q, k, v, N_NODES, 256);
    qt_kernel<<<gQT, 256>>>(q, wt2, bt2, qt, qb);
    node_attn_kernel<<<NB, 256>>>(q, k, qt, qb, v, nullptr, wc, y, 1);

    // ---- edge readout ----
    edge_final_kernel<<<(N_EDGES + 255) / 256, 256>>>(bc, out);
}

// round 12
// speedup vs baseline: 3.2291x; 1.0608x over previous
#include <cuda_runtime.h>
#include <math.h>
#include <float.h>
#include <stdint.h>

#define N_NODES 20000
#define N_EDGES 320000
#define HC      256     // HEADS*HIDDEN
#define HEADS   4
#define HIDDEN  64
#define TD      64

// ---------------- scratch (device globals; no runtime allocation) ----------------
__device__ float g_te [(size_t)N_EDGES * TD];       //  82 MB, CSR-position order
__device__ float g_q  [(size_t)N_NODES * HC];
__device__ float g_k  [(size_t)N_NODES * HC];
__device__ float g_v  [(size_t)N_NODES * HC];
__device__ float g_qt [(size_t)N_NODES * HC];       // per-node time-proj of q
__device__ float g_qb [(size_t)N_NODES * HEADS];    // q · bt per head
__device__ float g_x1 [(size_t)N_NODES * HC];
__device__ float g_y  [N_NODES];                    // per-node readout dot
__device__ int   g_src[N_EDGES];
__device__ int   g_dst[N_EDGES];
__device__ int   g_off[N_NODES + 1];                // CSR offsets (by dst)
__device__ int   g_cur[N_NODES];                    // scatter cursors
__device__ int   g_eid[N_EDGES];                    // edge id at CSR position
__device__ int   g_csr_src[N_EDGES];                // src node at CSR position
__device__ int   g_is64;

// ---------------- edge_index dtype detection + conversion ----------------
__global__ void detect_idx_kernel(const unsigned int* __restrict__ w) {
    if (threadIdx.x == 0 && blockIdx.x == 0) {
        int ok = 1;
        for (int i = 0; i < 256; i++) {
            unsigned lo = w[2 * i], hi = w[2 * i + 1];
            if (hi != 0u || lo >= (unsigned)N_NODES) { ok = 0; break; }
        }
        g_is64 = ok;
    }
}

__global__ void convert_idx_kernel(const int* __restrict__ w) {
    int i = blockIdx.x * blockDim.x + threadIdx.x;
    if (i >= 2 * N_EDGES) return;
    int v = g_is64 ? w[2 * i] : w[i];    // little-endian low word
    if (i < N_EDGES) g_src[i] = v;
    else             g_dst[i - N_EDGES] = v;
}

// ---------------- CSR build: histogram -> scan -> scatter ----------------
__global__ void hist_zero_kernel() {
    int i = blockIdx.x * blockDim.x + threadIdx.x;
    if (i < N_NODES) g_cur[i] = 0;
}

__global__ void hist_kernel() {
    int e = blockIdx.x * blockDim.x + threadIdx.x;
    if (e < N_EDGES) atomicAdd(&g_cur[g_dst[e]], 1);
}

// single block, 1024 threads; each thread scans a 20-element chunk
__global__ void scan_kernel() {
    __shared__ int part[1024];
    const int CH = (N_NODES + 1023) / 1024;   // 20
    int t = threadIdx.x;
    int b0 = t * CH;
    int b1 = min(b0 + CH, N_NODES);
    int s = 0;
    for (int i = b0; i < b1; i++) s += g_cur[i];
    part[t] = s;
    __syncthreads();
    for (int off = 1; off < 1024; off <<= 1) {
        int vv = (t >= off) ? part[t - off] : 0;
        __syncthreads();
        part[t] += vv;
        __syncthreads();
    }
    int run = part[t] - s;   // exclusive base of this chunk
    for (int i = b0; i < b1; i++) {
        int d = g_cur[i];
        g_off[i] = run;
        run += d;
    }
    if (t == 1023) g_off[N_NODES] = run;
    __syncthreads();
    for (int i = b0; i < b1; i++) g_cur[i] = g_off[i];
}

__global__ void scatter_kernel() {
    int e = blockIdx.x * blockDim.x + threadIdx.x;
    if (e >= N_EDGES) return;
    int s = g_src[e];
    int pos = atomicAdd(&g_cur[g_dst[e]], 1);
    g_eid[pos] = e;
    g_csr_src[pos] = s;
}

// ---------------- time encoding into CSR order ----------------
// te[pos] corresponds to edge g_eid[pos]; attention reads it sequentially.
__global__ void time_encode_kernel(const float* __restrict__ raw, const float* __restrict__ noise) {
    int pos = blockIdx.x * 8 + (threadIdx.x >> 5);
    int lane = threadIdx.x & 31;
    if (pos >= N_EDGES) return;
    int e = g_eid[pos];
    float t = raw[e] + noise[e];
    const float cst = -0.14391156831212787f;        // -ln(10000)/64
    float div = expf((float)(2 * lane) * cst);
    float arg = t * div;
    float kf = rintf(arg * 0.15915494309189535f);
    float r  = fmaf(-kf, 6.28125f, arg);
    r = fmaf(-kf, 1.9353071795864792e-3f, r);
    float s = __sinf(r);
    float c = __cosf(r);
    g_te[(size_t)pos * TD + 2 * lane]     = s;
    g_te[(size_t)pos * TD + 2 * lane + 1] = c;
}

// ---------------- fused QKV GEMM: C{q,k,v}[M,256] = A[M,K] @ W{q,k,v} + b ----------------
__global__ void sgemm3_kernel(const float* __restrict__ A,
                              const float* __restrict__ W0, const float* __restrict__ W1,
                              const float* __restrict__ W2,
                              const float* __restrict__ b0, const float* __restrict__ b1,
                              const float* __restrict__ b2,
                              float* __restrict__ C0, float* __restrict__ C1,
                              float* __restrict__ C2,
                              int M, int K) {
    const int N = HC;
    const float* W    = blockIdx.z == 0 ? W0 : (blockIdx.z == 1 ? W1 : W2);
    const float* bias = blockIdx.z == 0 ? b0 : (blockIdx.z == 1 ? b1 : b2);
    float*       C    = blockIdx.z == 0 ? C0 : (blockIdx.z == 1 ? C1 : C2);

    __shared__ float sA[16][128];
    __shared__ float sW[16][64];

    int tid = threadIdx.x;              // 256
    int tx = tid & 15, ty = tid >> 4;
    int bm = blockIdx.y * 128, bn = blockIdx.x * 64;

    int ar = tid >> 1;                  // 0..127
    int ac = (tid & 1) * 8;             // 0 or 8
    int wr = tid >> 4;                  // 0..15
    int wcol = (tid & 15) * 4;          // 0..60

    float acc[8][4];
#pragma unroll
    for (int i = 0; i < 8; i++)
#pragma unroll
        for (int j = 0; j < 4; j++) acc[i][j] = 0.f;

    for (int k0 = 0; k0 < K; k0 += 16) {
        float4 a0 = make_float4(0.f, 0.f, 0.f, 0.f);
        float4 a1 = make_float4(0.f, 0.f, 0.f, 0.f);
        if (bm + ar < M) {
            a0 = *(const float4*)(A + (size_t)(bm + ar) * K + k0 + ac);
            a1 = *(const float4*)(A + (size_t)(bm + ar) * K + k0 + ac + 4);
        }
        sA[ac + 0][ar] = a0.x; sA[ac + 1][ar] = a0.y;
        sA[ac + 2][ar] = a0.z; sA[ac + 3][ar] = a0.w;
        sA[ac + 4][ar] = a1.x; sA[ac + 5][ar] = a1.y;
        sA[ac + 6][ar] = a1.z; sA[ac + 7][ar] = a1.w;
        *(float4*)&sW[wr][wcol] = *(const float4*)(W + (size_t)(k0 + wr) * N + bn + wcol);
        __syncthreads();
#pragma unroll
        for (int kk = 0; kk < 16; kk++) {
            float4 w = *(const float4*)&sW[kk][tx * 4];
            float a[8];
#pragma unroll
            for (int i = 0; i < 8; i++) a[i] = sA[kk][ty * 8 + i];
#pragma unroll
            for (int i = 0; i < 8; i++) {
                acc[i][0] = fmaf(a[i], w.x, acc[i][0]);
                acc[i][1] = fmaf(a[i], w.y, acc[i][1]);
                acc[i][2] = fmaf(a[i], w.z, acc[i][2]);
                acc[i][3] = fmaf(a[i], w.w, acc[i][3]);
            }
        }
        __syncthreads();
    }

    float4 bv = *(const float4*)(bias + bn + tx * 4);
#pragma unroll
    for (int i = 0; i < 8; i++) {
        int m = bm + ty * 8 + i;
        if (m < M) {
            float4 o;
            o.x = acc[i][0] + bv.x;
            o.y = acc[i][1] + bv.y;
            o.z = acc[i][2] + bv.z;
            o.w = acc[i][3] + bv.w;
            *(float4*)(C + (size_t)m * N + bn + tx * 4) = o;
        }
    }
}

// ---------------- per-node time transform of q ----------------
__global__ void qt_kernel(const float* __restrict__ q, const float* __restrict__ wt,
                          const float* __restrict__ bt,
                          float* __restrict__ qt, float* __restrict__ qb) {
    __shared__ float sQ[64][68];
    __shared__ float sW[64][68];
    __shared__ float sB[64];
    int h = blockIdx.x;
    int bm = blockIdx.y * 64;
    int tid = threadIdx.x;         // 256

    int lr = tid >> 2;
    int lc = (tid & 3) * 16;
#pragma unroll
    for (int i = 0; i < 16; i += 4) {
        float4 v = make_float4(0.f, 0.f, 0.f, 0.f);
        if (bm + lr < N_NODES)
            v = *(const float4*)(q + (size_t)(bm + lr) * HC + h * 64 + lc + i);
        *(float4*)&sQ[lr][lc + i] = v;
        *(float4*)&sW[lr][lc + i] = *(const float4*)(wt + (size_t)lr * HC + h * 64 + lc + i);
    }
    if (tid < 64) sB[tid] = bt[h * 64 + tid];
    __syncthreads();

    int tx = tid & 15, ty = tid >> 4;
    float acc[4][4];
#pragma unroll
    for (int i = 0; i < 4; i++)
#pragma unroll
        for (int j = 0; j < 4; j++) acc[i][j] = 0.f;
#pragma unroll 8
    for (int c = 0; c < 64; c++) {
        float a0 = sQ[ty * 4 + 0][c], a1 = sQ[ty * 4 + 1][c];
        float a2 = sQ[ty * 4 + 2][c], a3 = sQ[ty * 4 + 3][c];
        float w0 = sW[tx * 4 + 0][c], w1 = sW[tx * 4 + 1][c];
        float w2 = sW[tx * 4 + 2][c], w3 = sW[tx * 4 + 3][c];
        acc[0][0] = fmaf(a0, w0, acc[0][0]); acc[0][1] = fmaf(a0, w1, acc[0][1]);
        acc[0][2] = fmaf(a0, w2, acc[0][2]); acc[0][3] = fmaf(a0, w3, acc[0][3]);
        acc[1][0] = fmaf(a1, w0, acc[1][0]); acc[1][1] = fmaf(a1, w1, acc[1][1]);
        acc[1][2] = fmaf(a1, w2, acc[1][2]); acc[1][3] = fmaf(a1, w3, acc[1][3]);
        acc[2][0] = fmaf(a2, w0, acc[2][0]); acc[2][1] = fmaf(a2, w1, acc[2][1]);
        acc[2][2] = fmaf(a2, w2, acc[2][2]); acc[2][3] = fmaf(a2, w3, acc[2][3]);
        acc[3][0] = fmaf(a3, w0, acc[3][0]); acc[3][1] = fmaf(a3, w1, acc[3][1]);
        acc[3][2] = fmaf(a3, w2, acc[3][2]); acc[3][3] = fmaf(a3, w3, acc[3][3]);
    }
#pragma unroll
    for (int i = 0; i < 4; i++) {
        int m = bm + ty * 4 + i;
        if (m < N_NODES) {
            float4 o = make_float4(acc[i][0], acc[i][1], acc[i][2], acc[i][3]);
            *(float4*)(qt + (size_t)m * HC + h * 64 + tx * 4) = o;
        }
    }

    {
        int row = tid >> 2, part = tid & 3;
        float ssum = 0.f;
#pragma unroll
        for (int c = part * 16; c < part * 16 + 16; c++)
            ssum += sQ[row][c] * sB[c];
        ssum += __shfl_down_sync(0xffffffffu, ssum, 2, 4);
        ssum += __shfl_down_sync(0xffffffffu, ssum, 1, 4);
        if (part == 0 && bm + row < N_NODES)
            qb[(size_t)(bm + row) * HEADS + h] = ssum;
    }
}

// ---------------- fused single-pass attention (warp per dst node, online softmax) ----------------
// For each in-edge: alpha = (q·k + te·qt + qb)/8 (8-lane xor-reduce, all lanes hold it),
// then online-softmax update of (m, denom, acc). One gather pass total.
// epilogue: mode 0 -> xout[n] = relu(acc/denom);  mode 1 -> y[n] = <relu(acc/denom), wc>
__global__ void node_attn_kernel(const float* __restrict__ q, const float* __restrict__ k,
                                 const float* __restrict__ qt, const float* __restrict__ qb,
                                 const float* __restrict__ v,
                                 float* __restrict__ xout, const float* __restrict__ wc,
                                 float* __restrict__ y, int mode) {
    int n = blockIdx.x * 8 + (threadIdx.x >> 5);
    int lane = threadIdx.x & 31;
    if (n >= N_NODES) return;
    int off0 = g_off[n], off1 = g_off[n + 1];

    int c0 = lane * 8;              // channel block (h = lane>>3)
    int j0 = (lane & 7) * 8;        // te block within row
    int h8 = lane >> 3;

    float4 q0, q1, w0, w1;
    {
        const float4* qp = (const float4*)(q  + (size_t)n * HC + c0);
        const float4* wp = (const float4*)(qt + (size_t)n * HC + c0);
        q0 = qp[0]; q1 = qp[1];
        w0 = wp[0]; w1 = wp[1];
    }
    float qbh = qb[(size_t)n * HEADS + h8];   // all lanes (L1 hit)

    float m = -FLT_MAX;
    float denom = 0.f;
    float4 acc0 = make_float4(0.f, 0.f, 0.f, 0.f);
    float4 acc1 = make_float4(0.f, 0.f, 0.f, 0.f);

    for (int i = off0; i < off1; i++) {
        int s = g_csr_src[i];
        const float4* kp = (const float4*)(k + (size_t)s * HC + c0);
        const float4* vp = (const float4*)(v + (size_t)s * HC + c0);
        const float4* tp = (const float4*)(g_te + (size_t)i * TD + j0);
        float4 k0 = kp[0], k1 = kp[1];
        float4 t0 = tp[0], t1 = tp[1];
        float4 v0 = vp[0], v1 = vp[1];
        float p = q0.x * k0.x + q0.y * k0.y + q0.z * k0.z + q0.w * k0.w
                + q1.x * k1.x + q1.y * k1.y + q1.z * k1.z + q1.w * k1.w
                + w0.x * t0.x + w0.y * t0.y + w0.z * t0.z + w0.w * t0.w
                + w1.x * t1.x + w1.y * t1.y + w1.z * t1.z + w1.w * t1.w;
        // xor-reduce within 8-lane head group: all lanes get the head sum
        p += __shfl_xor_sync(0xffffffffu, p, 4, 8);
        p += __shfl_xor_sync(0xffffffffu, p, 2, 8);
        p += __shfl_xor_sync(0xffffffffu, p, 1, 8);
        float alpha = (p + qbh) * 0.125f;      // / sqrt(64)

        // online softmax update
        float m_new = fmaxf(m, alpha);
        float corr = __expf(m - m_new);        // exp(-inf)=0 on first edge
        float wgt  = __expf(alpha - m_new);
        denom = denom * corr + wgt;
        m = m_new;
        acc0.x = fmaf(acc0.x, corr, v0.x * wgt);
        acc0.y = fmaf(acc0.y, corr, v0.y * wgt);
        acc0.z = fmaf(acc0.z, corr, v0.z * wgt);
        acc0.w = fmaf(acc0.w, corr, v0.w * wgt);
        acc1.x = fmaf(acc1.x, corr, v1.x * wgt);
        acc1.y = fmaf(acc1.y, corr, v1.y * wgt);
        acc1.z = fmaf(acc1.z, corr, v1.z * wgt);
        acc1.w = fmaf(acc1.w, corr, v1.w * wgt);
    }

    float inv = 1.f / (denom + 1e-16f);
    acc0.x = fmaxf(acc0.x * inv, 0.f); acc0.y = fmaxf(acc0.y * inv, 0.f);
    acc0.z = fmaxf(acc0.z * inv, 0.f); acc0.w = fmaxf(acc0.w * inv, 0.f);
    acc1.x = fmaxf(acc1.x * inv, 0.f); acc1.y = fmaxf(acc1.y * inv, 0.f);
    acc1.z = fmaxf(acc1.z * inv, 0.f); acc1.w = fmaxf(acc1.w * inv, 0.f);

    if (mode == 0) {
        float4* op = (float4*)(xout + (size_t)n * HC + c0);
        op[0] = acc0;
        op[1] = acc1;
    } else {
        const float4* wp = (const float4*)(wc + c0);
        float4 wc0 = wp[0], wc1 = wp[1];
        float p = acc0.x * wc0.x + acc0.y * wc0.y + acc0.z * wc0.z + acc0.w * wc0.w
                + acc1.x * wc1.x + acc1.y * wc1.y + acc1.z * wc1.z + acc1.w * wc1.w;
#pragma unroll
        for (int off = 16; off >= 1; off >>= 1)
            p += __shfl_down_sync(0xffffffffu, p, off);
        if (lane == 0) y[n] = p;
    }
}

// ---------------- final: out[e] = y[src] + y[dst] + bc ----------------
__global__ void edge_final_kernel(const float* __restrict__ bc, float* __restrict__ out) {
    int e = blockIdx.x * blockDim.x + threadIdx.x;
    if (e >= N_EDGES) return;
    out[e] = g_y[g_src[e]] + g_y[g_dst[e]] + bc[0];
}

// ---------------- launch ----------------
extern "C" void kernel_launch(void* const* d_in, const int* in_sizes, int n_in,
                              void* d_out, int out_size) {
    const void* ei        = d_in[0];
    const float* raw_time = (const float*)d_in[1];
    const float* noise    = (const float*)d_in[2];
    const float* node_emb = (const float*)d_in[3];
    const float* wq1 = (const float*)d_in[4],  *bq1 = (const float*)d_in[5];
    const float* wk1 = (const float*)d_in[6],  *bk1 = (const float*)d_in[7];
    const float* wv1 = (const float*)d_in[8],  *bv1 = (const float*)d_in[9];
    const float* wt1 = (const float*)d_in[10], *bt1 = (const float*)d_in[11];
    const float* wq2 = (const float*)d_in[12], *bq2 = (const float*)d_in[13];
    const float* wk2 = (const float*)d_in[14], *bk2 = (const float*)d_in[15];
    const float* wv2 = (const float*)d_in[16], *bv2 = (const float*)d_in[17];
    const float* wt2 = (const float*)d_in[18], *bt2 = (const float*)d_in[19];
    const float* wc  = (const float*)d_in[20], *bc  = (const float*)d_in[21];
    float* out = (float*)d_out;

    float *q, *k, *v, *qt, *qb, *x1, *y;
    cudaGetSymbolAddress((void**)&q,  g_q);
    cudaGetSymbolAddress((void**)&k,  g_k);
    cudaGetSymbolAddress((void**)&v,  g_v);
    cudaGetSymbolAddress((void**)&qt, g_qt);
    cudaGetSymbolAddress((void**)&qb, g_qb);
    cudaGetSymbolAddress((void**)&x1, g_x1);
    cudaGetSymbolAddress((void**)&y,  g_y);

    dim3 g3(HC / 64, (N_NODES + 127) / 128, 3);   // (4, 157, 3)
    dim3 gQT(HEADS, (N_NODES + 63) / 64);         // (4, 313)
    const int EB = N_EDGES / 8;                   // 40000 blocks, warp/edge
    const int NB = (N_NODES + 7) / 8;             // warp/node

    // index dtype detection + int32 conversion
    detect_idx_kernel<<<1, 32>>>((const unsigned int*)ei);
    convert_idx_kernel<<<(2 * N_EDGES + 255) / 256, 256>>>((const int*)ei);

    // CSR build (by dst)
    hist_zero_kernel<<<(N_NODES + 255) / 256, 256>>>();
    hist_kernel<<<(N_EDGES + 255) / 256, 256>>>();
    scan_kernel<<<1, 1024>>>();
    scatter_kernel<<<(N_EDGES + 255) / 256, 256>>>();

    // time encoding in CSR order (needs g_eid; shared by both layers)
    time_encode_kernel<<<EB, 256>>>(raw_time, noise);

    // ---- layer 1 ----
    sgemm3_kernel<<<g3, 256>>>(node_emb, wq1, wk1, wv1, bq1, bk1, bv1, q, k, v, N_NODES, 128);
    qt_kernel<<<gQT, 256>>>(q, wt1, bt1, qt, qb);
    node_attn_kernel<<<NB, 256>>>(q, k, qt, qb, v, x1, wc, y, 0);

    // ---- layer 2 (x1 already relu'd; epilogue emits y directly) ----
    sgemm3_kernel<<<g3, 256>>>(x1, wq2, wk2, wv2, bq2, bk2, bv2, q, k, v, N_NODES, 256);
    qt_kernel<<<gQT, 256>>>(q, wt2, bt2, qt, qb);
    node_attn_kernel<<<NB, 256>>>(q, k, qt, qb, v, nullptr, wc, y, 1);

    // ---- edge readout ----
    edge_final_kernel<<<(N_EDGES + 255) / 256, 256>>>(bc, out);
}

// round 13
// speedup vs baseline: 3.4071x; 1.0551x over previous
#include <cuda_runtime.h>
#include <math.h>
#include <float.h>
#include <stdint.h>

#define N_NODES 20000
#define N_EDGES 320000
#define HC      256     // HEADS*HIDDEN
#define HEADS   4
#define HIDDEN  64
#define TD      64

// ---------------- scratch (device globals; no runtime allocation) ----------------
__device__ float g_te [(size_t)N_EDGES * TD];       //  82 MB, CSR-position order
__device__ float g_q  [(size_t)N_NODES * HC];
__device__ float g_k  [(size_t)N_NODES * HC];
__device__ float g_v  [(size_t)N_NODES * HC];
__device__ float g_qt [(size_t)N_NODES * HC];       // per-node time-proj of q
__device__ float g_qb [(size_t)N_NODES * HEADS];    // q · bt per head
__device__ float g_x1 [(size_t)N_NODES * HC];
__device__ float g_y  [N_NODES];                    // per-node readout dot
__device__ int   g_src[N_EDGES];
__device__ int   g_dst[N_EDGES];
__device__ int   g_off[N_NODES + 1];                // CSR offsets (by dst)
__device__ int   g_cur[N_NODES];                    // scatter cursors
__device__ int   g_eid[N_EDGES];                    // edge id at CSR position
__device__ int   g_csr_src[N_EDGES];                // src node at CSR position
__device__ int   g_is64;

// ---------------- edge_index dtype detection + conversion ----------------
__global__ void detect_idx_kernel(const unsigned int* __restrict__ w) {
    if (threadIdx.x == 0 && blockIdx.x == 0) {
        int ok = 1;
        for (int i = 0; i < 256; i++) {
            unsigned lo = w[2 * i], hi = w[2 * i + 1];
            if (hi != 0u || lo >= (unsigned)N_NODES) { ok = 0; break; }
        }
        g_is64 = ok;
    }
}

__global__ void convert_idx_kernel(const int* __restrict__ w) {
    int i = blockIdx.x * blockDim.x + threadIdx.x;
    if (i >= 2 * N_EDGES) return;
    int v = g_is64 ? w[2 * i] : w[i];    // little-endian low word
    if (i < N_EDGES) g_src[i] = v;
    else             g_dst[i - N_EDGES] = v;
}

// ---------------- CSR build: histogram -> scan -> scatter ----------------
__global__ void hist_zero_kernel() {
    int i = blockIdx.x * blockDim.x + threadIdx.x;
    if (i < N_NODES) g_cur[i] = 0;
}

__global__ void hist_kernel() {
    int e = blockIdx.x * blockDim.x + threadIdx.x;
    if (e < N_EDGES) atomicAdd(&g_cur[g_dst[e]], 1);
}

// single block, 1024 threads; each thread scans a 20-element chunk
__global__ void scan_kernel() {
    __shared__ int part[1024];
    const int CH = (N_NODES + 1023) / 1024;   // 20
    int t = threadIdx.x;
    int b0 = t * CH;
    int b1 = min(b0 + CH, N_NODES);
    int s = 0;
    for (int i = b0; i < b1; i++) s += g_cur[i];
    part[t] = s;
    __syncthreads();
    for (int off = 1; off < 1024; off <<= 1) {
        int vv = (t >= off) ? part[t - off] : 0;
        __syncthreads();
        part[t] += vv;
        __syncthreads();
    }
    int run = part[t] - s;   // exclusive base of this chunk
    for (int i = b0; i < b1; i++) {
        int d = g_cur[i];
        g_off[i] = run;
        run += d;
    }
    if (t == 1023) g_off[N_NODES] = run;
    __syncthreads();
    for (int i = b0; i < b1; i++) g_cur[i] = g_off[i];
}

__global__ void scatter_kernel() {
    int e = blockIdx.x * blockDim.x + threadIdx.x;
    if (e >= N_EDGES) return;
    int s = g_src[e];
    int pos = atomicAdd(&g_cur[g_dst[e]], 1);
    g_eid[pos] = e;
    g_csr_src[pos] = s;
}

// ---------------- time encoding into CSR order ----------------
__global__ void time_encode_kernel(const float* __restrict__ raw, const float* __restrict__ noise) {
    int pos = blockIdx.x * 8 + (threadIdx.x >> 5);
    int lane = threadIdx.x & 31;
    if (pos >= N_EDGES) return;
    int e = g_eid[pos];
    float t = raw[e] + noise[e];
    const float cst = -0.14391156831212787f;        // -ln(10000)/64
    float div = expf((float)(2 * lane) * cst);
    float arg = t * div;
    float kf = rintf(arg * 0.15915494309189535f);
    float r  = fmaf(-kf, 6.28125f, arg);
    r = fmaf(-kf, 1.9353071795864792e-3f, r);
    float s = __sinf(r);
    float c = __cosf(r);
    g_te[(size_t)pos * TD + 2 * lane]     = s;
    g_te[(size_t)pos * TD + 2 * lane + 1] = c;
}

// ---------------- TF32 helpers ----------------
__device__ __forceinline__ unsigned f2tf32(float x) {
    unsigned r;
    asm("cvt.rna.tf32.f32 %0, %1;" : "=r"(r) : "f"(x));
    return r;
}
__device__ __forceinline__ void tf32_split(float x, unsigned& hi, unsigned& lo) {
    hi = f2tf32(x);
    lo = f2tf32(x - __uint_as_float(hi));
}
__device__ __forceinline__ void mma_tf32(float* c, unsigned a0, unsigned a1, unsigned a2, unsigned a3,
                                         unsigned b0, unsigned b1) {
    asm volatile("mma.sync.aligned.m16n8k8.row.col.f32.tf32.tf32.f32 "
                 "{%0,%1,%2,%3}, {%4,%5,%6,%7}, {%8,%9}, {%0,%1,%2,%3};"
                 : "+f"(c[0]), "+f"(c[1]), "+f"(c[2]), "+f"(c[3])
                 : "r"(a0), "r"(a1), "r"(a2), "r"(a3), "r"(b0), "r"(b1));
}

// ---------------- fused QKV GEMM (tensor cores, 3xTF32): C = A[M,K] @ W + b ----------------
// 128x64 tile, 8 warps (4m x 2n), each warp 32x32 via m16n8k8 fragments.
// 3xTF32 split: C += Ahi*Bhi + Ahi*Blo + Alo*Bhi  (~fp32 accuracy).
__global__ __launch_bounds__(256) void mma3_kernel(const float* __restrict__ A,
                              const float* __restrict__ W0, const float* __restrict__ W1,
                              const float* __restrict__ W2,
                              const float* __restrict__ b0, const float* __restrict__ b1,
                              const float* __restrict__ b2,
                              float* __restrict__ C0, float* __restrict__ C1,
                              float* __restrict__ C2,
                              int M, int K) {
    const int N = HC;
    const float* W    = blockIdx.z == 0 ? W0 : (blockIdx.z == 1 ? W1 : W2);
    const float* bias = blockIdx.z == 0 ? b0 : (blockIdx.z == 1 ? b1 : b2);
    float*       C    = blockIdx.z == 0 ? C0 : (blockIdx.z == 1 ? C1 : C2);

    // stride ≡ 8 (mod 32): fragment LDS bank = 8*quad+group = lane → conflict-free
    __shared__ float sA[16][136];
    __shared__ float sW[16][72];

    int tid = threadIdx.x;
    int bm = blockIdx.y * 128, bn = blockIdx.x * 64;
    int warp = tid >> 5, lane = tid & 31;
    int wm = (warp >> 1) * 32, wn = (warp & 1) * 32;
    int gp = lane >> 2, qd = lane & 3;

    int ar = tid >> 1;                  // 0..127 A-load row
    int ac = (tid & 1) * 8;             // 0 or 8
    int wr = tid >> 4;                  // 0..15 W-load row
    int wcol = (tid & 15) * 4;          // 0..60

    float c[2][4][4];
#pragma unroll
    for (int t = 0; t < 2; t++)
#pragma unroll
        for (int u = 0; u < 4; u++)
#pragma unroll
            for (int f = 0; f < 4; f++) c[t][u][f] = 0.f;

    for (int k0 = 0; k0 < K; k0 += 16) {
        float4 a0 = make_float4(0.f, 0.f, 0.f, 0.f);
        float4 a1 = make_float4(0.f, 0.f, 0.f, 0.f);
        if (bm + ar < M) {
            a0 = *(const float4*)(A + (size_t)(bm + ar) * K + k0 + ac);
            a1 = *(const float4*)(A + (size_t)(bm + ar) * K + k0 + ac + 4);
        }
        sA[ac + 0][ar] = a0.x; sA[ac + 1][ar] = a0.y;
        sA[ac + 2][ar] = a0.z; sA[ac + 3][ar] = a0.w;
        sA[ac + 4][ar] = a1.x; sA[ac + 5][ar] = a1.y;
        sA[ac + 6][ar] = a1.z; sA[ac + 7][ar] = a1.w;
        *(float4*)&sW[wr][wcol] = *(const float4*)(W + (size_t)(k0 + wr) * N + bn + wcol);
        __syncthreads();

#pragma unroll
        for (int kc = 0; kc < 16; kc += 8) {
            unsigned ahi[2][4], alo[2][4];
#pragma unroll
            for (int t = 0; t < 2; t++) {
                float f0 = sA[kc + qd    ][wm + t * 16 + gp];
                float f1 = sA[kc + qd    ][wm + t * 16 + gp + 8];
                float f2 = sA[kc + qd + 4][wm + t * 16 + gp];
                float f3 = sA[kc + qd + 4][wm + t * 16 + gp + 8];
                tf32_split(f0, ahi[t][0], alo[t][0]);
                tf32_split(f1, ahi[t][1], alo[t][1]);
                tf32_split(f2, ahi[t][2], alo[t][2]);
                tf32_split(f3, ahi[t][3], alo[t][3]);
            }
            unsigned bhi[4][2], blo[4][2];
#pragma unroll
            for (int u = 0; u < 4; u++) {
                float g0 = sW[kc + qd    ][wn + u * 8 + gp];
                float g1 = sW[kc + qd + 4][wn + u * 8 + gp];
                tf32_split(g0, bhi[u][0], blo[u][0]);
                tf32_split(g1, bhi[u][1], blo[u][1]);
            }
#pragma unroll
            for (int t = 0; t < 2; t++)
#pragma unroll
                for (int u = 0; u < 4; u++) {
                    mma_tf32(c[t][u], alo[t][0], alo[t][1], alo[t][2], alo[t][3],
                             bhi[u][0], bhi[u][1]);
                    mma_tf32(c[t][u], ahi[t][0], ahi[t][1], ahi[t][2], ahi[t][3],
                             blo[u][0], blo[u][1]);
                    mma_tf32(c[t][u], ahi[t][0], ahi[t][1], ahi[t][2], ahi[t][3],
                             bhi[u][0], bhi[u][1]);
                }
        }
        __syncthreads();
    }

    // epilogue: C frag (gp, 2qd) / (gp+8, 2qd) pairs + bias
#pragma unroll
    for (int t = 0; t < 2; t++) {
        int r0 = bm + wm + t * 16 + gp;
        int r1 = r0 + 8;
#pragma unroll
        for (int u = 0; u < 4; u++) {
            int col = bn + wn + u * 8 + qd * 2;
            float bx = bias[col], by = bias[col + 1];
            if (r0 < M) {
                float2 o = make_float2(c[t][u][0] + bx, c[t][u][1] + by);
                *(float2*)(C + (size_t)r0 * N + col) = o;
            }
            if (r1 < M) {
                float2 o = make_float2(c[t][u][2] + bx, c[t][u][3] + by);
                *(float2*)(C + (size_t)r1 * N + col) = o;
            }
        }
    }
}

// ---------------- per-node time transform of q ----------------
__global__ void qt_kernel(const float* __restrict__ q, const float* __restrict__ wt,
                          const float* __restrict__ bt,
                          float* __restrict__ qt, float* __restrict__ qb) {
    __shared__ float sQ[64][68];
    __shared__ float sW[64][68];
    __shared__ float sB[64];
    int h = blockIdx.x;
    int bm = blockIdx.y * 64;
    int tid = threadIdx.x;         // 256

    int lr = tid >> 2;
    int lc = (tid & 3) * 16;
#pragma unroll
    for (int i = 0; i < 16; i += 4) {
        float4 v = make_float4(0.f, 0.f, 0.f, 0.f);
        if (bm + lr < N_NODES)
            v = *(const float4*)(q + (size_t)(bm + lr) * HC + h * 64 + lc + i);
        *(float4*)&sQ[lr][lc + i] = v;
        *(float4*)&sW[lr][lc + i] = *(const float4*)(wt + (size_t)lr * HC + h * 64 + lc + i);
    }
    if (tid < 64) sB[tid] = bt[h * 64 + tid];
    __syncthreads();

    int tx = tid & 15, ty = tid >> 4;
    float acc[4][4];
#pragma unroll
    for (int i = 0; i < 4; i++)
#pragma unroll
        for (int j = 0; j < 4; j++) acc[i][j] = 0.f;
#pragma unroll 8
    for (int c = 0; c < 64; c++) {
        float a0 = sQ[ty * 4 + 0][c], a1 = sQ[ty * 4 + 1][c];
        float a2 = sQ[ty * 4 + 2][c], a3 = sQ[ty * 4 + 3][c];
        float w0 = sW[tx * 4 + 0][c], w1 = sW[tx * 4 + 1][c];
        float w2 = sW[tx * 4 + 2][c], w3 = sW[tx * 4 + 3][c];
        acc[0][0] = fmaf(a0, w0, acc[0][0]); acc[0][1] = fmaf(a0, w1, acc[0][1]);
        acc[0][2] = fmaf(a0, w2, acc[0][2]); acc[0][3] = fmaf(a0, w3, acc[0][3]);
        acc[1][0] = fmaf(a1, w0, acc[1][0]); acc[1][1] = fmaf(a1, w1, acc[1][1]);
        acc[1][2] = fmaf(a1, w2, acc[1][2]); acc[1][3] = fmaf(a1, w3, acc[1][3]);
        acc[2][0] = fmaf(a2, w0, acc[2][0]); acc[2][1] = fmaf(a2, w1, acc[2][1]);
        acc[2][2] = fmaf(a2, w2, acc[2][2]); acc[2][3] = fmaf(a2, w3, acc[2][3]);
        acc[3][0] = fmaf(a3, w0, acc[3][0]); acc[3][1] = fmaf(a3, w1, acc[3][1]);
        acc[3][2] = fmaf(a3, w2, acc[3][2]); acc[3][3] = fmaf(a3, w3, acc[3][3]);
    }
#pragma unroll
    for (int i = 0; i < 4; i++) {
        int m = bm + ty * 4 + i;
        if (m < N_NODES) {
            float4 o = make_float4(acc[i][0], acc[i][1], acc[i][2], acc[i][3]);
            *(float4*)(qt + (size_t)m * HC + h * 64 + tx * 4) = o;
        }
    }

    {
        int row = tid >> 2, part = tid & 3;
        float ssum = 0.f;
#pragma unroll
        for (int c = part * 16; c < part * 16 + 16; c++)
            ssum += sQ[row][c] * sB[c];
        ssum += __shfl_down_sync(0xffffffffu, ssum, 2, 4);
        ssum += __shfl_down_sync(0xffffffffu, ssum, 1, 4);
        if (part == 0 && bm + row < N_NODES)
            qb[(size_t)(bm + row) * HEADS + h] = ssum;
    }
}

// ---------------- fused single-pass attention (warp per dst node, online softmax) ----------------
__global__ void node_attn_kernel(const float* __restrict__ q, const float* __restrict__ k,
                                 const float* __restrict__ qt, const float* __restrict__ qb,
                                 const float* __restrict__ v,
                                 float* __restrict__ xout, const float* __restrict__ wc,
                                 float* __restrict__ y, int mode) {
    int n = blockIdx.x * 8 + (threadIdx.x >> 5);
    int lane = threadIdx.x & 31;
    if (n >= N_NODES) return;
    int off0 = g_off[n], off1 = g_off[n + 1];

    int c0 = lane * 8;              // channel block (h = lane>>3)
    int j0 = (lane & 7) * 8;        // te block within row
    int h8 = lane >> 3;

    float4 q0, q1, w0, w1;
    {
        const float4* qp = (const float4*)(q  + (size_t)n * HC + c0);
        const float4* wp = (const float4*)(qt + (size_t)n * HC + c0);
        q0 = qp[0]; q1 = qp[1];
        w0 = wp[0]; w1 = wp[1];
    }
    float qbh = qb[(size_t)n * HEADS + h8];

    float m = -FLT_MAX;
    float denom = 0.f;
    float4 acc0 = make_float4(0.f, 0.f, 0.f, 0.f);
    float4 acc1 = make_float4(0.f, 0.f, 0.f, 0.f);

    for (int i = off0; i < off1; i++) {
        int s = g_csr_src[i];
        const float4* kp = (const float4*)(k + (size_t)s * HC + c0);
        const float4* vp = (const float4*)(v + (size_t)s * HC + c0);
        const float4* tp = (const float4*)(g_te + (size_t)i * TD + j0);
        float4 k0 = kp[0], k1 = kp[1];
        float4 t0 = tp[0], t1 = tp[1];
        float4 v0 = vp[0], v1 = vp[1];
        float p = q0.x * k0.x + q0.y * k0.y + q0.z * k0.z + q0.w * k0.w
                + q1.x * k1.x + q1.y * k1.y + q1.z * k1.z + q1.w * k1.w
                + w0.x * t0.x + w0.y * t0.y + w0.z * t0.z + w0.w * t0.w
                + w1.x * t1.x + w1.y * t1.y + w1.z * t1.z + w1.w * t1.w;
        p += __shfl_xor_sync(0xffffffffu, p, 4, 8);
        p += __shfl_xor_sync(0xffffffffu, p, 2, 8);
        p += __shfl_xor_sync(0xffffffffu, p, 1, 8);
        float alpha = (p + qbh) * 0.125f;      // / sqrt(64)

        float m_new = fmaxf(m, alpha);
        float corr = __expf(m - m_new);
        float wgt  = __expf(alpha - m_new);
        denom = denom * corr + wgt;
        m = m_new;
        acc0.x = fmaf(acc0.x, corr, v0.x * wgt);
        acc0.y = fmaf(acc0.y, corr, v0.y * wgt);
        acc0.z = fmaf(acc0.z, corr, v0.z * wgt);
        acc0.w = fmaf(acc0.w, corr, v0.w * wgt);
        acc1.x = fmaf(acc1.x, corr, v1.x * wgt);
        acc1.y = fmaf(acc1.y, corr, v1.y * wgt);
        acc1.z = fmaf(acc1.z, corr, v1.z * wgt);
        acc1.w = fmaf(acc1.w, corr, v1.w * wgt);
    }

    float inv = 1.f / (denom + 1e-16f);
    acc0.x = fmaxf(acc0.x * inv, 0.f); acc0.y = fmaxf(acc0.y * inv, 0.f);
    acc0.z = fmaxf(acc0.z * inv, 0.f); acc0.w = fmaxf(acc0.w * inv, 0.f);
    acc1.x = fmaxf(acc1.x * inv, 0.f); acc1.y = fmaxf(acc1.y * inv, 0.f);
    acc1.z = fmaxf(acc1.z * inv, 0.f); acc1.w = fmaxf(acc1.w * inv, 0.f);

    if (mode == 0) {
        float4* op = (float4*)(xout + (size_t)n * HC + c0);
        op[0] = acc0;
        op[1] = acc1;
    } else {
        const float4* wp = (const float4*)(wc + c0);
        float4 wc0 = wp[0], wc1 = wp[1];
        float p = acc0.x * wc0.x + acc0.y * wc0.y + acc0.z * wc0.z + acc0.w * wc0.w
                + acc1.x * wc1.x + acc1.y * wc1.y + acc1.z * wc1.z + acc1.w * wc1.w;
#pragma unroll
        for (int off = 16; off >= 1; off >>= 1)
            p += __shfl_down_sync(0xffffffffu, p, off);
        if (lane == 0) y[n] = p;
    }
}

// ---------------- final: out[e] = y[src] + y[dst] + bc ----------------
__global__ void edge_final_kernel(const float* __restrict__ bc, float* __restrict__ out) {
    int e = blockIdx.x * blockDim.x + threadIdx.x;
    if (e >= N_EDGES) return;
    out[e] = g_y[g_src[e]] + g_y[g_dst[e]] + bc[0];
}

// ---------------- launch ----------------
extern "C" void kernel_launch(void* const* d_in, const int* in_sizes, int n_in,
                              void* d_out, int out_size) {
    const void* ei        = d_in[0];
    const float* raw_time = (const float*)d_in[1];
    const float* noise    = (const float*)d_in[2];
    const float* node_emb = (const float*)d_in[3];
    const float* wq1 = (const float*)d_in[4],  *bq1 = (const float*)d_in[5];
    const float* wk1 = (const float*)d_in[6],  *bk1 = (const float*)d_in[7];
    const float* wv1 = (const float*)d_in[8],  *bv1 = (const float*)d_in[9];
    const float* wt1 = (const float*)d_in[10], *bt1 = (const float*)d_in[11];
    const float* wq2 = (const float*)d_in[12], *bq2 = (const float*)d_in[13];
    const float* wk2 = (const float*)d_in[14], *bk2 = (const float*)d_in[15];
    const float* wv2 = (const float*)d_in[16], *bv2 = (const float*)d_in[17];
    const float* wt2 = (const float*)d_in[18], *bt2 = (const float*)d_in[19];
    const float* wc  = (const float*)d_in[20], *bc  = (const float*)d_in[21];
    float* out = (float*)d_out;

    float *q, *k, *v, *qt, *qb, *x1, *y;
    cudaGetSymbolAddress((void**)&q,  g_q);
    cudaGetSymbolAddress((void**)&k,  g_k);
    cudaGetSymbolAddress((void**)&v,  g_v);
    cudaGetSymbolAddress((void**)&qt, g_qt);
    cudaGetSymbolAddress((void**)&qb, g_qb);
    cudaGetSymbolAddress((void**)&x1, g_x1);
    cudaGetSymbolAddress((void**)&y,  g_y);

    dim3 g3(HC / 64, (N_NODES + 127) / 128, 3);   // (4, 157, 3)
    dim3 gQT(HEADS, (N_NODES + 63) / 64);         // (4, 313)
    const int EB = N_EDGES / 8;                   // warp/edge
    const int NB = (N_NODES + 7) / 8;             // warp/node

    // index dtype detection + int32 conversion
    detect_idx_kernel<<<1, 32>>>((const unsigned int*)ei);
    convert_idx_kernel<<<(2 * N_EDGES + 255) / 256, 256>>>((const int*)ei);

    // CSR build (by dst)
    hist_zero_kernel<<<(N_NODES + 255) / 256, 256>>>();
    hist_kernel<<<(N_EDGES + 255) / 256, 256>>>();
    scan_kernel<<<1, 1024>>>();
    scatter_kernel<<<(N_EDGES + 255) / 256, 256>>>();

    // time encoding in CSR order (shared by both layers)
    time_encode_kernel<<<EB, 256>>>(raw_time, noise);

    // ---- layer 1 ----
    mma3_kernel<<<g3, 256>>>(node_emb, wq1, wk1, wv1, bq1, bk1, bv1, q, k, v, N_NODES, 128);
    qt_kernel<<<gQT, 256>>>(q, wt1, bt1, qt, qb);
    node_attn_kernel<<<NB, 256>>>(q, k, qt, qb, v, x1, wc, y, 0);

    // ---- layer 2 (x1 already relu'd; epilogue emits y directly) ----
    mma3_kernel<<<g3, 256>>>(x1, wq2, wk2, wv2, bq2, bk2, bv2, q, k, v, N_NODES, 256);
    qt_kernel<<<gQT, 256>>>(q, wt2, bt2, qt, qb);
    node_attn_kernel<<<NB, 256>>>(q, k, qt, qb, v, nullptr, wc, y, 1);

    // ---- edge readout ----
    edge_final_kernel<<<(N_EDGES + 255) / 256, 256>>>(bc, out);
}

// round 15
// speedup vs baseline: 3.5630x; 1.0457x over previous
#include <cuda_runtime.h>
#include <math.h>
#include <float.h>
#include <stdint.h>

#define N_NODES 20000
#define N_EDGES 320000
#define HC      256     // HEADS*HIDDEN
#define HEADS   4
#define HIDDEN  64
#define TD      64

// ---------------- scratch (device globals; no runtime allocation) ----------------
__device__ float g_te [(size_t)N_EDGES * TD];       //  82 MB, CSR-position order
__device__ float g_q  [(size_t)N_NODES * HC];
__device__ float g_k  [(size_t)N_NODES * HC];
__device__ float g_v  [(size_t)N_NODES * HC];
__device__ float g_qt [(size_t)N_NODES * HC];       // per-node time-proj of q
__device__ float g_qb [(size_t)N_NODES * HEADS];    // q · bt per head
__device__ float g_x1 [(size_t)N_NODES * HC];
__device__ float g_y  [N_NODES];                    // per-node readout dot
__device__ int   g_src[N_EDGES];
__device__ int   g_dst[N_EDGES];
__device__ int   g_off[N_NODES + 1];                // CSR offsets (by dst)
__device__ int   g_cur[N_NODES];                    // scatter cursors
__device__ int   g_eid[N_EDGES];                    // edge id at CSR position
__device__ int   g_csr_src[N_EDGES];                // src node at CSR position
__device__ int   g_is64;

// ---------------- edge_index dtype detection + conversion ----------------
__global__ void detect_idx_kernel(const unsigned int* __restrict__ w) {
    if (threadIdx.x == 0 && blockIdx.x == 0) {
        int ok = 1;
        for (int i = 0; i < 256; i++) {
            unsigned lo = w[2 * i], hi = w[2 * i + 1];
            if (hi != 0u || lo >= (unsigned)N_NODES) { ok = 0; break; }
        }
        g_is64 = ok;
    }
}

__global__ void convert_idx_kernel(const int* __restrict__ w) {
    int i = blockIdx.x * blockDim.x + threadIdx.x;
    if (i >= 2 * N_EDGES) return;
    int v = g_is64 ? w[2 * i] : w[i];    // little-endian low word
    if (i < N_EDGES) g_src[i] = v;
    else             g_dst[i - N_EDGES] = v;
}

// ---------------- CSR build: histogram -> scan -> scatter ----------------
__global__ void hist_zero_kernel() {
    int i = blockIdx.x * blockDim.x + threadIdx.x;
    if (i < N_NODES) g_cur[i] = 0;
}

__global__ void hist_kernel() {
    int e = blockIdx.x * blockDim.x + threadIdx.x;
    if (e < N_EDGES) atomicAdd(&g_cur[g_dst[e]], 1);
}

// single block, 1024 threads; each thread scans a 20-element chunk
__global__ void scan_kernel() {
    __shared__ int part[1024];
    const int CH = (N_NODES + 1023) / 1024;   // 20
    int t = threadIdx.x;
    int b0 = t * CH;
    int b1 = min(b0 + CH, N_NODES);
    int s = 0;
    for (int i = b0; i < b1; i++) s += g_cur[i];
    part[t] = s;
    __syncthreads();
    for (int off = 1; off < 1024; off <<= 1) {
        int vv = (t >= off) ? part[t - off] : 0;
        __syncthreads();
        part[t] += vv;
        __syncthreads();
    }
    int run = part[t] - s;   // exclusive base of this chunk
    for (int i = b0; i < b1; i++) {
        int d = g_cur[i];
        g_off[i] = run;
        run += d;
    }
    if (t == 1023) g_off[N_NODES] = run;
    __syncthreads();
    for (int i = b0; i < b1; i++) g_cur[i] = g_off[i];
}

__global__ void scatter_kernel() {
    int e = blockIdx.x * blockDim.x + threadIdx.x;
    if (e >= N_EDGES) return;
    int s = g_src[e];
    int pos = atomicAdd(&g_cur[g_dst[e]], 1);
    g_eid[pos] = e;
    g_csr_src[pos] = s;
}

// ---------------- time encoding into CSR order ----------------
__global__ void time_encode_kernel(const float* __restrict__ raw, const float* __restrict__ noise) {
    int pos = blockIdx.x * 8 + (threadIdx.x >> 5);
    int lane = threadIdx.x & 31;
    if (pos >= N_EDGES) return;
    int e = g_eid[pos];
    float t = raw[e] + noise[e];
    const float cst = -0.14391156831212787f;        // -ln(10000)/64
    float div = expf((float)(2 * lane) * cst);
    float arg = t * div;
    float kf = rintf(arg * 0.15915494309189535f);
    float r  = fmaf(-kf, 6.28125f, arg);
    r = fmaf(-kf, 1.9353071795864792e-3f, r);
    float s = __sinf(r);
    float c = __cosf(r);
    g_te[(size_t)pos * TD + 2 * lane]     = s;
    g_te[(size_t)pos * TD + 2 * lane + 1] = c;
}

// ---------------- TF32 helpers ----------------
__device__ __forceinline__ unsigned f2tf32(float x) {
    unsigned r;
    asm("cvt.rna.tf32.f32 %0, %1;" : "=r"(r) : "f"(x));
    return r;
}
__device__ __forceinline__ void tf32_split(float x, unsigned& hi, unsigned& lo) {
    hi = f2tf32(x);
    lo = f2tf32(x - __uint_as_float(hi));
}
__device__ __forceinline__ void mma_tf32(float* c, unsigned a0, unsigned a1, unsigned a2, unsigned a3,
                                         unsigned b0, unsigned b1) {
    asm volatile("mma.sync.aligned.m16n8k8.row.col.f32.tf32.tf32.f32 "
                 "{%0,%1,%2,%3}, {%4,%5,%6,%7}, {%8,%9}, {%0,%1,%2,%3};"
                 : "+f"(c[0]), "+f"(c[1]), "+f"(c[2]), "+f"(c[3])
                 : "r"(a0), "r"(a1), "r"(a2), "r"(a3), "r"(b0), "r"(b1));
}

// ---------------- fused QKV GEMM (tensor cores, 3xTF32): C = A[M,K] @ W + b ----------------
__global__ __launch_bounds__(256) void mma3_kernel(const float* __restrict__ A,
                              const float* __restrict__ W0, const float* __restrict__ W1,
                              const float* __restrict__ W2,
                              const float* __restrict__ b0, const float* __restrict__ b1,
                              const float* __restrict__ b2,
                              float* __restrict__ C0, float* __restrict__ C1,
                              float* __restrict__ C2,
                              int M, int K) {
    const int N = HC;
    const float* W    = blockIdx.z == 0 ? W0 : (blockIdx.z == 1 ? W1 : W2);
    const float* bias = blockIdx.z == 0 ? b0 : (blockIdx.z == 1 ? b1 : b2);
    float*       C    = blockIdx.z == 0 ? C0 : (blockIdx.z == 1 ? C1 : C2);

    __shared__ float sA[16][136];
    __shared__ float sW[16][72];

    int tid = threadIdx.x;
    int bm = blockIdx.y * 128, bn = blockIdx.x * 64;
    int warp = tid >> 5, lane = tid & 31;
    int wm = (warp >> 1) * 32, wn = (warp & 1) * 32;
    int gp = lane >> 2, qd = lane & 3;

    int ar = tid >> 1;                  // 0..127 A-load row
    int ac = (tid & 1) * 8;             // 0 or 8
    int wr = tid >> 4;                  // 0..15 W-load row
    int wcol = (tid & 15) * 4;          // 0..60

    float c[2][4][4];
#pragma unroll
    for (int t = 0; t < 2; t++)
#pragma unroll
        for (int u = 0; u < 4; u++)
#pragma unroll
            for (int f = 0; f < 4; f++) c[t][u][f] = 0.f;

    for (int k0 = 0; k0 < K; k0 += 16) {
        float4 a0 = make_float4(0.f, 0.f, 0.f, 0.f);
        float4 a1 = make_float4(0.f, 0.f, 0.f, 0.f);
        if (bm + ar < M) {
            a0 = *(const float4*)(A + (size_t)(bm + ar) * K + k0 + ac);
            a1 = *(const float4*)(A + (size_t)(bm + ar) * K + k0 + ac + 4);
        }
        sA[ac + 0][ar] = a0.x; sA[ac + 1][ar] = a0.y;
        sA[ac + 2][ar] = a0.z; sA[ac + 3][ar] = a0.w;
        sA[ac + 4][ar] = a1.x; sA[ac + 5][ar] = a1.y;
        sA[ac + 6][ar] = a1.z; sA[ac + 7][ar] = a1.w;
        *(float4*)&sW[wr][wcol] = *(const float4*)(W + (size_t)(k0 + wr) * N + bn + wcol);
        __syncthreads();

#pragma unroll
        for (int kc = 0; kc < 16; kc += 8) {
            unsigned ahi[2][4], alo[2][4];
#pragma unroll
            for (int t = 0; t < 2; t++) {
                float f0 = sA[kc + qd    ][wm + t * 16 + gp];
                float f1 = sA[kc + qd    ][wm + t * 16 + gp + 8];
                float f2 = sA[kc + qd + 4][wm + t * 16 + gp];
                float f3 = sA[kc + qd + 4][wm + t * 16 + gp + 8];
                tf32_split(f0, ahi[t][0], alo[t][0]);
                tf32_split(f1, ahi[t][1], alo[t][1]);
                tf32_split(f2, ahi[t][2], alo[t][2]);
                tf32_split(f3, ahi[t][3], alo[t][3]);
            }
            unsigned bhi[4][2], blo[4][2];
#pragma unroll
            for (int u = 0; u < 4; u++) {
                float g0 = sW[kc + qd    ][wn + u * 8 + gp];
                float g1 = sW[kc + qd + 4][wn + u * 8 + gp];
                tf32_split(g0, bhi[u][0], blo[u][0]);
                tf32_split(g1, bhi[u][1], blo[u][1]);
            }
#pragma unroll
            for (int t = 0; t < 2; t++)
#pragma unroll
                for (int u = 0; u < 4; u++) {
                    mma_tf32(c[t][u], alo[t][0], alo[t][1], alo[t][2], alo[t][3],
                             bhi[u][0], bhi[u][1]);
                    mma_tf32(c[t][u], ahi[t][0], ahi[t][1], ahi[t][2], ahi[t][3],
                             blo[u][0], blo[u][1]);
                    mma_tf32(c[t][u], ahi[t][0], ahi[t][1], ahi[t][2], ahi[t][3],
                             bhi[u][0], bhi[u][1]);
                }
        }
        __syncthreads();
    }

#pragma unroll
    for (int t = 0; t < 2; t++) {
        int r0 = bm + wm + t * 16 + gp;
        int r1 = r0 + 8;
#pragma unroll
        for (int u = 0; u < 4; u++) {
            int col = bn + wn + u * 8 + qd * 2;
            float bx = bias[col], by = bias[col + 1];
            if (r0 < M) {
                float2 o = make_float2(c[t][u][0] + bx, c[t][u][1] + by);
                *(float2*)(C + (size_t)r0 * N + col) = o;
            }
            if (r1 < M) {
                float2 o = make_float2(c[t][u][2] + bx, c[t][u][3] + by);
                *(float2*)(C + (size_t)r1 * N + col) = o;
            }
        }
    }
}

// ---------------- per-node time transform of q ----------------
__global__ void qt_kernel(const float* __restrict__ q, const float* __restrict__ wt,
                          const float* __restrict__ bt,
                          float* __restrict__ qt, float* __restrict__ qb) {
    __shared__ float sQ[64][68];
    __shared__ float sW[64][68];
    __shared__ float sB[64];
    int h = blockIdx.x;
    int bm = blockIdx.y * 64;
    int tid = threadIdx.x;         // 256

    int lr = tid >> 2;
    int lc = (tid & 3) * 16;
#pragma unroll
    for (int i = 0; i < 16; i += 4) {
        float4 v = make_float4(0.f, 0.f, 0.f, 0.f);
        if (bm + lr < N_NODES)
            v = *(const float4*)(q + (size_t)(bm + lr) * HC + h * 64 + lc + i);
        *(float4*)&sQ[lr][lc + i] = v;
        *(float4*)&sW[lr][lc + i] = *(const float4*)(wt + (size_t)lr * HC + h * 64 + lc + i);
    }
    if (tid < 64) sB[tid] = bt[h * 64 + tid];
    __syncthreads();

    int tx = tid & 15, ty = tid >> 4;
    float acc[4][4];
#pragma unroll
    for (int i = 0; i < 4; i++)
#pragma unroll
        for (int j = 0; j < 4; j++) acc[i][j] = 0.f;
#pragma unroll 8
    for (int c = 0; c < 64; c++) {
        float a0 = sQ[ty * 4 + 0][c], a1 = sQ[ty * 4 + 1][c];
        float a2 = sQ[ty * 4 + 2][c], a3 = sQ[ty * 4 + 3][c];
        float w0 = sW[tx * 4 + 0][c], w1 = sW[tx * 4 + 1][c];
        float w2 = sW[tx * 4 + 2][c], w3 = sW[tx * 4 + 3][c];
        acc[0][0] = fmaf(a0, w0, acc[0][0]); acc[0][1] = fmaf(a0, w1, acc[0][1]);
        acc[0][2] = fmaf(a0, w2, acc[0][2]); acc[0][3] = fmaf(a0, w3, acc[0][3]);
        acc[1][0] = fmaf(a1, w0, acc[1][0]); acc[1][1] = fmaf(a1, w1, acc[1][1]);
        acc[1][2] = fmaf(a1, w2, acc[1][2]); acc[1][3] = fmaf(a1, w3, acc[1][3]);
        acc[2][0] = fmaf(a2, w0, acc[2][0]); acc[2][1] = fmaf(a2, w1, acc[2][1]);
        acc[2][2] = fmaf(a2, w2, acc[2][2]); acc[2][3] = fmaf(a2, w3, acc[2][3]);
        acc[3][0] = fmaf(a3, w0, acc[3][0]); acc[3][1] = fmaf(a3, w1, acc[3][1]);
        acc[3][2] = fmaf(a3, w2, acc[3][2]); acc[3][3] = fmaf(a3, w3, acc[3][3]);
    }
#pragma unroll
    for (int i = 0; i < 4; i++) {
        int m = bm + ty * 4 + i;
        if (m < N_NODES) {
            float4 o = make_float4(acc[i][0], acc[i][1], acc[i][2], acc[i][3]);
            *(float4*)(qt + (size_t)m * HC + h * 64 + tx * 4) = o;
        }
    }

    {
        int row = tid >> 2, part = tid & 3;
        float ssum = 0.f;
#pragma unroll
        for (int c = part * 16; c < part * 16 + 16; c++)
            ssum += sQ[row][c] * sB[c];
        ssum += __shfl_down_sync(0xffffffffu, ssum, 2, 4);
        ssum += __shfl_down_sync(0xffffffffu, ssum, 1, 4);
        if (part == 0 && bm + row < N_NODES)
            qb[(size_t)(bm + row) * HEADS + h] = ssum;
    }
}

// ---------------- fused single-pass attention, 2-way unrolled online softmax ----------------
// Two independent (m, denom, acc) states over even/odd CSR slots, merged exactly at the end.
__global__ __launch_bounds__(128) void node_attn_kernel(
                                 const float* __restrict__ q, const float* __restrict__ k,
                                 const float* __restrict__ qt, const float* __restrict__ qb,
                                 const float* __restrict__ v,
                                 float* __restrict__ xout, const float* __restrict__ wc,
                                 float* __restrict__ y, int mode) {
    int n = blockIdx.x * 4 + (threadIdx.x >> 5);
    int lane = threadIdx.x & 31;
    if (n >= N_NODES) return;
    int off0 = g_off[n], off1 = g_off[n + 1];

    int c0 = lane * 8;              // channel block (h = lane>>3)
    int j0 = (lane & 7) * 8;        // te block within row
    int h8 = lane >> 3;

    float4 q0, q1, w0, w1;
    {
        const float4* qp = (const float4*)(q  + (size_t)n * HC + c0);
        const float4* wp = (const float4*)(qt + (size_t)n * HC + c0);
        q0 = qp[0]; q1 = qp[1];
        w0 = wp[0]; w1 = wp[1];
    }
    float qbh = qb[(size_t)n * HEADS + h8];

    // two independent online-softmax states
    float mA = -FLT_MAX, dA = 0.f;
    float mB = -FLT_MAX, dB = 0.f;
    float4 a0A = make_float4(0.f,0.f,0.f,0.f), a1A = make_float4(0.f,0.f,0.f,0.f);
    float4 a0B = make_float4(0.f,0.f,0.f,0.f), a1B = make_float4(0.f,0.f,0.f,0.f);

    int i = off0;
#pragma unroll 1
    for (; i + 1 < off1; i += 2) {
        int s0 = g_csr_src[i];
        int s1 = g_csr_src[i + 1];
        const float4* kp0 = (const float4*)(k + (size_t)s0 * HC + c0);
        const float4* kp1 = (const float4*)(k + (size_t)s1 * HC + c0);
        const float4* vp0 = (const float4*)(v + (size_t)s0 * HC + c0);
        const float4* vp1 = (const float4*)(v + (size_t)s1 * HC + c0);
        const float4* tp0 = (const float4*)(g_te + (size_t)i * TD + j0);
        const float4* tp1 = (const float4*)(g_te + (size_t)(i + 1) * TD + j0);
        float4 kA0 = kp0[0], kA1 = kp0[1];
        float4 kB0 = kp1[0], kB1 = kp1[1];
        float4 tA0 = tp0[0], tA1 = tp0[1];
        float4 tB0 = tp1[0], tB1 = tp1[1];
        float4 vA0 = vp0[0], vA1 = vp0[1];
        float4 vB0 = vp1[0], vB1 = vp1[1];

        float pA = q0.x*kA0.x + q0.y*kA0.y + q0.z*kA0.z + q0.w*kA0.w
                 + q1.x*kA1.x + q1.y*kA1.y + q1.z*kA1.z + q1.w*kA1.w
                 + w0.x*tA0.x + w0.y*tA0.y + w0.z*tA0.z + w0.w*tA0.w
                 + w1.x*tA1.x + w1.y*tA1.y + w1.z*tA1.z + w1.w*tA1.w;
        float pB = q0.x*kB0.x + q0.y*kB0.y + q0.z*kB0.z + q0.w*kB0.w
                 + q1.x*kB1.x + q1.y*kB1.y + q1.z*kB1.z + q1.w*kB1.w
                 + w0.x*tB0.x + w0.y*tB0.y + w0.z*tB0.z + w0.w*tB0.w
                 + w1.x*tB1.x + w1.y*tB1.y + w1.z*tB1.z + w1.w*tB1.w;
        pA += __shfl_xor_sync(0xffffffffu, pA, 4, 8);
        pB += __shfl_xor_sync(0xffffffffu, pB, 4, 8);
        pA += __shfl_xor_sync(0xffffffffu, pA, 2, 8);
        pB += __shfl_xor_sync(0xffffffffu, pB, 2, 8);
        pA += __shfl_xor_sync(0xffffffffu, pA, 1, 8);
        pB += __shfl_xor_sync(0xffffffffu, pB, 1, 8);
        float alA = (pA + qbh) * 0.125f;
        float alB = (pB + qbh) * 0.125f;

        float mnA = fmaxf(mA, alA);
        float mnB = fmaxf(mB, alB);
        float cA = __expf(mA - mnA), gA = __expf(alA - mnA);
        float cB = __expf(mB - mnB), gB = __expf(alB - mnB);
        dA = dA * cA + gA;  mA = mnA;
        dB = dB * cB + gB;  mB = mnB;
        a0A.x = fmaf(a0A.x, cA, vA0.x * gA); a0A.y = fmaf(a0A.y, cA, vA0.y * gA);
        a0A.z = fmaf(a0A.z, cA, vA0.z * gA); a0A.w = fmaf(a0A.w, cA, vA0.w * gA);
        a1A.x = fmaf(a1A.x, cA, vA1.x * gA); a1A.y = fmaf(a1A.y, cA, vA1.y * gA);
        a1A.z = fmaf(a1A.z, cA, vA1.z * gA); a1A.w = fmaf(a1A.w, cA, vA1.w * gA);
        a0B.x = fmaf(a0B.x, cB, vB0.x * gB); a0B.y = fmaf(a0B.y, cB, vB0.y * gB);
        a0B.z = fmaf(a0B.z, cB, vB0.z * gB); a0B.w = fmaf(a0B.w, cB, vB0.w * gB);
        a1B.x = fmaf(a1B.x, cB, vB1.x * gB); a1B.y = fmaf(a1B.y, cB, vB1.y * gB);
        a1B.z = fmaf(a1B.z, cB, vB1.z * gB); a1B.w = fmaf(a1B.w, cB, vB1.w * gB);
    }
    if (i < off1) {   // odd tail -> state A
        int s0 = g_csr_src[i];
        const float4* kp0 = (const float4*)(k + (size_t)s0 * HC + c0);
        const float4* vp0 = (const float4*)(v + (size_t)s0 * HC + c0);
        const float4* tp0 = (const float4*)(g_te + (size_t)i * TD + j0);
        float4 kA0 = kp0[0], kA1 = kp0[1];
        float4 tA0 = tp0[0], tA1 = tp0[1];
        float4 vA0 = vp0[0], vA1 = vp0[1];
        float pA = q0.x*kA0.x + q0.y*kA0.y + q0.z*kA0.z + q0.w*kA0.w
                 + q1.x*kA1.x + q1.y*kA1.y + q1.z*kA1.z + q1.w*kA1.w
                 + w0.x*tA0.x + w0.y*tA0.y + w0.z*tA0.z + w0.w*tA0.w
                 + w1.x*tA1.x + w1.y*tA1.y + w1.z*tA1.z + w1.w*tA1.w;
        pA += __shfl_xor_sync(0xffffffffu, pA, 4, 8);
        pA += __shfl_xor_sync(0xffffffffu, pA, 2, 8);
        pA += __shfl_xor_sync(0xffffffffu, pA, 1, 8);
        float alA = (pA + qbh) * 0.125f;
        float mnA = fmaxf(mA, alA);
        float cA = __expf(mA - mnA), gA = __expf(alA - mnA);
        dA = dA * cA + gA;  mA = mnA;
        a0A.x = fmaf(a0A.x, cA, vA0.x * gA); a0A.y = fmaf(a0A.y, cA, vA0.y * gA);
        a0A.z = fmaf(a0A.z, cA, vA0.z * gA); a0A.w = fmaf(a0A.w, cA, vA0.w * gA);
        a1A.x = fmaf(a1A.x, cA, vA1.x * gA); a1A.y = fmaf(a1A.y, cA, vA1.y * gA);
        a1A.z = fmaf(a1A.z, cA, vA1.z * gA); a1A.w = fmaf(a1A.w, cA, vA1.w * gA);
    }

    // merge states (exact; both-empty case: mA==mB==-FLT_MAX -> corr=1, denom=0 -> zeros)
    float mM = fmaxf(mA, mB);
    float cA = __expf(mA - mM), cB = __expf(mB - mM);
    float denom = dA * cA + dB * cB;
    float4 acc0, acc1;
    acc0.x = a0A.x * cA + a0B.x * cB; acc0.y = a0A.y * cA + a0B.y * cB;
    acc0.z = a0A.z * cA + a0B.z * cB; acc0.w = a0A.w * cA + a0B.w * cB;
    acc1.x = a1A.x * cA + a1B.x * cB; acc1.y = a1A.y * cA + a1B.y * cB;
    acc1.z = a1A.z * cA + a1B.z * cB; acc1.w = a1A.w * cA + a1B.w * cB;

    float inv = 1.f / (denom + 1e-16f);
    acc0.x = fmaxf(acc0.x * inv, 0.f); acc0.y = fmaxf(acc0.y * inv, 0.f);
    acc0.z = fmaxf(acc0.z * inv, 0.f); acc0.w = fmaxf(acc0.w * inv, 0.f);
    acc1.x = fmaxf(acc1.x * inv, 0.f); acc1.y = fmaxf(acc1.y * inv, 0.f);
    acc1.z = fmaxf(acc1.z * inv, 0.f); acc1.w = fmaxf(acc1.w * inv, 0.f);

    if (mode == 0) {
        float4* op = (float4*)(xout + (size_t)n * HC + c0);
        op[0] = acc0;
        op[1] = acc1;
    } else {
        const float4* wp = (const float4*)(wc + c0);
        float4 wc0 = wp[0], wc1 = wp[1];
        float p = acc0.x * wc0.x + acc0.y * wc0.y + acc0.z * wc0.z + acc0.w * wc0.w
                + acc1.x * wc1.x + acc1.y * wc1.y + acc1.z * wc1.z + acc1.w * wc1.w;
#pragma unroll
        for (int off = 16; off >= 1; off >>= 1)
            p += __shfl_down_sync(0xffffffffu, p, off);
        if (lane == 0) y[n] = p;
    }
}

// ---------------- final: out[e] = y[src] + y[dst] + bc ----------------
__global__ void edge_final_kernel(const float* __restrict__ bc, float* __restrict__ out) {
    int e = blockIdx.x * blockDim.x + threadIdx.x;
    if (e >= N_EDGES) return;
    out[e] = g_y[g_src[e]] + g_y[g_dst[e]] + bc[0];
}

// ---------------- launch ----------------
extern "C" void kernel_launch(void* const* d_in, const int* in_sizes, int n_in,
                              void* d_out, int out_size) {
    const void* ei        = d_in[0];
    const float* raw_time = (const float*)d_in[1];
    const float* noise    = (const float*)d_in[2];
    const float* node_emb = (const float*)d_in[3];
    const float* wq1 = (const float*)d_in[4],  *bq1 = (const float*)d_in[5];
    const float* wk1 = (const float*)d_in[6],  *bk1 = (const float*)d_in[7];
    const float* wv1 = (const float*)d_in[8],  *bv1 = (const float*)d_in[9];
    const float* wt1 = (const float*)d_in[10], *bt1 = (const float*)d_in[11];
    const float* wq2 = (const float*)d_in[12], *bq2 = (const float*)d_in[13];
    const float* wk2 = (const float*)d_in[14], *bk2 = (const float*)d_in[15];
    const float* wv2 = (const float*)d_in[16], *bv2 = (const float*)d_in[17];
    const float* wt2 = (const float*)d_in[18], *bt2 = (const float*)d_in[19];
    const float* wc  = (const float*)d_in[20], *bc  = (const float*)d_in[21];
    float* out = (float*)d_out;

    float *q, *k, *v, *qt, *qb, *x1, *y;
    cudaGetSymbolAddress((void**)&q,  g_q);
    cudaGetSymbolAddress((void**)&k,  g_k);
    cudaGetSymbolAddress((void**)&v,  g_v);
    cudaGetSymbolAddress((void**)&qt, g_qt);
    cudaGetSymbolAddress((void**)&qb, g_qb);
    cudaGetSymbolAddress((void**)&x1, g_x1);
    cudaGetSymbolAddress((void**)&y,  g_y);

    dim3 g3(HC / 64, (N_NODES + 127) / 128, 3);   // (4, 157, 3)
    dim3 gQT(HEADS, (N_NODES + 63) / 64);         // (4, 313)
    const int EB = N_EDGES / 8;                   // warp/edge
    const int NB = (N_NODES + 3) / 4;             // warp/node, 128-thread blocks

    // index dtype detection + int32 conversion
    detect_idx_kernel<<<1, 32>>>((const unsigned int*)ei);
    convert_idx_kernel<<<(2 * N_EDGES + 255) / 256, 256>>>((const int*)ei);

    // CSR build (by dst)
    hist_zero_kernel<<<(N_NODES + 255) / 256, 256>>>();
    hist_kernel<<<(N_EDGES + 255) / 256, 256>>>();
    scan_kernel<<<1, 1024>>>();
    scatter_kernel<<<(N_EDGES + 255) / 256, 256>>>();

    // time encoding in CSR order (shared by both layers)
    time_encode_kernel<<<EB, 256>>>(raw_time, noise);

    // ---- layer 1 ----
    mma3_kernel<<<g3, 256>>>(node_emb, wq1, wk1, wv1, bq1, bk1, bv1, q, k, v, N_NODES, 128);
    qt_kernel<<<gQT, 256>>>(q, wt1, bt1, qt, qb);
    node_attn_kernel<<<NB, 128>>>(q, k, qt, qb, v, x1, wc, y, 0);

    // ---- layer 2 (x1 already relu'd; epilogue emits y directly) ----
    mma3_kernel<<<g3, 256>>>(x1, wq2, wk2, wv2, bq2, bk2, bv2, q, k, v, N_NODES, 256);
    qt_kernel<<<gQT, 256>>>(q, wt2, bt2, qt, qb);
    node_attn_kernel<<<NB, 128>>>(q, k, qt, qb, v, nullptr, wc, y, 1);

    // ---- edge readout ----
    edge_final_kernel<<<(N_EDGES + 255) / 256, 256>>>(bc, out);
}

// round 16
// speedup vs baseline: 3.6523x; 1.0251x over previous
#include <cuda_runtime.h>
#include <math.h>
#include <float.h>
#include <stdint.h>

#define N_NODES 20000
#define N_EDGES 320000
#define HC      256     // HEADS*HIDDEN
#define HEADS   4
#define HIDDEN  64
#define TD      64

// ---------------- scratch (device globals; no runtime allocation) ----------------
__device__ float g_te [(size_t)N_EDGES * TD];       //  82 MB, CSR-position order
__device__ float g_q  [(size_t)N_NODES * HC];
__device__ float g_k  [(size_t)N_NODES * HC];
__device__ float g_v  [(size_t)N_NODES * HC];
__device__ float g_qt [(size_t)N_NODES * HC];       // per-node time-proj of q
__device__ float g_x1 [(size_t)N_NODES * HC];
__device__ float g_y  [N_NODES];                    // per-node readout dot
__device__ float g_wf [(size_t)HC * HC];            // fused Wq@WtT (K<=256)
__device__ float g_bf [HC];                         // fused bq@WtT
__device__ int   g_src[N_EDGES];
__device__ int   g_dst[N_EDGES];
__device__ int   g_off[N_NODES + 1];                // CSR offsets (by dst)
__device__ int   g_cur[N_NODES];                    // scatter cursors
__device__ int   g_eid[N_EDGES];                    // edge id at CSR position
__device__ int   g_csr_src[N_EDGES];                // src node at CSR position
__device__ int   g_is64;

// ---------------- edge_index dtype detection ----------------
__global__ void detect_idx_kernel(const unsigned int* __restrict__ w) {
    if (threadIdx.x == 0 && blockIdx.x == 0) {
        int ok = 1;
        for (int i = 0; i < 256; i++) {
            unsigned lo = w[2 * i], hi = w[2 * i + 1];
            if (hi != 0u || lo >= (unsigned)N_NODES) { ok = 0; break; }
        }
        g_is64 = ok;
    }
}

__global__ void hist_zero_kernel() {
    int i = blockIdx.x * blockDim.x + threadIdx.x;
    if (i < N_NODES) g_cur[i] = 0;
}

// convert + dst histogram in one pass
__global__ void convert_hist_kernel(const int* __restrict__ w) {
    int i = blockIdx.x * blockDim.x + threadIdx.x;
    if (i >= 2 * N_EDGES) return;
    int v = g_is64 ? w[2 * i] : w[i];    // little-endian low word
    if (i < N_EDGES) {
        g_src[i] = v;
    } else {
        g_dst[i - N_EDGES] = v;
        atomicAdd(&g_cur[v], 1);
    }
}

// single block, 1024 threads; each thread scans a 20-element chunk
__global__ void scan_kernel() {
    __shared__ int part[1024];
    const int CH = (N_NODES + 1023) / 1024;   // 20
    int t = threadIdx.x;
    int b0 = t * CH;
    int b1 = min(b0 + CH, N_NODES);
    int s = 0;
    for (int i = b0; i < b1; i++) s += g_cur[i];
    part[t] = s;
    __syncthreads();
    for (int off = 1; off < 1024; off <<= 1) {
        int vv = (t >= off) ? part[t - off] : 0;
        __syncthreads();
        part[t] += vv;
        __syncthreads();
    }
    int run = part[t] - s;   // exclusive base of this chunk
    for (int i = b0; i < b1; i++) {
        int d = g_cur[i];
        g_off[i] = run;
        run += d;
    }
    if (t == 1023) g_off[N_NODES] = run;
    __syncthreads();
    for (int i = b0; i < b1; i++) g_cur[i] = g_off[i];
}

__global__ void scatter_kernel() {
    int e = blockIdx.x * blockDim.x + threadIdx.x;
    if (e >= N_EDGES) return;
    int s = g_src[e];
    int pos = atomicAdd(&g_cur[g_dst[e]], 1);
    g_eid[pos] = e;
    g_csr_src[pos] = s;
}

// ---------------- time encoding into CSR order ----------------
__global__ void time_encode_kernel(const float* __restrict__ raw, const float* __restrict__ noise) {
    int pos = blockIdx.x * 8 + (threadIdx.x >> 5);
    int lane = threadIdx.x & 31;
    if (pos >= N_EDGES) return;
    int e = g_eid[pos];
    float t = raw[e] + noise[e];
    const float cst = -0.14391156831212787f;        // -ln(10000)/64
    float div = expf((float)(2 * lane) * cst);
    float arg = t * div;
    float kf = rintf(arg * 0.15915494309189535f);
    float r  = fmaf(-kf, 6.28125f, arg);
    r = fmaf(-kf, 1.9353071795864792e-3f, r);
    float s = __sinf(r);
    float c = __cosf(r);
    g_te[(size_t)pos * TD + 2 * lane]     = s;
    g_te[(size_t)pos * TD + 2 * lane + 1] = c;
}

// ---------------- fused time-weight prep: Wf = Wq @ WtT (blocked per head), bf = bq @ WtT ----------------
// Wf[k, h*64+j] = sum_c Wq[k, h*64+c] * Wt[j, h*64+c];  bf likewise from bq.
__global__ void fuse_wt_kernel(const float* __restrict__ wq, const float* __restrict__ wt,
                               const float* __restrict__ bq, int K) {
    int idx = blockIdx.x * blockDim.x + threadIdx.x;
    if (idx >= K * HC) return;
    int k = idx / HC, n = idx - k * HC;
    int h64 = n & ~63;     // h*64
    int j = n & 63;
    const float* wqr = wq + (size_t)k * HC + h64;
    const float* wtr = wt + (size_t)j * HC + h64;
    float s = 0.f, sb = 0.f;
    if (k == 0) {
        const float* bqr = bq + h64;
#pragma unroll 8
        for (int c = 0; c < 64; c++) {
            float w = wtr[c];
            s  = fmaf(wqr[c], w, s);
            sb = fmaf(bqr[c], w, sb);
        }
        g_bf[n] = sb;
    } else {
#pragma unroll 8
        for (int c = 0; c < 64; c++)
            s = fmaf(wqr[c], wtr[c], s);
    }
    g_wf[idx] = s;
}

// ---------------- TF32 helpers ----------------
__device__ __forceinline__ unsigned f2tf32(float x) {
    unsigned r;
    asm("cvt.rna.tf32.f32 %0, %1;" : "=r"(r) : "f"(x));
    return r;
}
__device__ __forceinline__ void tf32_split(float x, unsigned& hi, unsigned& lo) {
    hi = f2tf32(x);
    lo = f2tf32(x - __uint_as_float(hi));
}
__device__ __forceinline__ void mma_tf32(float* c, unsigned a0, unsigned a1, unsigned a2, unsigned a3,
                                         unsigned b0, unsigned b1) {
    asm volatile("mma.sync.aligned.m16n8k8.row.col.f32.tf32.tf32.f32 "
                 "{%0,%1,%2,%3}, {%4,%5,%6,%7}, {%8,%9}, {%0,%1,%2,%3};"
                 : "+f"(c[0]), "+f"(c[1]), "+f"(c[2]), "+f"(c[3])
                 : "r"(a0), "r"(a1), "r"(a2), "r"(a3), "r"(b0), "r"(b1));
}

// ---------------- fused Q/K/V/QT GEMM (tensor cores, 3xTF32) ----------------
// 128x128 tile, 8 warps (4m x 2n), each warp 32x64 via m16n8k8 fragments.
__global__ __launch_bounds__(256) void mma4_kernel(const float* __restrict__ A,
                              const float* __restrict__ W0, const float* __restrict__ W1,
                              const float* __restrict__ W2, const float* __restrict__ W3,
                              const float* __restrict__ b0, const float* __restrict__ b1,
                              const float* __restrict__ b2, const float* __restrict__ b3,
                              float* __restrict__ C0, float* __restrict__ C1,
                              float* __restrict__ C2, float* __restrict__ C3,
                              int M, int K) {
    const int N = HC;
    int z = blockIdx.z;
    const float* W    = z == 0 ? W0 : (z == 1 ? W1 : (z == 2 ? W2 : W3));
    const float* bias = z == 0 ? b0 : (z == 1 ? b1 : (z == 2 ? b2 : b3));
    float*       C    = z == 0 ? C0 : (z == 1 ? C1 : (z == 2 ? C2 : C3));

    __shared__ float sA[16][136];
    __shared__ float sW[16][136];

    int tid = threadIdx.x;
    int bm = blockIdx.y * 128, bn = blockIdx.x * 128;
    int warp = tid >> 5, lane = tid & 31;
    int wm = (warp >> 1) * 32, wn = (warp & 1) * 64;
    int gp = lane >> 2, qd = lane & 3;

    int ar = tid >> 1;                  // 0..127 A-load row
    int ac = (tid & 1) * 8;             // 0 or 8
    int wr = tid >> 4;                  // 0..15 W-load row
    int wcol = (tid & 15) * 8;          // 0..120

    float c[2][8][4];
#pragma unroll
    for (int t = 0; t < 2; t++)
#pragma unroll
        for (int u = 0; u < 8; u++)
#pragma unroll
            for (int f = 0; f < 4; f++) c[t][u][f] = 0.f;

    for (int k0 = 0; k0 < K; k0 += 16) {
        float4 a0 = make_float4(0.f, 0.f, 0.f, 0.f);
        float4 a1 = make_float4(0.f, 0.f, 0.f, 0.f);
        if (bm + ar < M) {
            a0 = *(const float4*)(A + (size_t)(bm + ar) * K + k0 + ac);
            a1 = *(const float4*)(A + (size_t)(bm + ar) * K + k0 + ac + 4);
        }
        sA[ac + 0][ar] = a0.x; sA[ac + 1][ar] = a0.y;
        sA[ac + 2][ar] = a0.z; sA[ac + 3][ar] = a0.w;
        sA[ac + 4][ar] = a1.x; sA[ac + 5][ar] = a1.y;
        sA[ac + 6][ar] = a1.z; sA[ac + 7][ar] = a1.w;
        *(float4*)&sW[wr][wcol]     = *(const float4*)(W + (size_t)(k0 + wr) * N + bn + wcol);
        *(float4*)&sW[wr][wcol + 4] = *(const float4*)(W + (size_t)(k0 + wr) * N + bn + wcol + 4);
        __syncthreads();

#pragma unroll
        for (int kc = 0; kc < 16; kc += 8) {
            unsigned ahi[2][4], alo[2][4];
#pragma unroll
            for (int t = 0; t < 2; t++) {
                float f0 = sA[kc + qd    ][wm + t * 16 + gp];
                float f1 = sA[kc + qd    ][wm + t * 16 + gp + 8];
                float f2 = sA[kc + qd + 4][wm + t * 16 + gp];
                float f3 = sA[kc + qd + 4][wm + t * 16 + gp + 8];
                tf32_split(f0, ahi[t][0], alo[t][0]);
                tf32_split(f1, ahi[t][1], alo[t][1]);
                tf32_split(f2, ahi[t][2], alo[t][2]);
                tf32_split(f3, ahi[t][3], alo[t][3]);
            }
#pragma unroll
            for (int u = 0; u < 8; u++) {
                unsigned bh0, bl0, bh1, bl1;
                float g0 = sW[kc + qd    ][wn + u * 8 + gp];
                float g1 = sW[kc + qd + 4][wn + u * 8 + gp];
                tf32_split(g0, bh0, bl0);
                tf32_split(g1, bh1, bl1);
#pragma unroll
                for (int t = 0; t < 2; t++) {
                    mma_tf32(c[t][u], alo[t][0], alo[t][1], alo[t][2], alo[t][3], bh0, bh1);
                    mma_tf32(c[t][u], ahi[t][0], ahi[t][1], ahi[t][2], ahi[t][3], bl0, bl1);
                    mma_tf32(c[t][u], ahi[t][0], ahi[t][1], ahi[t][2], ahi[t][3], bh0, bh1);
                }
            }
        }
        __syncthreads();
    }

#pragma unroll
    for (int t = 0; t < 2; t++) {
        int r0 = bm + wm + t * 16 + gp;
        int r1 = r0 + 8;
#pragma unroll
        for (int u = 0; u < 8; u++) {
            int col = bn + wn + u * 8 + qd * 2;
            float bx = bias[col], by = bias[col + 1];
            if (r0 < M) {
                float2 o = make_float2(c[t][u][0] + bx, c[t][u][1] + by);
                *(float2*)(C + (size_t)r0 * N + col) = o;
            }
            if (r1 < M) {
                float2 o = make_float2(c[t][u][2] + bx, c[t][u][3] + by);
                *(float2*)(C + (size_t)r1 * N + col) = o;
            }
        }
    }
}

// ---------------- fused single-pass attention, 2-way unrolled online softmax ----------------
// qb computed in prologue from q (regs) and bt (L1).
__global__ __launch_bounds__(128) void node_attn_kernel(
                                 const float* __restrict__ q, const float* __restrict__ k,
                                 const float* __restrict__ qt, const float* __restrict__ bt,
                                 const float* __restrict__ v,
                                 float* __restrict__ xout, const float* __restrict__ wc,
                                 float* __restrict__ y, int mode) {
    int n = blockIdx.x * 4 + (threadIdx.x >> 5);
    int lane = threadIdx.x & 31;
    if (n >= N_NODES) return;
    int off0 = g_off[n], off1 = g_off[n + 1];

    int c0 = lane * 8;              // channel block (h = lane>>3)
    int j0 = (lane & 7) * 8;        // te block within row

    float4 q0, q1, w0, w1;
    {
        const float4* qp = (const float4*)(q  + (size_t)n * HC + c0);
        const float4* wp = (const float4*)(qt + (size_t)n * HC + c0);
        q0 = qp[0]; q1 = qp[1];
        w0 = wp[0]; w1 = wp[1];
    }
    // qb = <q_h, bt_h> via the same 8-lane reduce
    float qbh;
    {
        const float4* bp = (const float4*)(bt + c0);
        float4 b0 = bp[0], b1 = bp[1];
        float pq = q0.x*b0.x + q0.y*b0.y + q0.z*b0.z + q0.w*b0.w
                 + q1.x*b1.x + q1.y*b1.y + q1.z*b1.z + q1.w*b1.w;
        pq += __shfl_xor_sync(0xffffffffu, pq, 4, 8);
        pq += __shfl_xor_sync(0xffffffffu, pq, 2, 8);
        pq += __shfl_xor_sync(0xffffffffu, pq, 1, 8);
        qbh = pq;
    }

    // two independent online-softmax states
    float mA = -FLT_MAX, dA = 0.f;
    float mB = -FLT_MAX, dB = 0.f;
    float4 a0A = make_float4(0.f,0.f,0.f,0.f), a1A = make_float4(0.f,0.f,0.f,0.f);
    float4 a0B = make_float4(0.f,0.f,0.f,0.f), a1B = make_float4(0.f,0.f,0.f,0.f);

    int i = off0;
#pragma unroll 1
    for (; i + 1 < off1; i += 2) {
        int s0 = g_csr_src[i];
        int s1 = g_csr_src[i + 1];
        const float4* kp0 = (const float4*)(k + (size_t)s0 * HC + c0);
        const float4* kp1 = (const float4*)(k + (size_t)s1 * HC + c0);
        const float4* vp0 = (const float4*)(v + (size_t)s0 * HC + c0);
        const float4* vp1 = (const float4*)(v + (size_t)s1 * HC + c0);
        const float4* tp0 = (const float4*)(g_te + (size_t)i * TD + j0);
        const float4* tp1 = (const float4*)(g_te + (size_t)(i + 1) * TD + j0);
        float4 kA0 = kp0[0], kA1 = kp0[1];
        float4 kB0 = kp1[0], kB1 = kp1[1];
        float4 tA0 = tp0[0], tA1 = tp0[1];
        float4 tB0 = tp1[0], tB1 = tp1[1];
        float4 vA0 = vp0[0], vA1 = vp0[1];
        float4 vB0 = vp1[0], vB1 = vp1[1];

        float pA = q0.x*kA0.x + q0.y*kA0.y + q0.z*kA0.z + q0.w*kA0.w
                 + q1.x*kA1.x + q1.y*kA1.y + q1.z*kA1.z + q1.w*kA1.w
                 + w0.x*tA0.x + w0.y*tA0.y + w0.z*tA0.z + w0.w*tA0.w
                 + w1.x*tA1.x + w1.y*tA1.y + w1.z*tA1.z + w1.w*tA1.w;
        float pB = q0.x*kB0.x + q0.y*kB0.y + q0.z*kB0.z + q0.w*kB0.w
                 + q1.x*kB1.x + q1.y*kB1.y + q1.z*kB1.z + q1.w*kB1.w
                 + w0.x*tB0.x + w0.y*tB0.y + w0.z*tB0.z + w0.w*tB0.w
                 + w1.x*tB1.x + w1.y*tB1.y + w1.z*tB1.z + w1.w*tB1.w;
        pA += __shfl_xor_sync(0xffffffffu, pA, 4, 8);
        pB += __shfl_xor_sync(0xffffffffu, pB, 4, 8);
        pA += __shfl_xor_sync(0xffffffffu, pA, 2, 8);
        pB += __shfl_xor_sync(0xffffffffu, pB, 2, 8);
        pA += __shfl_xor_sync(0xffffffffu, pA, 1, 8);
        pB += __shfl_xor_sync(0xffffffffu, pB, 1, 8);
        float alA = (pA + qbh) * 0.125f;
        float alB = (pB + qbh) * 0.125f;

        float mnA = fmaxf(mA, alA);
        float mnB = fmaxf(mB, alB);
        float cA = __expf(mA - mnA), gA = __expf(alA - mnA);
        float cB = __expf(mB - mnB), gB = __expf(alB - mnB);
        dA = dA * cA + gA;  mA = mnA;
        dB = dB * cB + gB;  mB = mnB;
        a0A.x = fmaf(a0A.x, cA, vA0.x * gA); a0A.y = fmaf(a0A.y, cA, vA0.y * gA);
        a0A.z = fmaf(a0A.z, cA, vA0.z * gA); a0A.w = fmaf(a0A.w, cA, vA0.w * gA);
        a1A.x = fmaf(a1A.x, cA, vA1.x * gA); a1A.y = fmaf(a1A.y, cA, vA1.y * gA);
        a1A.z = fmaf(a1A.z, cA, vA1.z * gA); a1A.w = fmaf(a1A.w, cA, vA1.w * gA);
        a0B.x = fmaf(a0B.x, cB, vB0.x * gB); a0B.y = fmaf(a0B.y, cB, vB0.y * gB);
        a0B.z = fmaf(a0B.z, cB, vB0.z * gB); a0B.w = fmaf(a0B.w, cB, vB0.w * gB);
        a1B.x = fmaf(a1B.x, cB, vB1.x * gB); a1B.y = fmaf(a1B.y, cB, vB1.y * gB);
        a1B.z = fmaf(a1B.z, cB, vB1.z * gB); a1B.w = fmaf(a1B.w, cB, vB1.w * gB);
    }
    if (i < off1) {   // odd tail -> state A
        int s0 = g_csr_src[i];
        const float4* kp0 = (const float4*)(k + (size_t)s0 * HC + c0);
        const float4* vp0 = (const float4*)(v + (size_t)s0 * HC + c0);
        const float4* tp0 = (const float4*)(g_te + (size_t)i * TD + j0);
        float4 kA0 = kp0[0], kA1 = kp0[1];
        float4 tA0 = tp0[0], tA1 = tp0[1];
        float4 vA0 = vp0[0], vA1 = vp0[1];
        float pA = q0.x*kA0.x + q0.y*kA0.y + q0.z*kA0.z + q0.w*kA0.w
                 + q1.x*kA1.x + q1.y*kA1.y + q1.z*kA1.z + q1.w*kA1.w
                 + w0.x*tA0.x + w0.y*tA0.y + w0.z*tA0.z + w0.w*tA0.w
                 + w1.x*tA1.x + w1.y*tA1.y + w1.z*tA1.z + w1.w*tA1.w;
        pA += __shfl_xor_sync(0xffffffffu, pA, 4, 8);
        pA += __shfl_xor_sync(0xffffffffu, pA, 2, 8);
        pA += __shfl_xor_sync(0xffffffffu, pA, 1, 8);
        float alA = (pA + qbh) * 0.125f;
        float mnA = fmaxf(mA, alA);
        float cA = __expf(mA - mnA), gA = __expf(alA - mnA);
        dA = dA * cA + gA;  mA = mnA;
        a0A.x = fmaf(a0A.x, cA, vA0.x * gA); a0A.y = fmaf(a0A.y, cA, vA0.y * gA);
        a0A.z = fmaf(a0A.z, cA, vA0.z * gA); a0A.w = fmaf(a0A.w, cA, vA0.w * gA);
        a1A.x = fmaf(a1A.x, cA, vA1.x * gA); a1A.y = fmaf(a1A.y, cA, vA1.y * gA);
        a1A.z = fmaf(a1A.z, cA, vA1.z * gA); a1A.w = fmaf(a1A.w, cA, vA1.w * gA);
    }

    // merge states (exact; both-empty case -> denom=0 -> zeros)
    float mM = fmaxf(mA, mB);
    float cA = __expf(mA - mM), cB = __expf(mB - mM);
    float denom = dA * cA + dB * cB;
    float4 acc0, acc1;
    acc0.x = a0A.x * cA + a0B.x * cB; acc0.y = a0A.y * cA + a0B.y * cB;
    acc0.z = a0A.z * cA + a0B.z * cB; acc0.w = a0A.w * cA + a0B.w * cB;
    acc1.x = a1A.x * cA + a1B.x * cB; acc1.y = a1A.y * cA + a1B.y * cB;
    acc1.z = a1A.z * cA + a1B.z * cB; acc1.w = a1A.w * cA + a1B.w * cB;

    float inv = 1.f / (denom + 1e-16f);
    acc0.x = fmaxf(acc0.x * inv, 0.f); acc0.y = fmaxf(acc0.y * inv, 0.f);
    acc0.z = fmaxf(acc0.z * inv, 0.f); acc0.w = fmaxf(acc0.w * inv, 0.f);
    acc1.x = fmaxf(acc1.x * inv, 0.f); acc1.y = fmaxf(acc1.y * inv, 0.f);
    acc1.z = fmaxf(acc1.z * inv, 0.f); acc1.w = fmaxf(acc1.w * inv, 0.f);

    if (mode == 0) {
        float4* op = (float4*)(xout + (size_t)n * HC + c0);
        op[0] = acc0;
        op[1] = acc1;
    } else {
        const float4* wp = (const float4*)(wc + c0);
        float4 wc0 = wp[0], wc1 = wp[1];
        float p = acc0.x * wc0.x + acc0.y * wc0.y + acc0.z * wc0.z + acc0.w * wc0.w
                + acc1.x * wc1.x + acc1.y * wc1.y + acc1.z * wc1.z + acc1.w * wc1.w;
#pragma unroll
        for (int off = 16; off >= 1; off >>= 1)
            p += __shfl_down_sync(0xffffffffu, p, off);
        if (lane == 0) y[n] = p;
    }
}

// ---------------- final: out[e] = y[src] + y[dst] + bc ----------------
__global__ void edge_final_kernel(const float* __restrict__ bc, float* __restrict__ out) {
    int e = blockIdx.x * blockDim.x + threadIdx.x;
    if (e >= N_EDGES) return;
    out[e] = g_y[g_src[e]] + g_y[g_dst[e]] + bc[0];
}

// ---------------- launch ----------------
extern "C" void kernel_launch(void* const* d_in, const int* in_sizes, int n_in,
                              void* d_out, int out_size) {
    const void* ei        = d_in[0];
    const float* raw_time = (const float*)d_in[1];
    const float* noise    = (const float*)d_in[2];
    const float* node_emb = (const float*)d_in[3];
    const float* wq1 = (const float*)d_in[4],  *bq1 = (const float*)d_in[5];
    const float* wk1 = (const float*)d_in[6],  *bk1 = (const float*)d_in[7];
    const float* wv1 = (const float*)d_in[8],  *bv1 = (const float*)d_in[9];
    const float* wt1 = (const float*)d_in[10], *bt1 = (const float*)d_in[11];
    const float* wq2 = (const float*)d_in[12], *bq2 = (const float*)d_in[13];
    const float* wk2 = (const float*)d_in[14], *bk2 = (const float*)d_in[15];
    const float* wv2 = (const float*)d_in[16], *bv2 = (const float*)d_in[17];
    const float* wt2 = (const float*)d_in[18], *bt2 = (const float*)d_in[19];
    const float* wc  = (const float*)d_in[20], *bc  = (const float*)d_in[21];
    float* out = (float*)d_out;

    float *q, *k, *v, *qt, *x1, *y, *wf, *bf;
    cudaGetSymbolAddress((void**)&q,  g_q);
    cudaGetSymbolAddress((void**)&k,  g_k);
    cudaGetSymbolAddress((void**)&v,  g_v);
    cudaGetSymbolAddress((void**)&qt, g_qt);
    cudaGetSymbolAddress((void**)&x1, g_x1);
    cudaGetSymbolAddress((void**)&y,  g_y);
    cudaGetSymbolAddress((void**)&wf, g_wf);
    cudaGetSymbolAddress((void**)&bf, g_bf);

    dim3 g4(2, (N_NODES + 127) / 128, 4);         // (2, 157, 4)
    const int EB = N_EDGES / 8;                   // warp/edge
    const int NB = (N_NODES + 3) / 4;             // warp/node, 128-thread blocks

    // index dtype detection + int32 conversion + dst histogram
    detect_idx_kernel<<<1, 32>>>((const unsigned int*)ei);
    hist_zero_kernel<<<(N_NODES + 255) / 256, 256>>>();
    convert_hist_kernel<<<(2 * N_EDGES + 255) / 256, 256>>>((const int*)ei);
    scan_kernel<<<1, 1024>>>();
    scatter_kernel<<<(N_EDGES + 255) / 256, 256>>>();

    // time encoding in CSR order (shared by both layers)
    time_encode_kernel<<<EB, 256>>>(raw_time, noise);

    // ---- layer 1 ----
    fuse_wt_kernel<<<(128 * HC + 255) / 256, 256>>>(wq1, wt1, bq1, 128);
    mma4_kernel<<<g4, 256>>>(node_emb, wq1, wk1, wv1, wf, bq1, bk1, bv1, bf,
                             q, k, v, qt, N_NODES, 128);
    node_attn_kernel<<<NB, 128>>>(q, k, qt, bt1, v, x1, wc, y, 0);

    // ---- layer 2 (x1 already relu'd; epilogue emits y directly) ----
    fuse_wt_kernel<<<(256 * HC + 255) / 256, 256>>>(wq2, wt2, bq2, 256);
    mma4_kernel<<<g4, 256>>>(x1, wq2, wk2, wv2, wf, bq2, bk2, bv2, bf,
                             q, k, v, qt, N_NODES, 256);
    node_attn_kernel<<<NB, 128>>>(q, k, qt, bt2, v, nullptr, wc, y, 1);

    // ---- edge readout ----
    edge_final_kernel<<<(N_EDGES + 255) / 256, 256>>>(bc, out);
}

// round 17
// speedup vs baseline: 4.0937x; 1.1209x over previous
#include <cuda_runtime.h>
#include <cuda_fp16.h>
#include <math.h>
#include <float.h>
#include <stdint.h>

#define N_NODES 20000
#define N_EDGES 320000
#define HC      256     // HEADS*HIDDEN
#define HEADS   4
#define HIDDEN  64
#define TD      64
#define SBLK    256
#define NSBLK   ((N_NODES + SBLK - 1) / SBLK)   // 79

// ---------------- scratch (device globals; no runtime allocation) ----------------
__device__ __half g_teh[(size_t)N_EDGES * TD];      // 41 MB, CSR-position order, fp16
__device__ float  g_q  [(size_t)N_NODES * HC];
__device__ __half g_kh [(size_t)N_NODES * HC];      // fp16 K
__device__ __half g_vh [(size_t)N_NODES * HC];      // fp16 V
__device__ float  g_qt [(size_t)N_NODES * HC];      // per-node time-proj of q
__device__ float  g_x1 [(size_t)N_NODES * HC];
__device__ float  g_y  [N_NODES];                   // per-node readout dot
__device__ float  g_wf [(size_t)HC * HC];           // fused Wq@WtT (K<=256)
__device__ float  g_bf [HC];                        // fused bq@WtT
__device__ int    g_src[N_EDGES];
__device__ int    g_dst[N_EDGES];
__device__ int    g_off[N_NODES + 1];               // CSR offsets (by dst)
__device__ int    g_cur[N_NODES];                   // scatter cursors
__device__ int    g_eid[N_EDGES];                   // edge id at CSR position
__device__ int    g_csr_src[N_EDGES];               // src node at CSR position
__device__ int    g_part[NSBLK];                    // scan partials
__device__ int    g_is64;

// ---------------- edge_index dtype detection ----------------
__global__ void detect_idx_kernel(const unsigned int* __restrict__ w) {
    if (threadIdx.x == 0 && blockIdx.x == 0) {
        int ok = 1;
        for (int i = 0; i < 256; i++) {
            unsigned lo = w[2 * i], hi = w[2 * i + 1];
            if (hi != 0u || lo >= (unsigned)N_NODES) { ok = 0; break; }
        }
        g_is64 = ok;
    }
}

__global__ void hist_zero_kernel() {
    int i = blockIdx.x * blockDim.x + threadIdx.x;
    if (i < N_NODES) g_cur[i] = 0;
}

// convert + dst histogram in one pass
__global__ void convert_hist_kernel(const int* __restrict__ w) {
    int i = blockIdx.x * blockDim.x + threadIdx.x;
    if (i >= 2 * N_EDGES) return;
    int v = g_is64 ? w[2 * i] : w[i];    // little-endian low word
    if (i < N_EDGES) {
        g_src[i] = v;
    } else {
        g_dst[i - N_EDGES] = v;
        atomicAdd(&g_cur[v], 1);
    }
}

// ---------------- parallel 3-phase exclusive scan of g_cur -> g_off ----------------
__global__ void scan1_kernel() {     // per-block partial sums
    __shared__ int sh[SBLK];
    int i = blockIdx.x * SBLK + threadIdx.x;
    int val = (i < N_NODES) ? g_cur[i] : 0;
    sh[threadIdx.x] = val;
    __syncthreads();
    for (int off = SBLK / 2; off > 0; off >>= 1) {
        if (threadIdx.x < off) sh[threadIdx.x] += sh[threadIdx.x + off];
        __syncthreads();
    }
    if (threadIdx.x == 0) g_part[blockIdx.x] = sh[0];
}

__global__ void scan2_kernel() {     // 1 block: exclusive scan of NSBLK partials
    __shared__ int sh[128];
    int t = threadIdx.x;             // 128 >= NSBLK
    int v = (t < NSBLK) ? g_part[t] : 0;
    sh[t] = v;
    __syncthreads();
    for (int off = 1; off < 128; off <<= 1) {
        int add = (t >= off) ? sh[t - off] : 0;
        __syncthreads();
        sh[t] += add;
        __syncthreads();
    }
    if (t < NSBLK) g_part[t] = sh[t] - v;     // exclusive base
    if (t == 127) g_off[N_NODES] = sh[127];   // total
}

__global__ void scan3_kernel() {     // per-block local exclusive scan + base
    __shared__ int sh[SBLK];
    int i = blockIdx.x * SBLK + threadIdx.x;
    int t = threadIdx.x;
    int v = (i < N_NODES) ? g_cur[i] : 0;
    sh[t] = v;
    __syncthreads();
    for (int off = 1; off < SBLK; off <<= 1) {
        int add = (t >= off) ? sh[t - off] : 0;
        __syncthreads();
        sh[t] += add;
        __syncthreads();
    }
    if (i < N_NODES) {
        int o = g_part[blockIdx.x] + sh[t] - v;
        g_off[i] = o;
        g_cur[i] = o;
    }
}

__global__ void scatter_kernel() {
    int e = blockIdx.x * blockDim.x + threadIdx.x;
    if (e >= N_EDGES) return;
    int s = g_src[e];
    int pos = atomicAdd(&g_cur[g_dst[e]], 1);
    g_eid[pos] = e;
    g_csr_src[pos] = s;
}

// ---------------- time encoding into CSR order (fp16 output) ----------------
__global__ void time_encode_kernel(const float* __restrict__ raw, const float* __restrict__ noise) {
    int pos = blockIdx.x * 8 + (threadIdx.x >> 5);
    int lane = threadIdx.x & 31;
    if (pos >= N_EDGES) return;
    int e = g_eid[pos];
    float t = raw[e] + noise[e];
    const float cst = -0.14391156831212787f;        // -ln(10000)/64
    float div = expf((float)(2 * lane) * cst);
    float arg = t * div;
    float kf = rintf(arg * 0.15915494309189535f);
    float r  = fmaf(-kf, 6.28125f, arg);
    r = fmaf(-kf, 1.9353071795864792e-3f, r);
    float s = __sinf(r);
    float c = __cosf(r);
    *(__half2*)(g_teh + (size_t)pos * TD + 2 * lane) = __floats2half2_rn(s, c);
}

// ---------------- fused time-weight prep: Wf = Wq @ WtT (per head), bf = bq @ WtT ----------------
__global__ void fuse_wt_kernel(const float* __restrict__ wq, const float* __restrict__ wt,
                               const float* __restrict__ bq, int K) {
    int idx = blockIdx.x * blockDim.x + threadIdx.x;
    if (idx >= K * HC) return;
    int k = idx / HC, n = idx - k * HC;
    int h64 = n & ~63;     // h*64
    int j = n & 63;
    const float* wqr = wq + (size_t)k * HC + h64;
    const float* wtr = wt + (size_t)j * HC + h64;
    float s = 0.f, sb = 0.f;
    if (k == 0) {
        const float* bqr = bq + h64;
#pragma unroll 8
        for (int c = 0; c < 64; c++) {
            float w = wtr[c];
            s  = fmaf(wqr[c], w, s);
            sb = fmaf(bqr[c], w, sb);
        }
        g_bf[n] = sb;
    } else {
#pragma unroll 8
        for (int c = 0; c < 64; c++)
            s = fmaf(wqr[c], wtr[c], s);
    }
    g_wf[idx] = s;
}

// ---------------- TF32 helpers ----------------
__device__ __forceinline__ unsigned f2tf32(float x) {
    unsigned r;
    asm("cvt.rna.tf32.f32 %0, %1;" : "=r"(r) : "f"(x));
    return r;
}
__device__ __forceinline__ void tf32_split(float x, unsigned& hi, unsigned& lo) {
    hi = f2tf32(x);
    lo = f2tf32(x - __uint_as_float(hi));
}
__device__ __forceinline__ void mma_tf32(float* c, unsigned a0, unsigned a1, unsigned a2, unsigned a3,
                                         unsigned b0, unsigned b1) {
    asm volatile("mma.sync.aligned.m16n8k8.row.col.f32.tf32.tf32.f32 "
                 "{%0,%1,%2,%3}, {%4,%5,%6,%7}, {%8,%9}, {%0,%1,%2,%3};"
                 : "+f"(c[0]), "+f"(c[1]), "+f"(c[2]), "+f"(c[3])
                 : "r"(a0), "r"(a1), "r"(a2), "r"(a3), "r"(b0), "r"(b1));
}

// ---------------- fused Q/K/V/QT GEMM (tensor cores, 3xTF32) ----------------
// z: 0 -> q (fp32), 1 -> k (fp16), 2 -> v (fp16), 3 -> qt (fp32)
__global__ __launch_bounds__(256) void mma4_kernel(const float* __restrict__ A,
                              const float* __restrict__ W0, const float* __restrict__ W1,
                              const float* __restrict__ W2, const float* __restrict__ W3,
                              const float* __restrict__ b0, const float* __restrict__ b1,
                              const float* __restrict__ b2, const float* __restrict__ b3,
                              float* __restrict__ CQ, __half* __restrict__ KH,
                              __half* __restrict__ VH, float* __restrict__ CT,
                              int M, int K) {
    const int N = HC;
    int z = blockIdx.z;
    const float* W    = z == 0 ? W0 : (z == 1 ? W1 : (z == 2 ? W2 : W3));
    const float* bias = z == 0 ? b0 : (z == 1 ? b1 : (z == 2 ? b2 : b3));

    __shared__ float sA[16][136];
    __shared__ float sW[16][136];

    int tid = threadIdx.x;
    int bm = blockIdx.y * 128, bn = blockIdx.x * 128;
    int warp = tid >> 5, lane = tid & 31;
    int wm = (warp >> 1) * 32, wn = (warp & 1) * 64;
    int gp = lane >> 2, qd = lane & 3;

    int ar = tid >> 1;                  // 0..127 A-load row
    int ac = (tid & 1) * 8;             // 0 or 8
    int wr = tid >> 4;                  // 0..15 W-load row
    int wcol = (tid & 15) * 8;          // 0..120

    float c[2][8][4];
#pragma unroll
    for (int t = 0; t < 2; t++)
#pragma unroll
        for (int u = 0; u < 8; u++)
#pragma unroll
            for (int f = 0; f < 4; f++) c[t][u][f] = 0.f;

    for (int k0 = 0; k0 < K; k0 += 16) {
        float4 a0 = make_float4(0.f, 0.f, 0.f, 0.f);
        float4 a1 = make_float4(0.f, 0.f, 0.f, 0.f);
        if (bm + ar < M) {
            a0 = *(const float4*)(A + (size_t)(bm + ar) * K + k0 + ac);
            a1 = *(const float4*)(A + (size_t)(bm + ar) * K + k0 + ac + 4);
        }
        sA[ac + 0][ar] = a0.x; sA[ac + 1][ar] = a0.y;
        sA[ac + 2][ar] = a0.z; sA[ac + 3][ar] = a0.w;
        sA[ac + 4][ar] = a1.x; sA[ac + 5][ar] = a1.y;
        sA[ac + 6][ar] = a1.z; sA[ac + 7][ar] = a1.w;
        *(float4*)&sW[wr][wcol]     = *(const float4*)(W + (size_t)(k0 + wr) * N + bn + wcol);
        *(float4*)&sW[wr][wcol + 4] = *(const float4*)(W + (size_t)(k0 + wr) * N + bn + wcol + 4);
        __syncthreads();

#pragma unroll
        for (int kc = 0; kc < 16; kc += 8) {
            unsigned ahi[2][4], alo[2][4];
#pragma unroll
            for (int t = 0; t < 2; t++) {
                float f0 = sA[kc + qd    ][wm + t * 16 + gp];
                float f1 = sA[kc + qd    ][wm + t * 16 + gp + 8];
                float f2 = sA[kc + qd + 4][wm + t * 16 + gp];
                float f3 = sA[kc + qd + 4][wm + t * 16 + gp + 8];
                tf32_split(f0, ahi[t][0], alo[t][0]);
                tf32_split(f1, ahi[t][1], alo[t][1]);
                tf32_split(f2, ahi[t][2], alo[t][2]);
                tf32_split(f3, ahi[t][3], alo[t][3]);
            }
#pragma unroll
            for (int u = 0; u < 8; u++) {
                unsigned bh0, bl0, bh1, bl1;
                float g0 = sW[kc + qd    ][wn + u * 8 + gp];
                float g1 = sW[kc + qd + 4][wn + u * 8 + gp];
                tf32_split(g0, bh0, bl0);
                tf32_split(g1, bh1, bl1);
#pragma unroll
                for (int t = 0; t < 2; t++) {
                    mma_tf32(c[t][u], alo[t][0], alo[t][1], alo[t][2], alo[t][3], bh0, bh1);
                    mma_tf32(c[t][u], ahi[t][0], ahi[t][1], ahi[t][2], ahi[t][3], bl0, bl1);
                    mma_tf32(c[t][u], ahi[t][0], ahi[t][1], ahi[t][2], ahi[t][3], bh0, bh1);
                }
            }
        }
        __syncthreads();
    }

    if (z == 1 || z == 2) {
        __half* CH = (z == 1) ? KH : VH;
#pragma unroll
        for (int t = 0; t < 2; t++) {
            int r0 = bm + wm + t * 16 + gp;
            int r1 = r0 + 8;
#pragma unroll
            for (int u = 0; u < 8; u++) {
                int col = bn + wn + u * 8 + qd * 2;
                float bx = bias[col], by = bias[col + 1];
                if (r0 < M)
                    *(__half2*)(CH + (size_t)r0 * N + col) = __floats2half2_rn(c[t][u][0] + bx, c[t][u][1] + by);
                if (r1 < M)
                    *(__half2*)(CH + (size_t)r1 * N + col) = __floats2half2_rn(c[t][u][2] + bx, c[t][u][3] + by);
            }
        }
    } else {
        float* C = (z == 0) ? CQ : CT;
#pragma unroll
        for (int t = 0; t < 2; t++) {
            int r0 = bm + wm + t * 16 + gp;
            int r1 = r0 + 8;
#pragma unroll
            for (int u = 0; u < 8; u++) {
                int col = bn + wn + u * 8 + qd * 2;
                float bx = bias[col], by = bias[col + 1];
                if (r0 < M) {
                    float2 o = make_float2(c[t][u][0] + bx, c[t][u][1] + by);
                    *(float2*)(C + (size_t)r0 * N + col) = o;
                }
                if (r1 < M) {
                    float2 o = make_float2(c[t][u][2] + bx, c[t][u][3] + by);
                    *(float2*)(C + (size_t)r1 * N + col) = o;
                }
            }
        }
    }
}

// ---------------- half8 load helper ----------------
__device__ __forceinline__ void ld_half8(const __half* p, float4& f0, float4& f1) {
    uint4 r = *(const uint4*)p;
    float2 a = __half22float2(*(__half2*)&r.x);
    float2 b = __half22float2(*(__half2*)&r.y);
    float2 cc = __half22float2(*(__half2*)&r.z);
    float2 d = __half22float2(*(__half2*)&r.w);
    f0 = make_float4(a.x, a.y, b.x, b.y);
    f1 = make_float4(cc.x, cc.y, d.x, d.y);
}

// ---------------- fused single-pass attention, 2-way unrolled online softmax ----------------
__global__ __launch_bounds__(128) void node_attn_kernel(
                                 const float* __restrict__ q, const __half* __restrict__ kh,
                                 const float* __restrict__ qt, const float* __restrict__ bt,
                                 const __half* __restrict__ vh,
                                 float* __restrict__ xout, const float* __restrict__ wc,
                                 float* __restrict__ y, int mode) {
    int n = blockIdx.x * 4 + (threadIdx.x >> 5);
    int lane = threadIdx.x & 31;
    if (n >= N_NODES) return;
    int off0 = g_off[n], off1 = g_off[n + 1];

    int c0 = lane * 8;              // channel block (h = lane>>3)
    int j0 = (lane & 7) * 8;        // te block within row

    float4 q0, q1, w0, w1;
    {
        const float4* qp = (const float4*)(q  + (size_t)n * HC + c0);
        const float4* wp = (const float4*)(qt + (size_t)n * HC + c0);
        q0 = qp[0]; q1 = qp[1];
        w0 = wp[0]; w1 = wp[1];
    }
    float qbh;
    {
        const float4* bp = (const float4*)(bt + c0);
        float4 b0 = bp[0], b1 = bp[1];
        float pq = q0.x*b0.x + q0.y*b0.y + q0.z*b0.z + q0.w*b0.w
                 + q1.x*b1.x + q1.y*b1.y + q1.z*b1.z + q1.w*b1.w;
        pq += __shfl_xor_sync(0xffffffffu, pq, 4, 8);
        pq += __shfl_xor_sync(0xffffffffu, pq, 2, 8);
        pq += __shfl_xor_sync(0xffffffffu, pq, 1, 8);
        qbh = pq;
    }

    float mA = -FLT_MAX, dA = 0.f;
    float mB = -FLT_MAX, dB = 0.f;
    float4 a0A = make_float4(0.f,0.f,0.f,0.f), a1A = make_float4(0.f,0.f,0.f,0.f);
    float4 a0B = make_float4(0.f,0.f,0.f,0.f), a1B = make_float4(0.f,0.f,0.f,0.f);

    int i = off0;
#pragma unroll 1
    for (; i + 1 < off1; i += 2) {
        int s0 = g_csr_src[i];
        int s1 = g_csr_src[i + 1];
        float4 kA0, kA1, kB0, kB1, tA0, tA1, tB0, tB1, vA0, vA1, vB0, vB1;
        ld_half8(kh + (size_t)s0 * HC + c0, kA0, kA1);
        ld_half8(kh + (size_t)s1 * HC + c0, kB0, kB1);
        ld_half8(g_teh + (size_t)i * TD + j0, tA0, tA1);
        ld_half8(g_teh + (size_t)(i + 1) * TD + j0, tB0, tB1);
        ld_half8(vh + (size_t)s0 * HC + c0, vA0, vA1);
        ld_half8(vh + (size_t)s1 * HC + c0, vB0, vB1);

        float pA = q0.x*kA0.x + q0.y*kA0.y + q0.z*kA0.z + q0.w*kA0.w
                 + q1.x*kA1.x + q1.y*kA1.y + q1.z*kA1.z + q1.w*kA1.w
                 + w0.x*tA0.x + w0.y*tA0.y + w0.z*tA0.z + w0.w*tA0.w
                 + w1.x*tA1.x + w1.y*tA1.y + w1.z*tA1.z + w1.w*tA1.w;
        float pB = q0.x*kB0.x + q0.y*kB0.y + q0.z*kB0.z + q0.w*kB0.w
                 + q1.x*kB1.x + q1.y*kB1.y + q1.z*kB1.z + q1.w*kB1.w
                 + w0.x*tB0.x + w0.y*tB0.y + w0.z*tB0.z + w0.w*tB0.w
                 + w1.x*tB1.x + w1.y*tB1.y + w1.z*tB1.z + w1.w*tB1.w;
        pA += __shfl_xor_sync(0xffffffffu, pA, 4, 8);
        pB += __shfl_xor_sync(0xffffffffu, pB, 4, 8);
        pA += __shfl_xor_sync(0xffffffffu, pA, 2, 8);
        pB += __shfl_xor_sync(0xffffffffu, pB, 2, 8);
        pA += __shfl_xor_sync(0xffffffffu, pA, 1, 8);
        pB += __shfl_xor_sync(0xffffffffu, pB, 1, 8);
        float alA = (pA + qbh) * 0.125f;
        float alB = (pB + qbh) * 0.125f;

        float mnA = fmaxf(mA, alA);
        float mnB = fmaxf(mB, alB);
        float cA = __expf(mA - mnA), gA = __expf(alA - mnA);
        float cB = __expf(mB - mnB), gB = __expf(alB - mnB);
        dA = dA * cA + gA;  mA = mnA;
        dB = dB * cB + gB;  mB = mnB;
        a0A.x = fmaf(a0A.x, cA, vA0.x * gA); a0A.y = fmaf(a0A.y, cA, vA0.y * gA);
        a0A.z = fmaf(a0A.z, cA, vA0.z * gA); a0A.w = fmaf(a0A.w, cA, vA0.w * gA);
        a1A.x = fmaf(a1A.x, cA, vA1.x * gA); a1A.y = fmaf(a1A.y, cA, vA1.y * gA);
        a1A.z = fmaf(a1A.z, cA, vA1.z * gA); a1A.w = fmaf(a1A.w, cA, vA1.w * gA);
        a0B.x = fmaf(a0B.x, cB, vB0.x * gB); a0B.y = fmaf(a0B.y, cB, vB0.y * gB);
        a0B.z = fmaf(a0B.z, cB, vB0.z * gB); a0B.w = fmaf(a0B.w, cB, vB0.w * gB);
        a1B.x = fmaf(a1B.x, cB, vB1.x * gB); a1B.y = fmaf(a1B.y, cB, vB1.y * gB);
        a1B.z = fmaf(a1B.z, cB, vB1.z * gB); a1B.w = fmaf(a1B.w, cB, vB1.w * gB);
    }
    if (i < off1) {   // odd tail -> state A
        int s0 = g_csr_src[i];
        float4 kA0, kA1, tA0, tA1, vA0, vA1;
        ld_half8(kh + (size_t)s0 * HC + c0, kA0, kA1);
        ld_half8(g_teh + (size_t)i * TD + j0, tA0, tA1);
        ld_half8(vh + (size_t)s0 * HC + c0, vA0, vA1);
        float pA = q0.x*kA0.x + q0.y*kA0.y + q0.z*kA0.z + q0.w*kA0.w
                 + q1.x*kA1.x + q1.y*kA1.y + q1.z*kA1.z + q1.w*kA1.w
                 + w0.x*tA0.x + w0.y*tA0.y + w0.z*tA0.z + w0.w*tA0.w
                 + w1.x*tA1.x + w1.y*tA1.y + w1.z*tA1.z + w1.w*tA1.w;
        pA += __shfl_xor_sync(0xffffffffu, pA, 4, 8);
        pA += __shfl_xor_sync(0xffffffffu, pA, 2, 8);
        pA += __shfl_xor_sync(0xffffffffu, pA, 1, 8);
        float alA = (pA + qbh) * 0.125f;
        float mnA = fmaxf(mA, alA);
        float cA = __expf(mA - mnA), gA = __expf(alA - mnA);
        dA = dA * cA + gA;  mA = mnA;
        a0A.x = fmaf(a0A.x, cA, vA0.x * gA); a0A.y = fmaf(a0A.y, cA, vA0.y * gA);
        a0A.z = fmaf(a0A.z, cA, vA0.z * gA); a0A.w = fmaf(a0A.w, cA, vA0.w * gA);
        a1A.x = fmaf(a1A.x, cA, vA1.x * gA); a1A.y = fmaf(a1A.y, cA, vA1.y * gA);
        a1A.z = fmaf(a1A.z, cA, vA1.z * gA); a1A.w = fmaf(a1A.w, cA, vA1.w * gA);
    }

    // merge states (exact; both-empty case -> denom=0 -> zeros)
    float mM = fmaxf(mA, mB);
    float cA = __expf(mA - mM), cB = __expf(mB - mM);
    float denom = dA * cA + dB * cB;
    float4 acc0, acc1;
    acc0.x = a0A.x * cA + a0B.x * cB; acc0.y = a0A.y * cA + a0B.y * cB;
    acc0.z = a0A.z * cA + a0B.z * cB; acc0.w = a0A.w * cA + a0B.w * cB;
    acc1.x = a1A.x * cA + a1B.x * cB; acc1.y = a1A.y * cA + a1B.y * cB;
    acc1.z = a1A.z * cA + a1B.z * cB; acc1.w = a1A.w * cA + a1B.w * cB;

    float inv = 1.f / (denom + 1e-16f);
    acc0.x = fmaxf(acc0.x * inv, 0.f); acc0.y = fmaxf(acc0.y * inv, 0.f);
    acc0.z = fmaxf(acc0.z * inv, 0.f); acc0.w = fmaxf(acc0.w * inv, 0.f);
    acc1.x = fmaxf(acc1.x * inv, 0.f); acc1.y = fmaxf(acc1.y * inv, 0.f);
    acc1.w = fmaxf(acc1.w * inv, 0.f); acc1.z = fmaxf(acc1.z * inv, 0.f);

    if (mode == 0) {
        float4* op = (float4*)(xout + (size_t)n * HC + c0);
        op[0] = acc0;
        op[1] = acc1;
    } else {
        const float4* wp = (const float4*)(wc + c0);
        float4 wc0 = wp[0], wc1 = wp[1];
        float p = acc0.x * wc0.x + acc0.y * wc0.y + acc0.z * wc0.z + acc0.w * wc0.w
                + acc1.x * wc1.x + acc1.y * wc1.y + acc1.z * wc1.z + acc1.w * wc1.w;
#pragma unroll
        for (int off = 16; off >= 1; off >>= 1)
            p += __shfl_down_sync(0xffffffffu, p, off);
        if (lane == 0) y[n] = p;
    }
}

// ---------------- final: out[e] = y[src] + y[dst] + bc ----------------
__global__ void edge_final_kernel(const float* __restrict__ bc, float* __restrict__ out) {
    int e = blockIdx.x * blockDim.x + threadIdx.x;
    if (e >= N_EDGES) return;
    out[e] = g_y[g_src[e]] + g_y[g_dst[e]] + bc[0];
}

// ---------------- launch ----------------
extern "C" void kernel_launch(void* const* d_in, const int* in_sizes, int n_in,
                              void* d_out, int out_size) {
    const void* ei        = d_in[0];
    const float* raw_time = (const float*)d_in[1];
    const float* noise    = (const float*)d_in[2];
    const float* node_emb = (const float*)d_in[3];
    const float* wq1 = (const float*)d_in[4],  *bq1 = (const float*)d_in[5];
    const float* wk1 = (const float*)d_in[6],  *bk1 = (const float*)d_in[7];
    const float* wv1 = (const float*)d_in[8],  *bv1 = (const float*)d_in[9];
    const float* wt1 = (const float*)d_in[10], *bt1 = (const float*)d_in[11];
    const float* wq2 = (const float*)d_in[12], *bq2 = (const float*)d_in[13];
    const float* wk2 = (const float*)d_in[14], *bk2 = (const float*)d_in[15];
    const float* wv2 = (const float*)d_in[16], *bv2 = (const float*)d_in[17];
    const float* wt2 = (const float*)d_in[18], *bt2 = (const float*)d_in[19];
    const float* wc  = (const float*)d_in[20], *bc  = (const float*)d_in[21];
    float* out = (float*)d_out;

    float *q, *qt, *x1, *y, *wf, *bf;
    __half *kh, *vh;
    cudaGetSymbolAddress((void**)&q,  g_q);
    cudaGetSymbolAddress((void**)&kh, g_kh);
    cudaGetSymbolAddress((void**)&vh, g_vh);
    cudaGetSymbolAddress((void**)&qt, g_qt);
    cudaGetSymbolAddress((void**)&x1, g_x1);
    cudaGetSymbolAddress((void**)&y,  g_y);
    cudaGetSymbolAddress((void**)&wf, g_wf);
    cudaGetSymbolAddress((void**)&bf, g_bf);

    dim3 g4(2, (N_NODES + 127) / 128, 4);         // (2, 157, 4)
    const int EB = N_EDGES / 8;                   // warp/edge
    const int NB = (N_NODES + 3) / 4;             // warp/node, 128-thread blocks

    // index dtype detection + int32 conversion + dst histogram
    detect_idx_kernel<<<1, 32>>>((const unsigned int*)ei);
    hist_zero_kernel<<<(N_NODES + 255) / 256, 256>>>();
    convert_hist_kernel<<<(2 * N_EDGES + 255) / 256, 256>>>((const int*)ei);
    scan1_kernel<<<NSBLK, SBLK>>>();
    scan2_kernel<<<1, 128>>>();
    scan3_kernel<<<NSBLK, SBLK>>>();
    scatter_kernel<<<(N_EDGES + 255) / 256, 256>>>();

    // time encoding in CSR order (fp16; shared by both layers)
    time_encode_kernel<<<EB, 256>>>(raw_time, noise);

    // ---- layer 1 ----
    fuse_wt_kernel<<<(128 * HC + 255) / 256, 256>>>(wq1, wt1, bq1, 128);
    mma4_kernel<<<g4, 256>>>(node_emb, wq1, wk1, wv1, wf, bq1, bk1, bv1, bf,
                             q, kh, vh, qt, N_NODES, 128);
    node_attn_kernel<<<NB, 128>>>(q, kh, qt, bt1, vh, x1, wc, y, 0);

    // ---- layer 2 (x1 already relu'd; epilogue emits y directly) ----
    fuse_wt_kernel<<<(256 * HC + 255) / 256, 256>>>(wq2, wt2, bq2, 256);
    mma4_kernel<<<g4, 256>>>(x1, wq2, wk2, wv2, wf, bq2, bk2, bv2, bf,
                             q, kh, vh, qt, N_NODES, 256);
    node_attn_kernel<<<NB, 128>>>(q, kh, qt, bt2, vh, nullptr, wc, y, 1);

    // ---- edge readout ----
    edge_final_kernel<<<(N_EDGES + 255) / 256, 256>>>(bc, out);
}